// round 10
// baseline (speedup 1.0000x reference)
#include <cuda_runtime.h>
#include <cuda_bf16.h>
#include <math.h>
#include <stdint.h>

// ---------------------------------------------------------------------------
// MultiviewDecoderBlock (Vx=8, Vy=8, B=4, N=196, C=768, H=12, DH=64, M=4)
// cp.async 3-stage TF32 GEMMs (scalar-LDS frags, round-6 mainloop) +
// bf16 mma attention + fused trims. Graph-capturable.
// ---------------------------------------------------------------------------

constexpr int VX = 8, BB = 4, NN = 196, CC = 768, HH = 12, DHH = 64, MV = 4;
constexpr int HID = 4 * CC;            // 3072
constexpr int VB = VX * BB;            // 32
constexpr int T  = VB * NN;            // 6272
constexpr int TT = VX * MV * BB * NN;  // 25088
constexpr int PSELF  = VB * HH;            // 384
constexpr int PCROSS = VX * MV * BB * HH;  // 1536
constexpr float ATTN_SCALE = 0.125f;

// -------------------------- device scratch ---------------------------------
__device__ float g_x  [T * CC];
__device__ float g_h  [T * CC];
__device__ float g_yn [T * CC];
__device__ float g_qkv[T * 3 * CC];   // self qkv; later reused as fused cross k|v
__device__ float g_q  [T * CC];
__device__ float g_o  [T * CC];
__device__ float g_big [TT * CC];
__device__ float g_big2[TT * CC];
__device__ float g_wr [9437184];      // tf32-rounded weights

constexpr int WO_QKV = 0;
constexpr int WO_AP  = 3 * CC * CC;
constexpr int WO_Q   = WO_AP  + CC * CC;
constexpr int WO_K   = WO_Q   + CC * CC;   // k|v contiguous -> fused N=1536 GEMM
constexpr int WO_V   = WO_K   + CC * CC;
constexpr int WO_CP  = WO_V   + CC * CC;
constexpr int WO_FC1 = WO_CP  + CC * CC;
constexpr int WO_FC2 = WO_FC1 + HID * CC;

extern __shared__ __align__(16) unsigned char dyn_smem[];

// ----------------------------- helpers -------------------------------------
__device__ __forceinline__ float tf32r(float f) {
    unsigned u; asm("cvt.rna.tf32.f32 %0, %1;" : "=r"(u) : "f"(f));
    return __uint_as_float(u);
}
__device__ __forceinline__ unsigned pkbf(float lo, float hi) {
    unsigned r;
    asm("cvt.rn.bf16x2.f32 %0, %1, %2;" : "=r"(r) : "f"(hi), "f"(lo));
    return r;
}
__device__ __forceinline__ void mma8(float* c, const unsigned* a, const unsigned* b) {
    asm volatile(
        "mma.sync.aligned.m16n8k8.row.col.f32.tf32.tf32.f32 "
        "{%0,%1,%2,%3},{%4,%5,%6,%7},{%8,%9},{%0,%1,%2,%3};\n"
        : "+f"(c[0]), "+f"(c[1]), "+f"(c[2]), "+f"(c[3])
        : "r"(a[0]), "r"(a[1]), "r"(a[2]), "r"(a[3]), "r"(b[0]), "r"(b[1]));
}
__device__ __forceinline__ void mma16(float* c, const unsigned* a, const unsigned* b) {
    asm volatile(
        "mma.sync.aligned.m16n8k16.row.col.f32.bf16.bf16.f32 "
        "{%0,%1,%2,%3},{%4,%5,%6,%7},{%8,%9},{%0,%1,%2,%3};\n"
        : "+f"(c[0]), "+f"(c[1]), "+f"(c[2]), "+f"(c[3])
        : "r"(a[0]), "r"(a[1]), "r"(a[2]), "r"(a[3]), "r"(b[0]), "r"(b[1]));
}
__device__ __forceinline__ void ldmx4t(unsigned* d, unsigned addr) {
    asm volatile("ldmatrix.sync.aligned.m8n8.x4.trans.shared.b16 {%0,%1,%2,%3}, [%4];"
                 : "=r"(d[0]), "=r"(d[1]), "=r"(d[2]), "=r"(d[3]) : "r"(addr));
}
__device__ __forceinline__ void cp16(unsigned d, const void* s) {
    asm volatile("cp.async.cg.shared.global [%0], [%1], 16;" :: "r"(d), "l"(s));
}

// ----------------------------- utility kernels ------------------------------
__global__ void round_all_kernel(
    const float4* s0, const float4* s1, const float4* s2, const float4* s3,
    const float4* s4, const float4* s5, const float4* s6, const float4* s7,
    float4* dst)
{
    const int seg = blockIdx.y;
    const float4* srcs[8] = {s0, s1, s2, s3, s4, s5, s6, s7};
    const int sizes4[8] = {3*CC*CC/4, CC*CC/4, CC*CC/4, CC*CC/4,
                           CC*CC/4, CC*CC/4, HID*CC/4, CC*HID/4};
    const int offs4[8] = {WO_QKV/4, WO_AP/4, WO_Q/4, WO_K/4,
                          WO_V/4, WO_CP/4, WO_FC1/4, WO_FC2/4};
    int i = blockIdx.x * blockDim.x + threadIdx.x;
    if (i < sizes4[seg]) {
        float4 v = srcs[seg][i];
        v.x = tf32r(v.x); v.y = tf32r(v.y); v.z = tf32r(v.z); v.w = tf32r(v.w);
        dst[offs4[seg] + i] = v;
    }
}

__global__ void layernorm_kernel(const float* __restrict__ in,
                                 const float* __restrict__ w,
                                 const float* __restrict__ b,
                                 float* __restrict__ out) {
    int row = blockIdx.x;
    const float* xr = in + (size_t)row * CC;
    float* orow = out + (size_t)row * CC;
    int tid = threadIdx.x;
    float v0 = xr[tid], v1 = xr[tid + 256], v2 = xr[tid + 512];
    float s  = v0 + v1 + v2;
    float sq = v0 * v0 + v1 * v1 + v2 * v2;
    #pragma unroll
    for (int off = 16; off; off >>= 1) {
        s  += __shfl_xor_sync(0xffffffffu, s, off);
        sq += __shfl_xor_sync(0xffffffffu, sq, off);
    }
    __shared__ float red[2][8];
    int warp = tid >> 5, lane = tid & 31;
    if (lane == 0) { red[0][warp] = s; red[1][warp] = sq; }
    __syncthreads();
    float ts = 0.f, tsq = 0.f;
    #pragma unroll
    for (int i = 0; i < 8; i++) { ts += red[0][i]; tsq += red[1][i]; }
    float mu = ts * (1.0f / CC);
    float var = tsq * (1.0f / CC) - mu * mu;
    float rstd = rsqrtf(var + 1e-5f);
    orow[tid]       = tf32r((v0 - mu) * rstd * w[tid]       + b[tid]);
    orow[tid + 256] = tf32r((v1 - mu) * rstd * w[tid + 256] + b[tid + 256]);
    orow[tid + 512] = tf32r((v2 - mu) * rstd * w[tid + 512] + b[tid + 512]);
}

__global__ void merge_kernel(const float* __restrict__ proj, float* __restrict__ x) {
    int idx = blockIdx.x * blockDim.x + threadIdx.x;
    if (idx >= T * CC) return;
    int c = idx % CC;
    int n = (idx / CC) % NN;
    int b = (idx / (CC * NN)) % BB;
    int v = idx / (CC * NN * BB);
    size_t base = ((((size_t)v * MV) * BB + b) * NN + n) * CC + c;
    size_t ms = (size_t)BB * NN * CC;
    float mx = proj[base];
    #pragma unroll
    for (int m = 1; m < MV; m++) mx = fmaxf(mx, proj[base + (size_t)m * ms]);
    x[idx] += mx;
}

// --------------- TF32 GEMM, cp.async 3 stages, scalar-LDS frags -------------
// Round-6 mainloop (measured best: ~190 TF/s on the legacy mma path).
// C = A @ B^T. A:(M,K) B:(N,K) row-major, pre-rounded to tf32 bit patterns.
// 128x128x32 tile, 256 thr, warp tile 64x32, smem swizzle g=(k>>2)^(row&7).
// EPI: 0=store, 1=+bias, 2=+bias+residual, 3=+bias+gelu(exact)+tf32round
constexpr int GSTAGES = 3;
constexpr int GEMM_SMEM = GSTAGES * 2 * 128 * 32 * 4;  // 98304

template<int EPI>
__global__ void __launch_bounds__(256) gemm_tf32(
    const float* __restrict__ A, const float* __restrict__ Bw,
    const float* __restrict__ bias, const float* __restrict__ res,
    float* __restrict__ C, int Mdim, int Ndim, int Kdim)
{
    const unsigned sbase = (unsigned)__cvta_generic_to_shared(dyn_smem);
    const int tid = threadIdx.x;
    const int lane = tid & 31, warp = tid >> 5;
    const int wm = (warp >> 2) * 64;
    const int wn = (warp & 3) * 32;
    const int bm = blockIdx.y * 128, bn = blockIdx.x * 128;
    const int lr = tid >> 3;
    const int lk = (tid & 7) * 4;
    const float* Ag = A  + (size_t)(bm + lr) * Kdim + lk;
    const float* Bg = Bw + (size_t)(bn + lr) * Kdim + lk;

    // per-thread swizzled smem byte addresses (stage 0)
    unsigned sa[4], sb[4];
    #pragma unroll
    for (int i = 0; i < 4; i++) {
        int row = lr + 32 * i;
        int g = (lk >> 2) ^ (row & 7);
        sa[i] = sbase + (unsigned)(row * 32 + g * 4) * 4u;
        sb[i] = sbase + (unsigned)(GSTAGES * 4096 + row * 32 + g * 4) * 4u;
    }

    float acc[4][4][4];
    #pragma unroll
    for (int i = 0; i < 4; i++)
        #pragma unroll
        for (int j = 0; j < 4; j++)
            #pragma unroll
            for (int t = 0; t < 4; t++) acc[i][j][t] = 0.f;

    const int nk = Kdim >> 5;
    // prologue: stages 0, 1
    #pragma unroll
    for (int s = 0; s < GSTAGES - 1; s++) {
        const float* a = Ag + s * 32;
        const float* b = Bg + s * 32;
        unsigned off = (unsigned)s * 16384u;
        #pragma unroll
        for (int i = 0; i < 4; i++) cp16(sa[i] + off, a + (size_t)32 * i * Kdim);
        #pragma unroll
        for (int i = 0; i < 4; i++) cp16(sb[i] + off, b + (size_t)32 * i * Kdim);
        asm volatile("cp.async.commit_group;");
    }

    const int r = lane >> 2, kq = lane & 3;
    #pragma unroll 1
    for (int kt = 0; kt < nk; kt++) {
        asm volatile("cp.async.wait_group 1;");
        __syncthreads();
        const int buf = kt % GSTAGES;
        const unsigned* Ab = (const unsigned*)dyn_smem + buf * 4096;
        const unsigned* Bb = (const unsigned*)dyn_smem + GSTAGES * 4096 + buf * 4096;
        #pragma unroll
        for (int ks = 0; ks < 4; ks++) {
            const int g0 = (((2 * ks)     ^ r) << 2) + kq;
            const int g1 = (((2 * ks + 1) ^ r) << 2) + kq;
            unsigned a[4][4], b[4][2];
            #pragma unroll
            for (int mf = 0; mf < 4; mf++) {
                const unsigned* p = Ab + (wm + mf * 16 + r) * 32;
                a[mf][0] = p[g0];
                a[mf][1] = p[8 * 32 + g0];
                a[mf][2] = p[g1];
                a[mf][3] = p[8 * 32 + g1];
            }
            #pragma unroll
            for (int nf = 0; nf < 4; nf++) {
                const unsigned* p = Bb + (wn + nf * 8 + r) * 32;
                b[nf][0] = p[g0];
                b[nf][1] = p[g1];
            }
            #pragma unroll
            for (int mf = 0; mf < 4; mf++)
                #pragma unroll
                for (int nf = 0; nf < 4; nf++)
                    mma8(acc[mf][nf], a[mf], b[nf]);
        }
        // prefetch stage kt + GSTAGES - 1
        if (kt + GSTAGES - 1 < nk) {
            int t = (kt + GSTAGES - 1) % GSTAGES;
            const float* a = Ag + (size_t)(kt + GSTAGES - 1) * 32;
            const float* b = Bg + (size_t)(kt + GSTAGES - 1) * 32;
            unsigned off = (unsigned)t * 16384u;
            #pragma unroll
            for (int i = 0; i < 4; i++) cp16(sa[i] + off, a + (size_t)32 * i * Kdim);
            #pragma unroll
            for (int i = 0; i < 4; i++) cp16(sb[i] + off, b + (size_t)32 * i * Kdim);
        }
        asm volatile("cp.async.commit_group;");
    }

    #pragma unroll
    for (int mf = 0; mf < 4; mf++) {
        #pragma unroll
        for (int nf = 0; nf < 4; nf++) {
            const int col = bn + wn + nf * 8 + (lane & 3) * 2;
            float bb0 = 0.f, bb1 = 0.f;
            if (EPI >= 1) { bb0 = bias[col]; bb1 = bias[col + 1]; }
            #pragma unroll
            for (int hh = 0; hh < 2; hh++) {
                const size_t row = (size_t)(bm + wm + mf * 16 + (lane >> 2) + hh * 8);
                float v0 = acc[mf][nf][hh * 2 + 0] + bb0;
                float v1 = acc[mf][nf][hh * 2 + 1] + bb1;
                if (EPI == 2) {
                    v0 += res[row * Ndim + col];
                    v1 += res[row * Ndim + col + 1];
                }
                if (EPI == 3) {
                    v0 = tf32r(0.5f * v0 * (1.0f + erff(v0 * 0.70710678118654752f)));
                    v1 = tf32r(0.5f * v1 * (1.0f + erff(v1 * 0.70710678118654752f)));
                }
                *(float2*)(C + row * Ndim + col) = make_float2(v0, v1);
            }
        }
    }
}

// ------------------------- bf16 mma attention -------------------------------
// CROSS reads fused k|v buffer (stride 1536).
constexpr int QWS = 36;
constexpr int PWS = 108;
constexpr int W_Q = 0;
constexpr int W_K = 2304;
constexpr int W_V = 9792;
constexpr int W_RED = 17280;
constexpr int ATTN_SMEM = (W_RED + 256) * 4;  // 70144 bytes

template<bool CROSS>
__global__ void __launch_bounds__(256) attn_bf16(
    const float* __restrict__ Qsrc, const float* __restrict__ Ksrc,
    const int* __restrict__ rel, float* __restrict__ Out)
{
    unsigned* W = (unsigned*)dyn_smem;
    unsigned* Qw = W + W_Q;
    unsigned* Kw = W + W_K;
    unsigned* Vw = W + W_V;
    unsigned* Pw = W;
    float* redmax = (float*)(W + W_RED);
    float* redsum = redmax + 128;
    const unsigned sbase = (unsigned)__cvta_generic_to_shared(dyn_smem);

    const int p = blockIdx.y;
    const int m0 = blockIdx.x * 64;
    const int tid = threadIdx.x;
    const int lane = tid & 31, warp = tid >> 5;
    const int wm = warp & 3, wn = warp >> 2;
    const int r = lane >> 2, q = lane & 3;

    const float *qp, *kp, *vp;
    float* op;
    int qrs, kvs;
    if (!CROSS) {
        int vb = p / HH, h2 = p % HH;
        const float* base = Qsrc + (size_t)vb * NN * 3 * CC;
        qp = base + h2 * DHH;
        kp = base + CC + h2 * DHH;
        vp = base + 2 * CC + h2 * DHH;
        qrs = 3 * CC; kvs = 3 * CC;
        op = Out + (size_t)vb * NN * CC + h2 * DHH;
    } else {
        int h2 = p % HH; int rr = p / HH;
        int b = rr % BB; int r2 = rr / BB;
        int mvi = r2 % MV; int v = r2 / MV;
        int vy = rel[v * MV + mvi];
        qp = Qsrc + ((size_t)(v * BB + b) * NN) * CC + h2 * DHH; qrs = CC;
        kp = Ksrc + ((size_t)(vy * BB + b) * NN) * 1536 + h2 * DHH;
        vp = kp + CC;
        kvs = 1536;
        op = Out + (size_t)rr * NN * CC + h2 * DHH;
    }

    #pragma unroll
    for (int it = 0; it < 4; it++) {
        int idx = tid + 256 * it;
        int row = idx >> 4, c4 = (idx & 15) * 4;
        float4 qv = make_float4(0.f, 0.f, 0.f, 0.f);
        if (m0 + row < NN) qv = *(const float4*)(qp + (size_t)(m0 + row) * qrs + c4);
        Qw[row * QWS + (c4 >> 1)]     = pkbf(qv.x, qv.y);
        Qw[row * QWS + (c4 >> 1) + 1] = pkbf(qv.z, qv.w);
    }
    #pragma unroll
    for (int it = 0; it < 13; it++) {
        int idx = tid + 256 * it;
        int row = idx >> 4, c4 = (idx & 15) * 4;
        float4 kv = make_float4(0.f, 0.f, 0.f, 0.f);
        float4 vv = make_float4(0.f, 0.f, 0.f, 0.f);
        if (row < NN) {
            kv = *(const float4*)(kp + (size_t)row * kvs + c4);
            vv = *(const float4*)(vp + (size_t)row * kvs + c4);
        }
        Kw[row * QWS + (c4 >> 1)]     = pkbf(kv.x, kv.y);
        Kw[row * QWS + (c4 >> 1) + 1] = pkbf(kv.z, kv.w);
        Vw[row * QWS + (c4 >> 1)]     = pkbf(vv.x, vv.y);
        Vw[row * QWS + (c4 >> 1) + 1] = pkbf(vv.z, vv.w);
    }
    __syncthreads();

    const int n0 = wn * 104;
    float sc[13][4];
    #pragma unroll
    for (int j = 0; j < 13; j++)
        #pragma unroll
        for (int t = 0; t < 4; t++) sc[j][t] = 0.f;

    #pragma unroll
    for (int kt = 0; kt < 4; kt++) {
        unsigned a[4];
        const unsigned* ap = Qw + (wm * 16 + r) * QWS + kt * 8 + q;
        a[0] = ap[0];
        a[1] = ap[8 * QWS];
        a[2] = ap[4];
        a[3] = ap[8 * QWS + 4];
        #pragma unroll
        for (int j = 0; j < 13; j++) {
            unsigned b[2];
            const unsigned* bp = Kw + (n0 + j * 8 + r) * QWS + kt * 8 + q;
            b[0] = bp[0];
            b[1] = bp[4];
            mma16(sc[j], a, b);
        }
    }

    #pragma unroll
    for (int j = 0; j < 13; j++) {
        int cbase = n0 + j * 8 + 2 * q;
        #pragma unroll
        for (int t = 0; t < 4; t++) {
            int col = cbase + (t & 1);
            sc[j][t] = (col < NN) ? sc[j][t] * ATTN_SCALE : -1e30f;
        }
    }

    float mx0 = -1e30f, mx1 = -1e30f;
    #pragma unroll
    for (int j = 0; j < 13; j++) {
        mx0 = fmaxf(mx0, fmaxf(sc[j][0], sc[j][1]));
        mx1 = fmaxf(mx1, fmaxf(sc[j][2], sc[j][3]));
    }
    mx0 = fmaxf(mx0, __shfl_xor_sync(0xffffffffu, mx0, 1));
    mx0 = fmaxf(mx0, __shfl_xor_sync(0xffffffffu, mx0, 2));
    mx1 = fmaxf(mx1, __shfl_xor_sync(0xffffffffu, mx1, 1));
    mx1 = fmaxf(mx1, __shfl_xor_sync(0xffffffffu, mx1, 2));
    int rowl = wm * 16 + r;
    if (q == 0) {
        redmax[wn * 64 + rowl] = mx0;
        redmax[wn * 64 + rowl + 8] = mx1;
    }
    __syncthreads();
    float fm0 = fmaxf(redmax[rowl], redmax[64 + rowl]);
    float fm1 = fmaxf(redmax[rowl + 8], redmax[64 + rowl + 8]);

    float s0 = 0.f, s1 = 0.f;
    #pragma unroll
    for (int j = 0; j < 13; j++) {
        sc[j][0] = __expf(sc[j][0] - fm0);
        sc[j][1] = __expf(sc[j][1] - fm0);
        sc[j][2] = __expf(sc[j][2] - fm1);
        sc[j][3] = __expf(sc[j][3] - fm1);
        s0 += sc[j][0] + sc[j][1];
        s1 += sc[j][2] + sc[j][3];
    }
    s0 += __shfl_xor_sync(0xffffffffu, s0, 1);
    s0 += __shfl_xor_sync(0xffffffffu, s0, 2);
    s1 += __shfl_xor_sync(0xffffffffu, s1, 1);
    s1 += __shfl_xor_sync(0xffffffffu, s1, 2);
    if (q == 0) {
        redsum[wn * 64 + rowl] = s0;
        redsum[wn * 64 + rowl + 8] = s1;
    }
    #pragma unroll
    for (int j = 0; j < 13; j++) {
        int wbase = (n0 >> 1) + j * 4 + q;
        Pw[rowl * PWS + wbase]       = pkbf(sc[j][0], sc[j][1]);
        Pw[(rowl + 8) * PWS + wbase] = pkbf(sc[j][2], sc[j][3]);
    }
    __syncthreads();

    const int oc0 = wn * 32;
    float oacc[4][4];
    #pragma unroll
    for (int j = 0; j < 4; j++)
        #pragma unroll
        for (int t = 0; t < 4; t++) oacc[j][t] = 0.f;

    const int lrow = lane & 15;
    const int lcol = (lane >> 4) * 8;
    #pragma unroll
    for (int kt = 0; kt < 13; kt++) {
        unsigned a[4];
        const unsigned* ap2 = Pw + rowl * PWS + kt * 8 + q;
        a[0] = ap2[0];
        a[1] = ap2[8 * PWS];
        a[2] = ap2[4];
        a[3] = ap2[8 * PWS + 4];
        #pragma unroll
        for (int jp = 0; jp < 2; jp++) {
            unsigned b4[4];
            unsigned addr = sbase + (unsigned)(W_V * 4) +
                (unsigned)((kt * 16 + lrow) * 72 + oc0 + jp * 16 + lcol) * 2u;
            ldmx4t(b4, addr);
            mma16(oacc[jp * 2 + 0], a, b4 + 0);
            mma16(oacc[jp * 2 + 1], a, b4 + 2);
        }
    }

    float inv0 = 1.0f / (redsum[rowl] + redsum[64 + rowl]);
    float inv1 = 1.0f / (redsum[rowl + 8] + redsum[64 + rowl + 8]);
    int mg0 = m0 + rowl, mg1 = m0 + rowl + 8;
    #pragma unroll
    for (int j = 0; j < 4; j++) {
        int col = oc0 + j * 8 + 2 * q;
        if (mg0 < NN)
            *(float2*)(op + (size_t)mg0 * CC + col) =
                make_float2(tf32r(oacc[j][0] * inv0), tf32r(oacc[j][1] * inv0));
        if (mg1 < NN)
            *(float2*)(op + (size_t)mg1 * CC + col) =
                make_float2(tf32r(oacc[j][2] * inv1), tf32r(oacc[j][3] * inv1));
    }
}

// ------------------------------- launch -------------------------------------
extern "C" void kernel_launch(void* const* d_in, const int* in_sizes, int n_in,
                              void* d_out, int out_size) {
    int sh = (in_sizes[5] == 1) ? 0 : -1;

    const float* xs  = (const float*)d_in[0];
    const float* ys  = (const float*)d_in[1];
    const int* rel   = (const int*)d_in[4];
    const float* qkv_w = (const float*)d_in[6 + sh];
    const float* ap_w  = (const float*)d_in[7 + sh];
    const float* ap_b  = (const float*)d_in[8 + sh];
    const float* q_w   = (const float*)d_in[9 + sh];
    const float* k_w   = (const float*)d_in[10 + sh];
    const float* v_w   = (const float*)d_in[11 + sh];
    const float* cp_w  = (const float*)d_in[12 + sh];
    const float* cp_b  = (const float*)d_in[13 + sh];
    const float* fc1_w = (const float*)d_in[14 + sh];
    const float* fc1_b = (const float*)d_in[15 + sh];
    const float* fc2_w = (const float*)d_in[16 + sh];
    const float* fc2_b = (const float*)d_in[17 + sh];
    const float* ln1w = (const float*)d_in[18 + sh];
    const float* ln1b = (const float*)d_in[19 + sh];
    const float* ln2w = (const float*)d_in[20 + sh];
    const float* ln2b = (const float*)d_in[21 + sh];
    const float* ln3w = (const float*)d_in[22 + sh];
    const float* ln3b = (const float*)d_in[23 + sh];
    const float* lnyw = (const float*)d_in[24 + sh];
    const float* lnyb = (const float*)d_in[25 + sh];
    float* out = (float*)d_out;

    float *x, *h, *yn, *qkv, *q, *o, *big, *big2, *wr;
    cudaGetSymbolAddress((void**)&x, g_x);
    cudaGetSymbolAddress((void**)&h, g_h);
    cudaGetSymbolAddress((void**)&yn, g_yn);
    cudaGetSymbolAddress((void**)&qkv, g_qkv);
    cudaGetSymbolAddress((void**)&q, g_q);
    cudaGetSymbolAddress((void**)&o, g_o);
    cudaGetSymbolAddress((void**)&big, g_big);
    cudaGetSymbolAddress((void**)&big2, g_big2);
    cudaGetSymbolAddress((void**)&wr, g_wr);

    cudaFuncSetAttribute(gemm_tf32<0>, cudaFuncAttributeMaxDynamicSharedMemorySize, GEMM_SMEM);
    cudaFuncSetAttribute(gemm_tf32<1>, cudaFuncAttributeMaxDynamicSharedMemorySize, GEMM_SMEM);
    cudaFuncSetAttribute(gemm_tf32<2>, cudaFuncAttributeMaxDynamicSharedMemorySize, GEMM_SMEM);
    cudaFuncSetAttribute(gemm_tf32<3>, cudaFuncAttributeMaxDynamicSharedMemorySize, GEMM_SMEM);
    cudaFuncSetAttribute(attn_bf16<false>, cudaFuncAttributeMaxDynamicSharedMemorySize, ATTN_SMEM);
    cudaFuncSetAttribute(attn_bf16<true>,  cudaFuncAttributeMaxDynamicSharedMemorySize, ATTN_SMEM);

    round_all_kernel<<<dim3(HID * CC / 4 / 256, 8), 256>>>(
        (const float4*)qkv_w, (const float4*)ap_w, (const float4*)q_w,
        (const float4*)k_w, (const float4*)v_w, (const float4*)cp_w,
        (const float4*)fc1_w, (const float4*)fc2_w, (float4*)wr);

    // ---- self attention ----
    layernorm_kernel<<<T, 256>>>(xs, ln1w, ln1b, h);
    gemm_tf32<0><<<dim3(18, T / 128), 256, GEMM_SMEM>>>(h, wr + WO_QKV, nullptr, nullptr, qkv, T, 3 * CC, CC);
    attn_bf16<false><<<dim3(4, PSELF), 256, ATTN_SMEM>>>(qkv, qkv, nullptr, o);
    gemm_tf32<2><<<dim3(6, T / 128), 256, GEMM_SMEM>>>(o, wr + WO_AP, ap_b, xs, x, T, CC, CC);

    // ---- cross attention ----
    layernorm_kernel<<<T, 256>>>(x, ln2w, ln2b, h);
    layernorm_kernel<<<T, 256>>>(ys, lnyw, lnyb, yn);
    gemm_tf32<0><<<dim3(6, T / 128), 256, GEMM_SMEM>>>(h, wr + WO_Q, nullptr, nullptr, q, T, CC, CC);
    gemm_tf32<0><<<dim3(12, T / 128), 256, GEMM_SMEM>>>(yn, wr + WO_K, nullptr, nullptr, qkv, T, 2 * CC, CC);
    attn_bf16<true><<<dim3(4, PCROSS), 256, ATTN_SMEM>>>(q, qkv, rel, big);
    gemm_tf32<1><<<dim3(6, TT / 128), 256, GEMM_SMEM>>>(big, wr + WO_CP, cp_b, nullptr, big2, TT, CC, CC);
    merge_kernel<<<(T * CC + 255) / 256, 256>>>(big2, x);

    // ---- MLP ----
    layernorm_kernel<<<T, 256>>>(x, ln3w, ln3b, h);
    gemm_tf32<3><<<dim3(24, T / 128), 256, GEMM_SMEM>>>(h, wr + WO_FC1, fc1_b, nullptr, big2, T, HID, CC);
    gemm_tf32<2><<<dim3(6, T / 128), 256, GEMM_SMEM>>>(big2, wr + WO_FC2, fc2_b, x, out, T, CC, HID);
}

// round 11
// speedup vs baseline: 1.4457x; 1.4457x over previous
#include <cuda_runtime.h>
#include <cuda_fp16.h>
#include <math.h>
#include <stdint.h>

// ---------------------------------------------------------------------------
// MultiviewDecoderBlock (Vx=8, Vy=8, B=4, N=196, C=768, H=12, DH=64, M=4)
// fp16-operand GEMMs (cp.async 3-stage, m16n8k16, fp32 accum) + fp16 mma
// attention. fp16 mantissa == tf32 mantissa -> same accuracy, 2x mma rate.
// ---------------------------------------------------------------------------

constexpr int VX = 8, BB = 4, NN = 196, CC = 768, HH = 12, DHH = 64, MV = 4;
constexpr int HID = 4 * CC;            // 3072
constexpr int VB = VX * BB;            // 32
constexpr int T  = VB * NN;            // 6272
constexpr int TT = VX * MV * BB * NN;  // 25088
constexpr int PSELF  = VB * HH;            // 384
constexpr int PCROSS = VX * MV * BB * HH;  // 1536
constexpr float ATTN_SCALE = 0.125f;

// -------------------------- device scratch ---------------------------------
__device__ __align__(256) float  g_x   [T * CC];       // residual stream (fp32)
__device__ __align__(256) float  g_big2[TT * CC];      // cross-proj out (fp32)
__device__ __align__(256) __half g_h   [T * CC];       // LN out
__device__ __align__(256) __half g_yn  [T * CC];
__device__ __align__(256) __half g_qkv [T * 3 * CC];   // self qkv; later cross k|v
__device__ __align__(256) __half g_q   [T * CC];
__device__ __align__(256) __half g_o   [T * CC];
__device__ __align__(256) __half g_big [TT * CC];      // cross attn out; later MLP hidden
__device__ __align__(256) __half g_wh  [9437184];      // fp16 weights

constexpr int WO_QKV = 0;
constexpr int WO_AP  = 3 * CC * CC;
constexpr int WO_Q   = WO_AP  + CC * CC;
constexpr int WO_K   = WO_Q   + CC * CC;   // k|v contiguous -> fused N=1536 GEMM
constexpr int WO_V   = WO_K   + CC * CC;
constexpr int WO_CP  = WO_V   + CC * CC;
constexpr int WO_FC1 = WO_CP  + CC * CC;
constexpr int WO_FC2 = WO_FC1 + HID * CC;

extern __shared__ __align__(16) unsigned char dyn_smem[];

// ----------------------------- helpers -------------------------------------
__device__ __forceinline__ unsigned pkh(float lo, float hi) {
    unsigned r;
    asm("cvt.rn.f16x2.f32 %0, %1, %2;" : "=r"(r) : "f"(hi), "f"(lo));
    return r;
}
__device__ __forceinline__ void mma16h(float* c, const unsigned* a, const unsigned* b) {
    asm volatile(
        "mma.sync.aligned.m16n8k16.row.col.f32.f16.f16.f32 "
        "{%0,%1,%2,%3},{%4,%5,%6,%7},{%8,%9},{%0,%1,%2,%3};\n"
        : "+f"(c[0]), "+f"(c[1]), "+f"(c[2]), "+f"(c[3])
        : "r"(a[0]), "r"(a[1]), "r"(a[2]), "r"(a[3]), "r"(b[0]), "r"(b[1]));
}
__device__ __forceinline__ void ldmx4t(unsigned* d, unsigned addr) {
    asm volatile("ldmatrix.sync.aligned.m8n8.x4.trans.shared.b16 {%0,%1,%2,%3}, [%4];"
                 : "=r"(d[0]), "=r"(d[1]), "=r"(d[2]), "=r"(d[3]) : "r"(addr));
}
__device__ __forceinline__ void cp16(unsigned d, const void* s) {
    asm volatile("cp.async.cg.shared.global [%0], [%1], 16;" :: "r"(d), "l"(s));
}

// ----------------------------- utility kernels ------------------------------
// one launch converts all 8 weight matrices to fp16
__global__ void round_all_kernel(
    const float4* s0, const float4* s1, const float4* s2, const float4* s3,
    const float4* s4, const float4* s5, const float4* s6, const float4* s7,
    __half* dst)
{
    const int seg = blockIdx.y;
    const float4* srcs[8] = {s0, s1, s2, s3, s4, s5, s6, s7};
    const int sizes4[8] = {3*CC*CC/4, CC*CC/4, CC*CC/4, CC*CC/4,
                           CC*CC/4, CC*CC/4, HID*CC/4, CC*HID/4};
    const int offs4[8] = {WO_QKV/4, WO_AP/4, WO_Q/4, WO_K/4,
                          WO_V/4, WO_CP/4, WO_FC1/4, WO_FC2/4};
    int i = blockIdx.x * blockDim.x + threadIdx.x;
    if (i < sizes4[seg]) {
        float4 v = srcs[seg][i];
        __half2* d = (__half2*)(dst + (size_t)(offs4[seg] + i) * 4);
        d[0] = __floats2half2_rn(v.x, v.y);
        d[1] = __floats2half2_rn(v.z, v.w);
    }
}

__global__ void layernorm_kernel(const float* __restrict__ in,
                                 const float* __restrict__ w,
                                 const float* __restrict__ b,
                                 __half* __restrict__ out) {
    int row = blockIdx.x;
    const float* xr = in + (size_t)row * CC;
    __half* orow = out + (size_t)row * CC;
    int tid = threadIdx.x;
    float v0 = xr[tid], v1 = xr[tid + 256], v2 = xr[tid + 512];
    float s  = v0 + v1 + v2;
    float sq = v0 * v0 + v1 * v1 + v2 * v2;
    #pragma unroll
    for (int off = 16; off; off >>= 1) {
        s  += __shfl_xor_sync(0xffffffffu, s, off);
        sq += __shfl_xor_sync(0xffffffffu, sq, off);
    }
    __shared__ float red[2][8];
    int warp = tid >> 5, lane = tid & 31;
    if (lane == 0) { red[0][warp] = s; red[1][warp] = sq; }
    __syncthreads();
    float ts = 0.f, tsq = 0.f;
    #pragma unroll
    for (int i = 0; i < 8; i++) { ts += red[0][i]; tsq += red[1][i]; }
    float mu = ts * (1.0f / CC);
    float var = tsq * (1.0f / CC) - mu * mu;
    float rstd = rsqrtf(var + 1e-5f);
    orow[tid]       = __float2half_rn((v0 - mu) * rstd * w[tid]       + b[tid]);
    orow[tid + 256] = __float2half_rn((v1 - mu) * rstd * w[tid + 256] + b[tid + 256]);
    orow[tid + 512] = __float2half_rn((v2 - mu) * rstd * w[tid + 512] + b[tid + 512]);
}

__global__ void merge_kernel(const float* __restrict__ proj, float* __restrict__ x) {
    int idx = blockIdx.x * blockDim.x + threadIdx.x;
    if (idx >= T * CC) return;
    int c = idx % CC;
    int n = (idx / CC) % NN;
    int b = (idx / (CC * NN)) % BB;
    int v = idx / (CC * NN * BB);
    size_t base = ((((size_t)v * MV) * BB + b) * NN + n) * CC + c;
    size_t ms = (size_t)BB * NN * CC;
    float mx = proj[base];
    #pragma unroll
    for (int m = 1; m < MV; m++) mx = fmaxf(mx, proj[base + (size_t)m * ms]);
    x[idx] += mx;
}

// --------------- fp16 GEMM, cp.async 3 stages, m16n8k16 ---------------------
// C = A @ B^T. A:(M,K) B:(N,K) row-major __half. fp32 accumulate.
// 128x128x32 tile, 256 thr, warp tile 64x32.
// smem rows padded to 20 words (16 data + 4 pad) -> conflict-free scalar
// fragment loads without XOR swizzle.
// EPI: 0=store half, 1=+bias(f32 out), 2=+bias+residual(f32 out),
//      3=+bias+gelu(exact) half out
constexpr int GSTAGES = 3;
constexpr int WR  = 20;             // words per smem row (padded)
constexpr int WPS = 128 * WR;       // words per stage
constexpr int ASTG = WPS * 4;       // 10240 bytes
constexpr int GEMM_SMEM = GSTAGES * 2 * ASTG;  // 61440

template<int EPI>
__global__ void __launch_bounds__(256, 2) gemm_f16(
    const __half* __restrict__ A, const __half* __restrict__ Bw,
    const float* __restrict__ bias, const float* __restrict__ res,
    void* __restrict__ Cv, int Mdim, int Ndim, int Kdim)
{
    const unsigned sbase = (unsigned)__cvta_generic_to_shared(dyn_smem);
    const int tid = threadIdx.x;
    const int lane = tid & 31, warp = tid >> 5;
    const int wm = (warp >> 2) * 64;
    const int wn = (warp & 3) * 32;
    const int bm = blockIdx.y * 128, bn = blockIdx.x * 128;

    // cp.async: 2 granules (16B = 8 halves) per matrix per thread per stage
    const int grow = tid >> 2, gg = tid & 3;
    const __half* Ag0 = A  + (size_t)(bm + grow) * Kdim + gg * 8;
    const __half* Ag1 = A  + (size_t)(bm + grow + 64) * Kdim + gg * 8;
    const __half* Bg0 = Bw + (size_t)(bn + grow) * Kdim + gg * 8;
    const __half* Bg1 = Bw + (size_t)(bn + grow + 64) * Kdim + gg * 8;
    const unsigned da0 = sbase + (unsigned)(grow * 80 + gg * 16);
    const unsigned da1 = da0 + 64 * 80;
    const unsigned db0 = da0 + GSTAGES * ASTG;
    const unsigned db1 = da1 + GSTAGES * ASTG;

    float acc[4][4][4];
    #pragma unroll
    for (int i = 0; i < 4; i++)
        #pragma unroll
        for (int j = 0; j < 4; j++)
            #pragma unroll
            for (int t = 0; t < 4; t++) acc[i][j][t] = 0.f;

    const int nk = Kdim >> 5;
    #pragma unroll
    for (int s = 0; s < GSTAGES - 1; s++) {
        unsigned off = (unsigned)s * ASTG;
        int koff = s * 32;
        cp16(da0 + off, Ag0 + koff);
        cp16(da1 + off, Ag1 + koff);
        cp16(db0 + off, Bg0 + koff);
        cp16(db1 + off, Bg1 + koff);
        asm volatile("cp.async.commit_group;");
    }

    const int r = lane >> 2, q = lane & 3;
    const unsigned* Wb = (const unsigned*)dyn_smem;
    #pragma unroll 1
    for (int kt = 0; kt < nk; kt++) {
        asm volatile("cp.async.wait_group 1;");
        __syncthreads();
        const int buf = kt % GSTAGES;
        const unsigned* Ab = Wb + buf * WPS;
        const unsigned* Bb = Wb + GSTAGES * WPS + buf * WPS;
        #pragma unroll
        for (int c = 0; c < 2; c++) {
            unsigned a[4][4], b[4][2];
            #pragma unroll
            for (int mf = 0; mf < 4; mf++) {
                const unsigned* p = Ab + (wm + mf * 16 + r) * WR + c * 8 + q;
                a[mf][0] = p[0];
                a[mf][1] = p[8 * WR];
                a[mf][2] = p[4];
                a[mf][3] = p[8 * WR + 4];
            }
            #pragma unroll
            for (int nf = 0; nf < 4; nf++) {
                const unsigned* p = Bb + (wn + nf * 8 + r) * WR + c * 8 + q;
                b[nf][0] = p[0];
                b[nf][1] = p[4];
            }
            #pragma unroll
            for (int mf = 0; mf < 4; mf++)
                #pragma unroll
                for (int nf = 0; nf < 4; nf++)
                    mma16h(acc[mf][nf], a[mf], b[nf]);
        }
        if (kt + GSTAGES - 1 < nk) {
            unsigned off = (unsigned)((kt + GSTAGES - 1) % GSTAGES) * ASTG;
            int koff = (kt + GSTAGES - 1) * 32;
            cp16(da0 + off, Ag0 + koff);
            cp16(da1 + off, Ag1 + koff);
            cp16(db0 + off, Bg0 + koff);
            cp16(db1 + off, Bg1 + koff);
        }
        asm volatile("cp.async.commit_group;");
    }

    #pragma unroll
    for (int mf = 0; mf < 4; mf++) {
        #pragma unroll
        for (int nf = 0; nf < 4; nf++) {
            const int col = bn + wn + nf * 8 + (lane & 3) * 2;
            float bb0 = 0.f, bb1 = 0.f;
            if (EPI >= 1) { bb0 = bias[col]; bb1 = bias[col + 1]; }
            #pragma unroll
            for (int hh = 0; hh < 2; hh++) {
                const size_t row = (size_t)(bm + wm + mf * 16 + (lane >> 2) + hh * 8);
                float v0 = acc[mf][nf][hh * 2 + 0] + bb0;
                float v1 = acc[mf][nf][hh * 2 + 1] + bb1;
                if (EPI == 2) {
                    v0 += res[row * Ndim + col];
                    v1 += res[row * Ndim + col + 1];
                }
                if (EPI == 3) {
                    v0 = 0.5f * v0 * (1.0f + erff(v0 * 0.70710678118654752f));
                    v1 = 0.5f * v1 * (1.0f + erff(v1 * 0.70710678118654752f));
                }
                if (EPI == 0 || EPI == 3) {
                    __half* C = (__half*)Cv;
                    *(unsigned*)(C + row * Ndim + col) = pkh(v0, v1);
                } else {
                    float* C = (float*)Cv;
                    *(float2*)(C + row * Ndim + col) = make_float2(v0, v1);
                }
            }
        }
    }
}

// ------------------------- fp16 mma attention -------------------------------
// Same structure as bf16 version; operands fp16, fp32 softmax.
// CROSS reads fused k|v buffer (stride 1536).
constexpr int QWS = 36;
constexpr int PWS = 108;
constexpr int W_Q = 0;
constexpr int W_K = 2304;
constexpr int W_V = 9792;
constexpr int W_RED = 17280;
constexpr int ATTN_SMEM = (W_RED + 256) * 4;  // 70144 bytes

template<bool CROSS>
__global__ void __launch_bounds__(256) attn_f16(
    const __half* __restrict__ Qsrc, const __half* __restrict__ Ksrc,
    const int* __restrict__ rel, __half* __restrict__ Out)
{
    unsigned* W = (unsigned*)dyn_smem;
    unsigned* Qw = W + W_Q;
    unsigned* Kw = W + W_K;
    unsigned* Vw = W + W_V;
    unsigned* Pw = W;
    float* redmax = (float*)(W + W_RED);
    float* redsum = redmax + 128;
    const unsigned sbase = (unsigned)__cvta_generic_to_shared(dyn_smem);

    const int p = blockIdx.y;
    const int m0 = blockIdx.x * 64;
    const int tid = threadIdx.x;
    const int lane = tid & 31, warp = tid >> 5;
    const int wm = warp & 3, wn = warp >> 2;
    const int r = lane >> 2, q = lane & 3;

    const __half *qp, *kp, *vp;
    __half* op;
    int qrs, kvs;
    if (!CROSS) {
        int vb = p / HH, h2 = p % HH;
        const __half* base = Qsrc + (size_t)vb * NN * 3 * CC;
        qp = base + h2 * DHH;
        kp = base + CC + h2 * DHH;
        vp = base + 2 * CC + h2 * DHH;
        qrs = 3 * CC; kvs = 3 * CC;
        op = Out + (size_t)vb * NN * CC + h2 * DHH;
    } else {
        int h2 = p % HH; int rr = p / HH;
        int b = rr % BB; int r2 = rr / BB;
        int mvi = r2 % MV; int v = r2 / MV;
        int vy = rel[v * MV + mvi];
        qp = Qsrc + ((size_t)(v * BB + b) * NN) * CC + h2 * DHH; qrs = CC;
        kp = Ksrc + ((size_t)(vy * BB + b) * NN) * 1536 + h2 * DHH;
        vp = kp + CC;
        kvs = 1536;
        op = Out + (size_t)rr * NN * CC + h2 * DHH;
    }

    // loads: raw copies, no conversion (data already fp16)
    #pragma unroll
    for (int it = 0; it < 4; it++) {
        int idx = tid + 256 * it;
        int row = idx >> 4, w2 = (idx & 15) * 2;
        uint2 qv = make_uint2(0u, 0u);
        if (m0 + row < NN) qv = *(const uint2*)(qp + (size_t)(m0 + row) * qrs + w2 * 2);
        Qw[row * QWS + w2]     = qv.x;
        Qw[row * QWS + w2 + 1] = qv.y;
    }
    #pragma unroll
    for (int it = 0; it < 13; it++) {
        int idx = tid + 256 * it;
        int row = idx >> 4, w2 = (idx & 15) * 2;
        uint2 kv = make_uint2(0u, 0u);
        uint2 vv = make_uint2(0u, 0u);
        if (row < NN) {
            kv = *(const uint2*)(kp + (size_t)row * kvs + w2 * 2);
            vv = *(const uint2*)(vp + (size_t)row * kvs + w2 * 2);
        }
        Kw[row * QWS + w2]     = kv.x;
        Kw[row * QWS + w2 + 1] = kv.y;
        Vw[row * QWS + w2]     = vv.x;
        Vw[row * QWS + w2 + 1] = vv.y;
    }
    __syncthreads();

    const int n0 = wn * 104;
    float sc[13][4];
    #pragma unroll
    for (int j = 0; j < 13; j++)
        #pragma unroll
        for (int t = 0; t < 4; t++) sc[j][t] = 0.f;

    #pragma unroll
    for (int kt = 0; kt < 4; kt++) {
        unsigned a[4];
        const unsigned* ap = Qw + (wm * 16 + r) * QWS + kt * 8 + q;
        a[0] = ap[0];
        a[1] = ap[8 * QWS];
        a[2] = ap[4];
        a[3] = ap[8 * QWS + 4];
        #pragma unroll
        for (int j = 0; j < 13; j++) {
            unsigned b[2];
            const unsigned* bp = Kw + (n0 + j * 8 + r) * QWS + kt * 8 + q;
            b[0] = bp[0];
            b[1] = bp[4];
            mma16h(sc[j], a, b);
        }
    }

    #pragma unroll
    for (int j = 0; j < 13; j++) {
        int cbase = n0 + j * 8 + 2 * q;
        #pragma unroll
        for (int t = 0; t < 4; t++) {
            int col = cbase + (t & 1);
            sc[j][t] = (col < NN) ? sc[j][t] * ATTN_SCALE : -1e30f;
        }
    }

    float mx0 = -1e30f, mx1 = -1e30f;
    #pragma unroll
    for (int j = 0; j < 13; j++) {
        mx0 = fmaxf(mx0, fmaxf(sc[j][0], sc[j][1]));
        mx1 = fmaxf(mx1, fmaxf(sc[j][2], sc[j][3]));
    }
    mx0 = fmaxf(mx0, __shfl_xor_sync(0xffffffffu, mx0, 1));
    mx0 = fmaxf(mx0, __shfl_xor_sync(0xffffffffu, mx0, 2));
    mx1 = fmaxf(mx1, __shfl_xor_sync(0xffffffffu, mx1, 1));
    mx1 = fmaxf(mx1, __shfl_xor_sync(0xffffffffu, mx1, 2));
    int rowl = wm * 16 + r;
    if (q == 0) {
        redmax[wn * 64 + rowl] = mx0;
        redmax[wn * 64 + rowl + 8] = mx1;
    }
    __syncthreads();
    float fm0 = fmaxf(redmax[rowl], redmax[64 + rowl]);
    float fm1 = fmaxf(redmax[rowl + 8], redmax[64 + rowl + 8]);

    float s0 = 0.f, s1 = 0.f;
    #pragma unroll
    for (int j = 0; j < 13; j++) {
        sc[j][0] = __expf(sc[j][0] - fm0);
        sc[j][1] = __expf(sc[j][1] - fm0);
        sc[j][2] = __expf(sc[j][2] - fm1);
        sc[j][3] = __expf(sc[j][3] - fm1);
        s0 += sc[j][0] + sc[j][1];
        s1 += sc[j][2] + sc[j][3];
    }
    s0 += __shfl_xor_sync(0xffffffffu, s0, 1);
    s0 += __shfl_xor_sync(0xffffffffu, s0, 2);
    s1 += __shfl_xor_sync(0xffffffffu, s1, 1);
    s1 += __shfl_xor_sync(0xffffffffu, s1, 2);
    if (q == 0) {
        redsum[wn * 64 + rowl] = s0;
        redsum[wn * 64 + rowl + 8] = s1;
    }
    #pragma unroll
    for (int j = 0; j < 13; j++) {
        int wbase = (n0 >> 1) + j * 4 + q;
        Pw[rowl * PWS + wbase]       = pkh(sc[j][0], sc[j][1]);
        Pw[(rowl + 8) * PWS + wbase] = pkh(sc[j][2], sc[j][3]);
    }
    __syncthreads();

    const int oc0 = wn * 32;
    float oacc[4][4];
    #pragma unroll
    for (int j = 0; j < 4; j++)
        #pragma unroll
        for (int t = 0; t < 4; t++) oacc[j][t] = 0.f;

    const int lrow = lane & 15;
    const int lcol = (lane >> 4) * 8;
    #pragma unroll
    for (int kt = 0; kt < 13; kt++) {
        unsigned a[4];
        const unsigned* ap2 = Pw + rowl * PWS + kt * 8 + q;
        a[0] = ap2[0];
        a[1] = ap2[8 * PWS];
        a[2] = ap2[4];
        a[3] = ap2[8 * PWS + 4];
        #pragma unroll
        for (int jp = 0; jp < 2; jp++) {
            unsigned b4[4];
            unsigned addr = sbase + (unsigned)(W_V * 4) +
                (unsigned)((kt * 16 + lrow) * 72 + oc0 + jp * 16 + lcol) * 2u;
            ldmx4t(b4, addr);
            mma16h(oacc[jp * 2 + 0], a, b4 + 0);
            mma16h(oacc[jp * 2 + 1], a, b4 + 2);
        }
    }

    float inv0 = 1.0f / (redsum[rowl] + redsum[64 + rowl]);
    float inv1 = 1.0f / (redsum[rowl + 8] + redsum[64 + rowl + 8]);
    int mg0 = m0 + rowl, mg1 = m0 + rowl + 8;
    #pragma unroll
    for (int j = 0; j < 4; j++) {
        int col = oc0 + j * 8 + 2 * q;
        if (mg0 < NN)
            *(unsigned*)(op + (size_t)mg0 * CC + col) =
                pkh(oacc[j][0] * inv0, oacc[j][1] * inv0);
        if (mg1 < NN)
            *(unsigned*)(op + (size_t)mg1 * CC + col) =
                pkh(oacc[j][2] * inv1, oacc[j][3] * inv1);
    }
}

// ------------------------------- launch -------------------------------------
extern "C" void kernel_launch(void* const* d_in, const int* in_sizes, int n_in,
                              void* d_out, int out_size) {
    int sh = (in_sizes[5] == 1) ? 0 : -1;

    const float* xs  = (const float*)d_in[0];
    const float* ys  = (const float*)d_in[1];
    const int* rel   = (const int*)d_in[4];
    const float* qkv_w = (const float*)d_in[6 + sh];
    const float* ap_w  = (const float*)d_in[7 + sh];
    const float* ap_b  = (const float*)d_in[8 + sh];
    const float* q_w   = (const float*)d_in[9 + sh];
    const float* k_w   = (const float*)d_in[10 + sh];
    const float* v_w   = (const float*)d_in[11 + sh];
    const float* cp_w  = (const float*)d_in[12 + sh];
    const float* cp_b  = (const float*)d_in[13 + sh];
    const float* fc1_w = (const float*)d_in[14 + sh];
    const float* fc1_b = (const float*)d_in[15 + sh];
    const float* fc2_w = (const float*)d_in[16 + sh];
    const float* fc2_b = (const float*)d_in[17 + sh];
    const float* ln1w = (const float*)d_in[18 + sh];
    const float* ln1b = (const float*)d_in[19 + sh];
    const float* ln2w = (const float*)d_in[20 + sh];
    const float* ln2b = (const float*)d_in[21 + sh];
    const float* ln3w = (const float*)d_in[22 + sh];
    const float* ln3b = (const float*)d_in[23 + sh];
    const float* lnyw = (const float*)d_in[24 + sh];
    const float* lnyb = (const float*)d_in[25 + sh];
    float* out = (float*)d_out;

    float *x, *big2;
    __half *h, *yn, *qkv, *q, *o, *big, *wh;
    cudaGetSymbolAddress((void**)&x, g_x);
    cudaGetSymbolAddress((void**)&big2, g_big2);
    cudaGetSymbolAddress((void**)&h, g_h);
    cudaGetSymbolAddress((void**)&yn, g_yn);
    cudaGetSymbolAddress((void**)&qkv, g_qkv);
    cudaGetSymbolAddress((void**)&q, g_q);
    cudaGetSymbolAddress((void**)&o, g_o);
    cudaGetSymbolAddress((void**)&big, g_big);
    cudaGetSymbolAddress((void**)&wh, g_wh);

    cudaFuncSetAttribute(gemm_f16<0>, cudaFuncAttributeMaxDynamicSharedMemorySize, GEMM_SMEM);
    cudaFuncSetAttribute(gemm_f16<1>, cudaFuncAttributeMaxDynamicSharedMemorySize, GEMM_SMEM);
    cudaFuncSetAttribute(gemm_f16<2>, cudaFuncAttributeMaxDynamicSharedMemorySize, GEMM_SMEM);
    cudaFuncSetAttribute(gemm_f16<3>, cudaFuncAttributeMaxDynamicSharedMemorySize, GEMM_SMEM);
    cudaFuncSetAttribute(attn_f16<false>, cudaFuncAttributeMaxDynamicSharedMemorySize, ATTN_SMEM);
    cudaFuncSetAttribute(attn_f16<true>,  cudaFuncAttributeMaxDynamicSharedMemorySize, ATTN_SMEM);

    // convert all weights to fp16 (one launch)
    round_all_kernel<<<dim3(HID * CC / 4 / 256, 8), 256>>>(
        (const float4*)qkv_w, (const float4*)ap_w, (const float4*)q_w,
        (const float4*)k_w, (const float4*)v_w, (const float4*)cp_w,
        (const float4*)fc1_w, (const float4*)fc2_w, wh);

    // ---- self attention ----
    layernorm_kernel<<<T, 256>>>(xs, ln1w, ln1b, h);
    gemm_f16<0><<<dim3(18, T / 128), 256, GEMM_SMEM>>>(h, wh + WO_QKV, nullptr, nullptr, qkv, T, 3 * CC, CC);
    attn_f16<false><<<dim3(4, PSELF), 256, ATTN_SMEM>>>(qkv, qkv, nullptr, o);
    gemm_f16<2><<<dim3(6, T / 128), 256, GEMM_SMEM>>>(o, wh + WO_AP, ap_b, xs, x, T, CC, CC);

    // ---- cross attention ----
    layernorm_kernel<<<T, 256>>>(x, ln2w, ln2b, h);
    layernorm_kernel<<<T, 256>>>(ys, lnyw, lnyb, yn);
    gemm_f16<0><<<dim3(6, T / 128), 256, GEMM_SMEM>>>(h, wh + WO_Q, nullptr, nullptr, q, T, CC, CC);
    gemm_f16<0><<<dim3(12, T / 128), 256, GEMM_SMEM>>>(yn, wh + WO_K, nullptr, nullptr, qkv, T, 2 * CC, CC);
    attn_f16<true><<<dim3(4, PCROSS), 256, ATTN_SMEM>>>(q, qkv, rel, big);
    gemm_f16<1><<<dim3(6, TT / 128), 256, GEMM_SMEM>>>(big, wh + WO_CP, cp_b, nullptr, big2, TT, CC, CC);
    merge_kernel<<<(T * CC + 255) / 256, 256>>>(big2, x);

    // ---- MLP ----
    layernorm_kernel<<<T, 256>>>(x, ln3w, ln3b, h);
    gemm_f16<3><<<dim3(24, T / 128), 256, GEMM_SMEM>>>(h, wh + WO_FC1, fc1_b, nullptr, big, T, HID, CC);
    gemm_f16<2><<<dim3(6, T / 128), 256, GEMM_SMEM>>>(big, wh + WO_FC2, fc2_b, x, out, T, CC, HID);
}

// round 12
// speedup vs baseline: 1.5918x; 1.1010x over previous
#include <cuda_runtime.h>
#include <cuda_fp16.h>
#include <math.h>
#include <stdint.h>

// ---------------------------------------------------------------------------
// MultiviewDecoderBlock (Vx=8, Vy=8, B=4, N=196, C=768, H=12, DH=64, M=4)
// fp16 GEMMs (cp.async 3-stage, m16n8k16, ldmatrix fragments, fp32 accum)
// + fp16 mma attention.
// ---------------------------------------------------------------------------

constexpr int VX = 8, BB = 4, NN = 196, CC = 768, HH = 12, DHH = 64, MV = 4;
constexpr int HID = 4 * CC;            // 3072
constexpr int VB = VX * BB;            // 32
constexpr int T  = VB * NN;            // 6272
constexpr int TT = VX * MV * BB * NN;  // 25088
constexpr int PSELF  = VB * HH;            // 384
constexpr int PCROSS = VX * MV * BB * HH;  // 1536
constexpr float ATTN_SCALE = 0.125f;

// -------------------------- device scratch ---------------------------------
__device__ __align__(256) float  g_x   [T * CC];       // residual stream (fp32)
__device__ __align__(256) float  g_big2[TT * CC];      // cross-proj out (fp32)
__device__ __align__(256) __half g_h   [T * CC];       // LN out
__device__ __align__(256) __half g_yn  [T * CC];
__device__ __align__(256) __half g_qkv [T * 3 * CC];   // self qkv; later cross k|v
__device__ __align__(256) __half g_q   [T * CC];
__device__ __align__(256) __half g_o   [T * CC];
__device__ __align__(256) __half g_big [TT * CC];      // cross attn out; later MLP hidden
__device__ __align__(256) __half g_wh  [9437184];      // fp16 weights

constexpr int WO_QKV = 0;
constexpr int WO_AP  = 3 * CC * CC;
constexpr int WO_Q   = WO_AP  + CC * CC;
constexpr int WO_K   = WO_Q   + CC * CC;   // k|v contiguous -> fused N=1536 GEMM
constexpr int WO_V   = WO_K   + CC * CC;
constexpr int WO_CP  = WO_V   + CC * CC;
constexpr int WO_FC1 = WO_CP  + CC * CC;
constexpr int WO_FC2 = WO_FC1 + HID * CC;

extern __shared__ __align__(16) unsigned char dyn_smem[];

// ----------------------------- helpers -------------------------------------
__device__ __forceinline__ unsigned pkh(float lo, float hi) {
    unsigned r;
    asm("cvt.rn.f16x2.f32 %0, %1, %2;" : "=r"(r) : "f"(hi), "f"(lo));
    return r;
}
__device__ __forceinline__ void mma16h(float* c, const unsigned* a, const unsigned* b) {
    asm volatile(
        "mma.sync.aligned.m16n8k16.row.col.f32.f16.f16.f32 "
        "{%0,%1,%2,%3},{%4,%5,%6,%7},{%8,%9},{%0,%1,%2,%3};\n"
        : "+f"(c[0]), "+f"(c[1]), "+f"(c[2]), "+f"(c[3])
        : "r"(a[0]), "r"(a[1]), "r"(a[2]), "r"(a[3]), "r"(b[0]), "r"(b[1]));
}
__device__ __forceinline__ void ldmx4(unsigned* d, unsigned addr) {
    asm("ldmatrix.sync.aligned.m8n8.x4.shared.b16 {%0,%1,%2,%3}, [%4];"
        : "=r"(d[0]), "=r"(d[1]), "=r"(d[2]), "=r"(d[3]) : "r"(addr));
}
__device__ __forceinline__ void ldmx4t(unsigned* d, unsigned addr) {
    asm volatile("ldmatrix.sync.aligned.m8n8.x4.trans.shared.b16 {%0,%1,%2,%3}, [%4];"
                 : "=r"(d[0]), "=r"(d[1]), "=r"(d[2]), "=r"(d[3]) : "r"(addr));
}
__device__ __forceinline__ void cp16(unsigned d, const void* s) {
    asm volatile("cp.async.cg.shared.global [%0], [%1], 16;" :: "r"(d), "l"(s));
}

// ----------------------------- utility kernels ------------------------------
__global__ void round_all_kernel(
    const float4* s0, const float4* s1, const float4* s2, const float4* s3,
    const float4* s4, const float4* s5, const float4* s6, const float4* s7,
    __half* dst)
{
    const int seg = blockIdx.y;
    const float4* srcs[8] = {s0, s1, s2, s3, s4, s5, s6, s7};
    const int sizes4[8] = {3*CC*CC/4, CC*CC/4, CC*CC/4, CC*CC/4,
                           CC*CC/4, CC*CC/4, HID*CC/4, CC*HID/4};
    const int offs4[8] = {WO_QKV/4, WO_AP/4, WO_Q/4, WO_K/4,
                          WO_V/4, WO_CP/4, WO_FC1/4, WO_FC2/4};
    int i = blockIdx.x * blockDim.x + threadIdx.x;
    if (i < sizes4[seg]) {
        float4 v = srcs[seg][i];
        __half2* d = (__half2*)(dst + (size_t)(offs4[seg] + i) * 4);
        d[0] = __floats2half2_rn(v.x, v.y);
        d[1] = __floats2half2_rn(v.z, v.w);
    }
}

__device__ __forceinline__ void ln_row(const float* xr, const float* w,
                                       const float* b, __half* orow, int tid) {
    float v0 = xr[tid], v1 = xr[tid + 256], v2 = xr[tid + 512];
    float s  = v0 + v1 + v2;
    float sq = v0 * v0 + v1 * v1 + v2 * v2;
    #pragma unroll
    for (int off = 16; off; off >>= 1) {
        s  += __shfl_xor_sync(0xffffffffu, s, off);
        sq += __shfl_xor_sync(0xffffffffu, sq, off);
    }
    __shared__ float red[2][8];
    int warp = tid >> 5, lane = tid & 31;
    if (lane == 0) { red[0][warp] = s; red[1][warp] = sq; }
    __syncthreads();
    float ts = 0.f, tsq = 0.f;
    #pragma unroll
    for (int i = 0; i < 8; i++) { ts += red[0][i]; tsq += red[1][i]; }
    float mu = ts * (1.0f / CC);
    float var = tsq * (1.0f / CC) - mu * mu;
    float rstd = rsqrtf(var + 1e-5f);
    orow[tid]       = __float2half_rn((v0 - mu) * rstd * w[tid]       + b[tid]);
    orow[tid + 256] = __float2half_rn((v1 - mu) * rstd * w[tid + 256] + b[tid + 256]);
    orow[tid + 512] = __float2half_rn((v2 - mu) * rstd * w[tid + 512] + b[tid + 512]);
}

__global__ void layernorm_kernel(const float* __restrict__ in,
                                 const float* __restrict__ w,
                                 const float* __restrict__ b,
                                 __half* __restrict__ out) {
    int row = blockIdx.x;
    ln_row(in + (size_t)row * CC, w, b, out + (size_t)row * CC, threadIdx.x);
}

// two independent LNs in one launch (blockIdx.y selects)
__global__ void layernorm2_kernel(
    const float* __restrict__ in0, const float* __restrict__ w0,
    const float* __restrict__ b0, __half* __restrict__ out0,
    const float* __restrict__ in1, const float* __restrict__ w1,
    const float* __restrict__ b1, __half* __restrict__ out1)
{
    int row = blockIdx.x;
    if (blockIdx.y == 0)
        ln_row(in0 + (size_t)row * CC, w0, b0, out0 + (size_t)row * CC, threadIdx.x);
    else
        ln_row(in1 + (size_t)row * CC, w1, b1, out1 + (size_t)row * CC, threadIdx.x);
}

__global__ void merge_kernel(const float* __restrict__ proj, float* __restrict__ x) {
    int idx = blockIdx.x * blockDim.x + threadIdx.x;
    if (idx >= T * CC) return;
    int c = idx % CC;
    int n = (idx / CC) % NN;
    int b = (idx / (CC * NN)) % BB;
    int v = idx / (CC * NN * BB);
    size_t base = ((((size_t)v * MV) * BB + b) * NN + n) * CC + c;
    size_t ms = (size_t)BB * NN * CC;
    float mx = proj[base];
    #pragma unroll
    for (int m = 1; m < MV; m++) mx = fmaxf(mx, proj[base + (size_t)m * ms]);
    x[idx] += mx;
}

// --------------- fp16 GEMM, cp.async 3 stages, ldmatrix frags ---------------
// C = A @ B^T. A:(M,K) B:(N,K) row-major __half. fp32 accumulate.
// 128x128x32 tile, 256 thr, warp tile 64x32. smem rows padded to 20 words.
// EPI: 0=store half, 1=+bias(f32 out), 2=+bias+residual(f32 out),
//      3=+bias+gelu(exact) half out
constexpr int GSTAGES = 3;
constexpr int WR  = 20;             // words per smem row (16 data + 4 pad)
constexpr int WPS = 128 * WR;       // words per stage
constexpr int ASTG = WPS * 4;       // 10240 bytes
constexpr int GEMM_SMEM = GSTAGES * 2 * ASTG;  // 61440

template<int EPI>
__global__ void __launch_bounds__(256, 2) gemm_f16(
    const __half* __restrict__ A, const __half* __restrict__ Bw,
    const float* __restrict__ bias, const float* __restrict__ res,
    void* __restrict__ Cv, int Mdim, int Ndim, int Kdim)
{
    const unsigned sbase = (unsigned)__cvta_generic_to_shared(dyn_smem);
    const int tid = threadIdx.x;
    const int lane = tid & 31, warp = tid >> 5;
    const int wm = (warp >> 2) * 64;
    const int wn = (warp & 3) * 32;
    const int bm = blockIdx.y * 128, bn = blockIdx.x * 128;

    // cp.async: 2 granules (16B = 8 halves) per matrix per thread per stage
    const int grow = tid >> 2, gg = tid & 3;
    const __half* Ag0 = A  + (size_t)(bm + grow) * Kdim + gg * 8;
    const __half* Ag1 = A  + (size_t)(bm + grow + 64) * Kdim + gg * 8;
    const __half* Bg0 = Bw + (size_t)(bn + grow) * Kdim + gg * 8;
    const __half* Bg1 = Bw + (size_t)(bn + grow + 64) * Kdim + gg * 8;
    const unsigned da0 = sbase + (unsigned)(grow * 80 + gg * 16);
    const unsigned da1 = da0 + 64 * 80;
    const unsigned db0 = da0 + GSTAGES * ASTG;
    const unsigned db1 = da1 + GSTAGES * ASTG;

    float acc[4][4][4];
    #pragma unroll
    for (int i = 0; i < 4; i++)
        #pragma unroll
        for (int j = 0; j < 4; j++)
            #pragma unroll
            for (int t = 0; t < 4; t++) acc[i][j][t] = 0.f;

    const int nk = Kdim >> 5;
    #pragma unroll
    for (int s = 0; s < GSTAGES - 1; s++) {
        unsigned off = (unsigned)s * ASTG;
        int koff = s * 32;
        cp16(da0 + off, Ag0 + koff);
        cp16(da1 + off, Ag1 + koff);
        cp16(db0 + off, Bg0 + koff);
        cp16(db1 + off, Bg1 + koff);
        asm volatile("cp.async.commit_group;");
    }

    // ldmatrix lane addressing (bytes, within stage):
    // A (m16xk16 tile, reg j = tile j):
    //   lanes 0-15  -> rows (wm+mf*16 + lane&15), k-byte +0
    //   lanes 16-31 -> same rows, k-byte +16
    const unsigned aoff = (unsigned)((lane & 15) * 80 + (lane >> 4) * 16);
    // B x4 covers nf pair: r0=nfA k0-7, r1=nfA k8-15, r2=nfB k0-7, r3=nfB k8-15
    //   sel = lane>>3: 0 -> rowsA +0B, 1 -> rowsA +16B, 2 -> rowsB +0B, 3 -> rowsB +16B
    const int bsel = lane >> 3;
    const unsigned boff = (unsigned)((((bsel >> 1) << 3) + (lane & 7)) * 80 +
                                     (bsel & 1) * 16);

    #pragma unroll 1
    for (int kt = 0; kt < nk; kt++) {
        asm volatile("cp.async.wait_group 1;");
        __syncthreads();
        const int buf = kt % GSTAGES;
        const unsigned abase = sbase + (unsigned)buf * ASTG;
        const unsigned bbase = sbase + (unsigned)(GSTAGES + buf) * ASTG;
        #pragma unroll
        for (int c = 0; c < 2; c++) {
            unsigned a[4][4], bb0[4], bb1[4];
            #pragma unroll
            for (int mf = 0; mf < 4; mf++)
                ldmx4(a[mf], abase + (unsigned)((wm + mf * 16) * 80 + c * 32) + aoff);
            ldmx4(bb0, bbase + (unsigned)(wn * 80 + c * 32) + boff);
            ldmx4(bb1, bbase + (unsigned)((wn + 16) * 80 + c * 32) + boff);
            unsigned b0[2] = {bb0[0], bb0[1]};
            unsigned b1[2] = {bb0[2], bb0[3]};
            unsigned b2[2] = {bb1[0], bb1[1]};
            unsigned b3[2] = {bb1[2], bb1[3]};
            #pragma unroll
            for (int mf = 0; mf < 4; mf++) {
                mma16h(acc[mf][0], a[mf], b0);
                mma16h(acc[mf][1], a[mf], b1);
                mma16h(acc[mf][2], a[mf], b2);
                mma16h(acc[mf][3], a[mf], b3);
            }
        }
        if (kt + GSTAGES - 1 < nk) {
            unsigned off = (unsigned)((kt + GSTAGES - 1) % GSTAGES) * ASTG;
            int koff = (kt + GSTAGES - 1) * 32;
            cp16(da0 + off, Ag0 + koff);
            cp16(da1 + off, Ag1 + koff);
            cp16(db0 + off, Bg0 + koff);
            cp16(db1 + off, Bg1 + koff);
        }
        asm volatile("cp.async.commit_group;");
    }

    #pragma unroll
    for (int mf = 0; mf < 4; mf++) {
        #pragma unroll
        for (int nf = 0; nf < 4; nf++) {
            const int col = bn + wn + nf * 8 + (lane & 3) * 2;
            float bb0 = 0.f, bb1 = 0.f;
            if (EPI >= 1) { bb0 = bias[col]; bb1 = bias[col + 1]; }
            #pragma unroll
            for (int hh = 0; hh < 2; hh++) {
                const size_t row = (size_t)(bm + wm + mf * 16 + (lane >> 2) + hh * 8);
                float v0 = acc[mf][nf][hh * 2 + 0] + bb0;
                float v1 = acc[mf][nf][hh * 2 + 1] + bb1;
                if (EPI == 2) {
                    v0 += res[row * Ndim + col];
                    v1 += res[row * Ndim + col + 1];
                }
                if (EPI == 3) {
                    v0 = 0.5f * v0 * (1.0f + erff(v0 * 0.70710678118654752f));
                    v1 = 0.5f * v1 * (1.0f + erff(v1 * 0.70710678118654752f));
                }
                if (EPI == 0 || EPI == 3) {
                    __half* C = (__half*)Cv;
                    *(unsigned*)(C + row * Ndim + col) = pkh(v0, v1);
                } else {
                    float* C = (float*)Cv;
                    *(float2*)(C + row * Ndim + col) = make_float2(v0, v1);
                }
            }
        }
    }
}

// ------------------------- fp16 mma attention -------------------------------
constexpr int QWS = 36;
constexpr int PWS = 108;
constexpr int W_Q = 0;
constexpr int W_K = 2304;
constexpr int W_V = 9792;
constexpr int W_RED = 17280;
constexpr int ATTN_SMEM = (W_RED + 256) * 4;  // 70144 bytes

template<bool CROSS>
__global__ void __launch_bounds__(256) attn_f16(
    const __half* __restrict__ Qsrc, const __half* __restrict__ Ksrc,
    const int* __restrict__ rel, __half* __restrict__ Out)
{
    unsigned* W = (unsigned*)dyn_smem;
    unsigned* Qw = W + W_Q;
    unsigned* Kw = W + W_K;
    unsigned* Vw = W + W_V;
    unsigned* Pw = W;
    float* redmax = (float*)(W + W_RED);
    float* redsum = redmax + 128;
    const unsigned sbase = (unsigned)__cvta_generic_to_shared(dyn_smem);

    const int p = blockIdx.y;
    const int m0 = blockIdx.x * 64;
    const int tid = threadIdx.x;
    const int lane = tid & 31, warp = tid >> 5;
    const int wm = warp & 3, wn = warp >> 2;
    const int r = lane >> 2, q = lane & 3;

    const __half *qp, *kp, *vp;
    __half* op;
    int qrs, kvs;
    if (!CROSS) {
        int vb = p / HH, h2 = p % HH;
        const __half* base = Qsrc + (size_t)vb * NN * 3 * CC;
        qp = base + h2 * DHH;
        kp = base + CC + h2 * DHH;
        vp = base + 2 * CC + h2 * DHH;
        qrs = 3 * CC; kvs = 3 * CC;
        op = Out + (size_t)vb * NN * CC + h2 * DHH;
    } else {
        int h2 = p % HH; int rr = p / HH;
        int b = rr % BB; int r2 = rr / BB;
        int mvi = r2 % MV; int v = r2 / MV;
        int vy = rel[v * MV + mvi];
        qp = Qsrc + ((size_t)(v * BB + b) * NN) * CC + h2 * DHH; qrs = CC;
        kp = Ksrc + ((size_t)(vy * BB + b) * NN) * 1536 + h2 * DHH;
        vp = kp + CC;
        kvs = 1536;
        op = Out + (size_t)rr * NN * CC + h2 * DHH;
    }

    #pragma unroll
    for (int it = 0; it < 4; it++) {
        int idx = tid + 256 * it;
        int row = idx >> 4, w2 = (idx & 15) * 2;
        uint2 qv = make_uint2(0u, 0u);
        if (m0 + row < NN) qv = *(const uint2*)(qp + (size_t)(m0 + row) * qrs + w2 * 2);
        Qw[row * QWS + w2]     = qv.x;
        Qw[row * QWS + w2 + 1] = qv.y;
    }
    #pragma unroll
    for (int it = 0; it < 13; it++) {
        int idx = tid + 256 * it;
        int row = idx >> 4, w2 = (idx & 15) * 2;
        uint2 kv = make_uint2(0u, 0u);
        uint2 vv = make_uint2(0u, 0u);
        if (row < NN) {
            kv = *(const uint2*)(kp + (size_t)row * kvs + w2 * 2);
            vv = *(const uint2*)(vp + (size_t)row * kvs + w2 * 2);
        }
        Kw[row * QWS + w2]     = kv.x;
        Kw[row * QWS + w2 + 1] = kv.y;
        Vw[row * QWS + w2]     = vv.x;
        Vw[row * QWS + w2 + 1] = vv.y;
    }
    __syncthreads();

    const int n0 = wn * 104;
    float sc[13][4];
    #pragma unroll
    for (int j = 0; j < 13; j++)
        #pragma unroll
        for (int t = 0; t < 4; t++) sc[j][t] = 0.f;

    #pragma unroll
    for (int kt = 0; kt < 4; kt++) {
        unsigned a[4];
        const unsigned* ap = Qw + (wm * 16 + r) * QWS + kt * 8 + q;
        a[0] = ap[0];
        a[1] = ap[8 * QWS];
        a[2] = ap[4];
        a[3] = ap[8 * QWS + 4];
        #pragma unroll
        for (int j = 0; j < 13; j++) {
            unsigned b[2];
            const unsigned* bp = Kw + (n0 + j * 8 + r) * QWS + kt * 8 + q;
            b[0] = bp[0];
            b[1] = bp[4];
            mma16h(sc[j], a, b);
        }
    }

    #pragma unroll
    for (int j = 0; j < 13; j++) {
        int cbase = n0 + j * 8 + 2 * q;
        #pragma unroll
        for (int t = 0; t < 4; t++) {
            int col = cbase + (t & 1);
            sc[j][t] = (col < NN) ? sc[j][t] * ATTN_SCALE : -1e30f;
        }
    }

    float mx0 = -1e30f, mx1 = -1e30f;
    #pragma unroll
    for (int j = 0; j < 13; j++) {
        mx0 = fmaxf(mx0, fmaxf(sc[j][0], sc[j][1]));
        mx1 = fmaxf(mx1, fmaxf(sc[j][2], sc[j][3]));
    }
    mx0 = fmaxf(mx0, __shfl_xor_sync(0xffffffffu, mx0, 1));
    mx0 = fmaxf(mx0, __shfl_xor_sync(0xffffffffu, mx0, 2));
    mx1 = fmaxf(mx1, __shfl_xor_sync(0xffffffffu, mx1, 1));
    mx1 = fmaxf(mx1, __shfl_xor_sync(0xffffffffu, mx1, 2));
    int rowl = wm * 16 + r;
    if (q == 0) {
        redmax[wn * 64 + rowl] = mx0;
        redmax[wn * 64 + rowl + 8] = mx1;
    }
    __syncthreads();
    float fm0 = fmaxf(redmax[rowl], redmax[64 + rowl]);
    float fm1 = fmaxf(redmax[rowl + 8], redmax[64 + rowl + 8]);

    float s0 = 0.f, s1 = 0.f;
    #pragma unroll
    for (int j = 0; j < 13; j++) {
        sc[j][0] = __expf(sc[j][0] - fm0);
        sc[j][1] = __expf(sc[j][1] - fm0);
        sc[j][2] = __expf(sc[j][2] - fm1);
        sc[j][3] = __expf(sc[j][3] - fm1);
        s0 += sc[j][0] + sc[j][1];
        s1 += sc[j][2] + sc[j][3];
    }
    s0 += __shfl_xor_sync(0xffffffffu, s0, 1);
    s0 += __shfl_xor_sync(0xffffffffu, s0, 2);
    s1 += __shfl_xor_sync(0xffffffffu, s1, 1);
    s1 += __shfl_xor_sync(0xffffffffu, s1, 2);
    if (q == 0) {
        redsum[wn * 64 + rowl] = s0;
        redsum[wn * 64 + rowl + 8] = s1;
    }
    #pragma unroll
    for (int j = 0; j < 13; j++) {
        int wbase = (n0 >> 1) + j * 4 + q;
        Pw[rowl * PWS + wbase]       = pkh(sc[j][0], sc[j][1]);
        Pw[(rowl + 8) * PWS + wbase] = pkh(sc[j][2], sc[j][3]);
    }
    __syncthreads();

    const int oc0 = wn * 32;
    float oacc[4][4];
    #pragma unroll
    for (int j = 0; j < 4; j++)
        #pragma unroll
        for (int t = 0; t < 4; t++) oacc[j][t] = 0.f;

    const int lrow = lane & 15;
    const int lcol = (lane >> 4) * 8;
    #pragma unroll
    for (int kt = 0; kt < 13; kt++) {
        unsigned a[4];
        const unsigned* ap2 = Pw + rowl * PWS + kt * 8 + q;
        a[0] = ap2[0];
        a[1] = ap2[8 * PWS];
        a[2] = ap2[4];
        a[3] = ap2[8 * PWS + 4];
        #pragma unroll
        for (int jp = 0; jp < 2; jp++) {
            unsigned b4[4];
            unsigned addr = sbase + (unsigned)(W_V * 4) +
                (unsigned)((kt * 16 + lrow) * 72 + oc0 + jp * 16 + lcol) * 2u;
            ldmx4t(b4, addr);
            mma16h(oacc[jp * 2 + 0], a, b4 + 0);
            mma16h(oacc[jp * 2 + 1], a, b4 + 2);
        }
    }

    float inv0 = 1.0f / (redsum[rowl] + redsum[64 + rowl]);
    float inv1 = 1.0f / (redsum[rowl + 8] + redsum[64 + rowl + 8]);
    int mg0 = m0 + rowl, mg1 = m0 + rowl + 8;
    #pragma unroll
    for (int j = 0; j < 4; j++) {
        int col = oc0 + j * 8 + 2 * q;
        if (mg0 < NN)
            *(unsigned*)(op + (size_t)mg0 * CC + col) =
                pkh(oacc[j][0] * inv0, oacc[j][1] * inv0);
        if (mg1 < NN)
            *(unsigned*)(op + (size_t)mg1 * CC + col) =
                pkh(oacc[j][2] * inv1, oacc[j][3] * inv1);
    }
}

// ------------------------------- launch -------------------------------------
extern "C" void kernel_launch(void* const* d_in, const int* in_sizes, int n_in,
                              void* d_out, int out_size) {
    int sh = (in_sizes[5] == 1) ? 0 : -1;

    const float* xs  = (const float*)d_in[0];
    const float* ys  = (const float*)d_in[1];
    const int* rel   = (const int*)d_in[4];
    const float* qkv_w = (const float*)d_in[6 + sh];
    const float* ap_w  = (const float*)d_in[7 + sh];
    const float* ap_b  = (const float*)d_in[8 + sh];
    const float* q_w   = (const float*)d_in[9 + sh];
    const float* k_w   = (const float*)d_in[10 + sh];
    const float* v_w   = (const float*)d_in[11 + sh];
    const float* cp_w  = (const float*)d_in[12 + sh];
    const float* cp_b  = (const float*)d_in[13 + sh];
    const float* fc1_w = (const float*)d_in[14 + sh];
    const float* fc1_b = (const float*)d_in[15 + sh];
    const float* fc2_w = (const float*)d_in[16 + sh];
    const float* fc2_b = (const float*)d_in[17 + sh];
    const float* ln1w = (const float*)d_in[18 + sh];
    const float* ln1b = (const float*)d_in[19 + sh];
    const float* ln2w = (const float*)d_in[20 + sh];
    const float* ln2b = (const float*)d_in[21 + sh];
    const float* ln3w = (const float*)d_in[22 + sh];
    const float* ln3b = (const float*)d_in[23 + sh];
    const float* lnyw = (const float*)d_in[24 + sh];
    const float* lnyb = (const float*)d_in[25 + sh];
    float* out = (float*)d_out;

    float *x, *big2;
    __half *h, *yn, *qkv, *q, *o, *big, *wh;
    cudaGetSymbolAddress((void**)&x, g_x);
    cudaGetSymbolAddress((void**)&big2, g_big2);
    cudaGetSymbolAddress((void**)&h, g_h);
    cudaGetSymbolAddress((void**)&yn, g_yn);
    cudaGetSymbolAddress((void**)&qkv, g_qkv);
    cudaGetSymbolAddress((void**)&q, g_q);
    cudaGetSymbolAddress((void**)&o, g_o);
    cudaGetSymbolAddress((void**)&big, g_big);
    cudaGetSymbolAddress((void**)&wh, g_wh);

    cudaFuncSetAttribute(gemm_f16<0>, cudaFuncAttributeMaxDynamicSharedMemorySize, GEMM_SMEM);
    cudaFuncSetAttribute(gemm_f16<1>, cudaFuncAttributeMaxDynamicSharedMemorySize, GEMM_SMEM);
    cudaFuncSetAttribute(gemm_f16<2>, cudaFuncAttributeMaxDynamicSharedMemorySize, GEMM_SMEM);
    cudaFuncSetAttribute(gemm_f16<3>, cudaFuncAttributeMaxDynamicSharedMemorySize, GEMM_SMEM);
    cudaFuncSetAttribute(attn_f16<false>, cudaFuncAttributeMaxDynamicSharedMemorySize, ATTN_SMEM);
    cudaFuncSetAttribute(attn_f16<true>,  cudaFuncAttributeMaxDynamicSharedMemorySize, ATTN_SMEM);

    round_all_kernel<<<dim3(HID * CC / 4 / 256, 8), 256>>>(
        (const float4*)qkv_w, (const float4*)ap_w, (const float4*)q_w,
        (const float4*)k_w, (const float4*)v_w, (const float4*)cp_w,
        (const float4*)fc1_w, (const float4*)fc2_w, wh);

    // ---- self attention ----
    layernorm_kernel<<<T, 256>>>(xs, ln1w, ln1b, h);
    gemm_f16<0><<<dim3(18, T / 128), 256, GEMM_SMEM>>>(h, wh + WO_QKV, nullptr, nullptr, qkv, T, 3 * CC, CC);
    attn_f16<false><<<dim3(4, PSELF), 256, ATTN_SMEM>>>(qkv, qkv, nullptr, o);
    gemm_f16<2><<<dim3(6, T / 128), 256, GEMM_SMEM>>>(o, wh + WO_AP, ap_b, xs, x, T, CC, CC);

    // ---- cross attention ----
    layernorm2_kernel<<<dim3(T, 2), 256>>>(x, ln2w, ln2b, h, ys, lnyw, lnyb, yn);
    gemm_f16<0><<<dim3(6, T / 128), 256, GEMM_SMEM>>>(h, wh + WO_Q, nullptr, nullptr, q, T, CC, CC);
    gemm_f16<0><<<dim3(12, T / 128), 256, GEMM_SMEM>>>(yn, wh + WO_K, nullptr, nullptr, qkv, T, 2 * CC, CC);
    attn_f16<true><<<dim3(4, PCROSS), 256, ATTN_SMEM>>>(q, qkv, rel, big);
    gemm_f16<1><<<dim3(6, TT / 128), 256, GEMM_SMEM>>>(big, wh + WO_CP, cp_b, nullptr, big2, TT, CC, CC);
    merge_kernel<<<(T * CC + 255) / 256, 256>>>(big2, x);

    // ---- MLP ----
    layernorm_kernel<<<T, 256>>>(x, ln3w, ln3b, h);
    gemm_f16<3><<<dim3(24, T / 128), 256, GEMM_SMEM>>>(h, wh + WO_FC1, fc1_b, nullptr, big, T, HID, CC);
    gemm_f16<2><<<dim3(6, T / 128), 256, GEMM_SMEM>>>(big, wh + WO_FC2, fc2_b, x, out, T, CC, HID);
}

// round 13
// speedup vs baseline: 1.5976x; 1.0036x over previous
#include <cuda_runtime.h>
#include <cuda_fp16.h>
#include <math.h>
#include <stdint.h>

// ---------------------------------------------------------------------------
// MultiviewDecoderBlock (Vx=8, Vy=8, B=4, N=196, C=768, H=12, DH=64, M=4)
// fp16 GEMMs (cp.async 3-stage, K64 tiles, m16n8k16, ldmatrix, fp32 accum)
// + fp16 mma attention.
// ---------------------------------------------------------------------------

constexpr int VX = 8, BB = 4, NN = 196, CC = 768, HH = 12, DHH = 64, MV = 4;
constexpr int HID = 4 * CC;            // 3072
constexpr int VB = VX * BB;            // 32
constexpr int T  = VB * NN;            // 6272
constexpr int TT = VX * MV * BB * NN;  // 25088
constexpr int PSELF  = VB * HH;            // 384
constexpr int PCROSS = VX * MV * BB * HH;  // 1536
constexpr float ATTN_SCALE = 0.125f;

// -------------------------- device scratch ---------------------------------
__device__ __align__(256) float  g_x   [T * CC];       // residual stream (fp32)
__device__ __align__(256) float  g_big2[TT * CC];      // cross-proj out (fp32)
__device__ __align__(256) __half g_h   [T * CC];       // LN out
__device__ __align__(256) __half g_yn  [T * CC];
__device__ __align__(256) __half g_qkv [T * 3 * CC];   // self qkv; later cross k|v
__device__ __align__(256) __half g_q   [T * CC];
__device__ __align__(256) __half g_o   [T * CC];
__device__ __align__(256) __half g_big [TT * CC];      // cross attn out; later MLP hidden
__device__ __align__(256) __half g_wh  [9437184];      // fp16 weights

constexpr int WO_QKV = 0;
constexpr int WO_AP  = 3 * CC * CC;
constexpr int WO_Q   = WO_AP  + CC * CC;
constexpr int WO_K   = WO_Q   + CC * CC;   // k|v contiguous -> fused N=1536 GEMM
constexpr int WO_V   = WO_K   + CC * CC;
constexpr int WO_CP  = WO_V   + CC * CC;
constexpr int WO_FC1 = WO_CP  + CC * CC;
constexpr int WO_FC2 = WO_FC1 + HID * CC;

extern __shared__ __align__(16) unsigned char dyn_smem[];

// ----------------------------- helpers -------------------------------------
__device__ __forceinline__ unsigned pkh(float lo, float hi) {
    unsigned r;
    asm("cvt.rn.f16x2.f32 %0, %1, %2;" : "=r"(r) : "f"(hi), "f"(lo));
    return r;
}
__device__ __forceinline__ void mma16h(float* c, const unsigned* a, const unsigned* b) {
    asm volatile(
        "mma.sync.aligned.m16n8k16.row.col.f32.f16.f16.f32 "
        "{%0,%1,%2,%3},{%4,%5,%6,%7},{%8,%9},{%0,%1,%2,%3};\n"
        : "+f"(c[0]), "+f"(c[1]), "+f"(c[2]), "+f"(c[3])
        : "r"(a[0]), "r"(a[1]), "r"(a[2]), "r"(a[3]), "r"(b[0]), "r"(b[1]));
}
__device__ __forceinline__ void ldmx4(unsigned* d, unsigned addr) {
    asm("ldmatrix.sync.aligned.m8n8.x4.shared.b16 {%0,%1,%2,%3}, [%4];"
        : "=r"(d[0]), "=r"(d[1]), "=r"(d[2]), "=r"(d[3]) : "r"(addr));
}
__device__ __forceinline__ void ldmx4t(unsigned* d, unsigned addr) {
    asm volatile("ldmatrix.sync.aligned.m8n8.x4.trans.shared.b16 {%0,%1,%2,%3}, [%4];"
                 : "=r"(d[0]), "=r"(d[1]), "=r"(d[2]), "=r"(d[3]) : "r"(addr));
}
__device__ __forceinline__ void cp16(unsigned d, const void* s) {
    asm volatile("cp.async.cg.shared.global [%0], [%1], 16;" :: "r"(d), "l"(s));
}

// ----------------------------- utility kernels ------------------------------
__global__ void round_all_kernel(
    const float4* s0, const float4* s1, const float4* s2, const float4* s3,
    const float4* s4, const float4* s5, const float4* s6, const float4* s7,
    __half* dst)
{
    const int seg = blockIdx.y;
    const float4* srcs[8] = {s0, s1, s2, s3, s4, s5, s6, s7};
    const int sizes4[8] = {3*CC*CC/4, CC*CC/4, CC*CC/4, CC*CC/4,
                           CC*CC/4, CC*CC/4, HID*CC/4, CC*HID/4};
    const int offs4[8] = {WO_QKV/4, WO_AP/4, WO_Q/4, WO_K/4,
                          WO_V/4, WO_CP/4, WO_FC1/4, WO_FC2/4};
    int i = blockIdx.x * blockDim.x + threadIdx.x;
    if (i < sizes4[seg]) {
        float4 v = srcs[seg][i];
        __half2* d = (__half2*)(dst + (size_t)(offs4[seg] + i) * 4);
        d[0] = __floats2half2_rn(v.x, v.y);
        d[1] = __floats2half2_rn(v.z, v.w);
    }
}

__device__ __forceinline__ void ln_row(const float* xr, const float* w,
                                       const float* b, __half* orow, int tid) {
    float v0 = xr[tid], v1 = xr[tid + 256], v2 = xr[tid + 512];
    float s  = v0 + v1 + v2;
    float sq = v0 * v0 + v1 * v1 + v2 * v2;
    #pragma unroll
    for (int off = 16; off; off >>= 1) {
        s  += __shfl_xor_sync(0xffffffffu, s, off);
        sq += __shfl_xor_sync(0xffffffffu, sq, off);
    }
    __shared__ float red[2][8];
    int warp = tid >> 5, lane = tid & 31;
    if (lane == 0) { red[0][warp] = s; red[1][warp] = sq; }
    __syncthreads();
    float ts = 0.f, tsq = 0.f;
    #pragma unroll
    for (int i = 0; i < 8; i++) { ts += red[0][i]; tsq += red[1][i]; }
    float mu = ts * (1.0f / CC);
    float var = tsq * (1.0f / CC) - mu * mu;
    float rstd = rsqrtf(var + 1e-5f);
    orow[tid]       = __float2half_rn((v0 - mu) * rstd * w[tid]       + b[tid]);
    orow[tid + 256] = __float2half_rn((v1 - mu) * rstd * w[tid + 256] + b[tid + 256]);
    orow[tid + 512] = __float2half_rn((v2 - mu) * rstd * w[tid + 512] + b[tid + 512]);
}

__global__ void layernorm_kernel(const float* __restrict__ in,
                                 const float* __restrict__ w,
                                 const float* __restrict__ b,
                                 __half* __restrict__ out) {
    int row = blockIdx.x;
    ln_row(in + (size_t)row * CC, w, b, out + (size_t)row * CC, threadIdx.x);
}

__global__ void layernorm2_kernel(
    const float* __restrict__ in0, const float* __restrict__ w0,
    const float* __restrict__ b0, __half* __restrict__ out0,
    const float* __restrict__ in1, const float* __restrict__ w1,
    const float* __restrict__ b1, __half* __restrict__ out1)
{
    int row = blockIdx.x;
    if (blockIdx.y == 0)
        ln_row(in0 + (size_t)row * CC, w0, b0, out0 + (size_t)row * CC, threadIdx.x);
    else
        ln_row(in1 + (size_t)row * CC, w1, b1, out1 + (size_t)row * CC, threadIdx.x);
}

// float4 merge: max over M views + residual add
__global__ void merge_kernel(const float4* __restrict__ proj, float4* __restrict__ x) {
    int idx = blockIdx.x * blockDim.x + threadIdx.x;
    if (idx >= T * CC / 4) return;
    int e = idx * 4;
    int c = e % CC;
    int n = (e / CC) % NN;
    int b = (e / (CC * NN)) % BB;
    int v = e / (CC * NN * BB);
    size_t base4 = (((((size_t)v * MV) * BB + b) * NN + n) * CC + c) >> 2;
    size_t ms4 = ((size_t)BB * NN * CC) >> 2;
    float4 mx = proj[base4];
    #pragma unroll
    for (int m = 1; m < MV; m++) {
        float4 p = proj[base4 + (size_t)m * ms4];
        mx.x = fmaxf(mx.x, p.x); mx.y = fmaxf(mx.y, p.y);
        mx.z = fmaxf(mx.z, p.z); mx.w = fmaxf(mx.w, p.w);
    }
    float4 xv = x[idx];
    xv.x += mx.x; xv.y += mx.y; xv.z += mx.z; xv.w += mx.w;
    x[idx] = xv;
}

// --------------- fp16 GEMM, cp.async 3 stages, K64 tiles --------------------
// C = A @ B^T. A:(M,K) B:(N,K) row-major __half. fp32 accumulate.
// 128x128x64 stage tile, 256 thr, warp tile 64x32.
// smem rows: 64 halves + 12B pad = 144 B (9x16B units -> conflict-free
// ldmatrix 8-row phases and acceptable cp.async store pattern).
// EPI: 0=store half, 1=+bias(f32 out), 2=+bias+residual(f32 out),
//      3=+bias+gelu(exact) half out
constexpr int GSTAGES = 3;
constexpr int RB   = 144;               // bytes per smem row
constexpr int ASTG = 128 * RB;          // 18432 bytes per matrix per stage
constexpr int GEMM_SMEM = GSTAGES * 2 * ASTG;  // 110592

template<int EPI>
__global__ void __launch_bounds__(256, 2) gemm_f16(
    const __half* __restrict__ A, const __half* __restrict__ Bw,
    const float* __restrict__ bias, const float* __restrict__ res,
    void* __restrict__ Cv, int Mdim, int Ndim, int Kdim)
{
    const unsigned sbase = (unsigned)__cvta_generic_to_shared(dyn_smem);
    const int tid = threadIdx.x;
    const int lane = tid & 31, warp = tid >> 5;
    const int wm = (warp >> 2) * 64;
    const int wn = (warp & 3) * 32;
    const int bm = blockIdx.y * 128, bn = blockIdx.x * 128;

    // cp.async: 4 granules per matrix per thread per stage (128 rows x 8 granules)
    const int r0 = tid >> 3;            // 0..31, +32*i
    const int gg = tid & 7;             // granule within row
    const __half* Agp = A  + (size_t)(bm + r0) * Kdim + gg * 8;
    const __half* Bgp = Bw + (size_t)(bn + r0) * Kdim + gg * 8;
    const unsigned dA = sbase + (unsigned)(r0 * RB + gg * 16);
    const unsigned dB = dA + GSTAGES * ASTG;

    float acc[4][4][4];
    #pragma unroll
    for (int i = 0; i < 4; i++)
        #pragma unroll
        for (int j = 0; j < 4; j++)
            #pragma unroll
            for (int t = 0; t < 4; t++) acc[i][j][t] = 0.f;

    const int nst = Kdim >> 6;
    #pragma unroll
    for (int s = 0; s < GSTAGES - 1; s++) {
        unsigned off = (unsigned)s * ASTG;
        int koff = s * 64;
        #pragma unroll
        for (int i = 0; i < 4; i++) {
            cp16(dA + off + (unsigned)(32 * i * RB), Agp + (size_t)(32 * i) * Kdim + koff);
            cp16(dB + off + (unsigned)(32 * i * RB), Bgp + (size_t)(32 * i) * Kdim + koff);
        }
        asm volatile("cp.async.commit_group;");
    }

    // ldmatrix lane addressing (bytes within stage)
    const unsigned aoff = (unsigned)((lane & 15) * RB + (lane >> 4) * 16);
    const int bsel = lane >> 3;
    const unsigned boff = (unsigned)((((bsel >> 1) << 3) + (lane & 7)) * RB +
                                     (bsel & 1) * 16);

    #pragma unroll 1
    for (int kt = 0; kt < nst; kt++) {
        asm volatile("cp.async.wait_group 1;");
        __syncthreads();
        const int buf = kt % GSTAGES;
        const unsigned abase = sbase + (unsigned)buf * ASTG;
        const unsigned bbase = sbase + (unsigned)(GSTAGES + buf) * ASTG;
        #pragma unroll
        for (int c = 0; c < 4; c++) {
            unsigned a[4][4], bb0[4], bb1[4];
            #pragma unroll
            for (int mf = 0; mf < 4; mf++)
                ldmx4(a[mf], abase + (unsigned)((wm + mf * 16) * RB + c * 32) + aoff);
            ldmx4(bb0, bbase + (unsigned)(wn * RB + c * 32) + boff);
            ldmx4(bb1, bbase + (unsigned)((wn + 16) * RB + c * 32) + boff);
            unsigned b0[2] = {bb0[0], bb0[1]};
            unsigned b1[2] = {bb0[2], bb0[3]};
            unsigned b2[2] = {bb1[0], bb1[1]};
            unsigned b3[2] = {bb1[2], bb1[3]};
            #pragma unroll
            for (int mf = 0; mf < 4; mf++) {
                mma16h(acc[mf][0], a[mf], b0);
                mma16h(acc[mf][1], a[mf], b1);
                mma16h(acc[mf][2], a[mf], b2);
                mma16h(acc[mf][3], a[mf], b3);
            }
        }
        if (kt + GSTAGES - 1 < nst) {
            unsigned off = (unsigned)((kt + GSTAGES - 1) % GSTAGES) * ASTG;
            int koff = (kt + GSTAGES - 1) * 64;
            #pragma unroll
            for (int i = 0; i < 4; i++) {
                cp16(dA + off + (unsigned)(32 * i * RB), Agp + (size_t)(32 * i) * Kdim + koff);
                cp16(dB + off + (unsigned)(32 * i * RB), Bgp + (size_t)(32 * i) * Kdim + koff);
            }
        }
        asm volatile("cp.async.commit_group;");
    }

    #pragma unroll
    for (int mf = 0; mf < 4; mf++) {
        #pragma unroll
        for (int nf = 0; nf < 4; nf++) {
            const int col = bn + wn + nf * 8 + (lane & 3) * 2;
            float bb0 = 0.f, bb1 = 0.f;
            if (EPI >= 1) { bb0 = bias[col]; bb1 = bias[col + 1]; }
            #pragma unroll
            for (int hh = 0; hh < 2; hh++) {
                const size_t row = (size_t)(bm + wm + mf * 16 + (lane >> 2) + hh * 8);
                float v0 = acc[mf][nf][hh * 2 + 0] + bb0;
                float v1 = acc[mf][nf][hh * 2 + 1] + bb1;
                if (EPI == 2) {
                    v0 += res[row * Ndim + col];
                    v1 += res[row * Ndim + col + 1];
                }
                if (EPI == 3) {
                    v0 = 0.5f * v0 * (1.0f + erff(v0 * 0.70710678118654752f));
                    v1 = 0.5f * v1 * (1.0f + erff(v1 * 0.70710678118654752f));
                }
                if (EPI == 0 || EPI == 3) {
                    __half* C = (__half*)Cv;
                    *(unsigned*)(C + row * Ndim + col) = pkh(v0, v1);
                } else {
                    float* C = (float*)Cv;
                    *(float2*)(C + row * Ndim + col) = make_float2(v0, v1);
                }
            }
        }
    }
}

// ------------------------- fp16 mma attention -------------------------------
constexpr int QWS = 36;
constexpr int PWS = 108;
constexpr int W_Q = 0;
constexpr int W_K = 2304;
constexpr int W_V = 9792;
constexpr int W_RED = 17280;
constexpr int ATTN_SMEM = (W_RED + 256) * 4;  // 70144 bytes

template<bool CROSS>
__global__ void __launch_bounds__(256) attn_f16(
    const __half* __restrict__ Qsrc, const __half* __restrict__ Ksrc,
    const int* __restrict__ rel, __half* __restrict__ Out)
{
    unsigned* W = (unsigned*)dyn_smem;
    unsigned* Qw = W + W_Q;
    unsigned* Kw = W + W_K;
    unsigned* Vw = W + W_V;
    unsigned* Pw = W;
    float* redmax = (float*)(W + W_RED);
    float* redsum = redmax + 128;
    const unsigned sbase = (unsigned)__cvta_generic_to_shared(dyn_smem);

    const int p = blockIdx.y;
    const int m0 = blockIdx.x * 64;
    const int tid = threadIdx.x;
    const int lane = tid & 31, warp = tid >> 5;
    const int wm = warp & 3, wn = warp >> 2;
    const int r = lane >> 2, q = lane & 3;

    const __half *qp, *kp, *vp;
    __half* op;
    int qrs, kvs;
    if (!CROSS) {
        int vb = p / HH, h2 = p % HH;
        const __half* base = Qsrc + (size_t)vb * NN * 3 * CC;
        qp = base + h2 * DHH;
        kp = base + CC + h2 * DHH;
        vp = base + 2 * CC + h2 * DHH;
        qrs = 3 * CC; kvs = 3 * CC;
        op = Out + (size_t)vb * NN * CC + h2 * DHH;
    } else {
        int h2 = p % HH; int rr = p / HH;
        int b = rr % BB; int r2 = rr / BB;
        int mvi = r2 % MV; int v = r2 / MV;
        int vy = rel[v * MV + mvi];
        qp = Qsrc + ((size_t)(v * BB + b) * NN) * CC + h2 * DHH; qrs = CC;
        kp = Ksrc + ((size_t)(vy * BB + b) * NN) * 1536 + h2 * DHH;
        vp = kp + CC;
        kvs = 1536;
        op = Out + (size_t)rr * NN * CC + h2 * DHH;
    }

    #pragma unroll
    for (int it = 0; it < 4; it++) {
        int idx = tid + 256 * it;
        int row = idx >> 4, w2 = (idx & 15) * 2;
        uint2 qv = make_uint2(0u, 0u);
        if (m0 + row < NN) qv = *(const uint2*)(qp + (size_t)(m0 + row) * qrs + w2 * 2);
        Qw[row * QWS + w2]     = qv.x;
        Qw[row * QWS + w2 + 1] = qv.y;
    }
    #pragma unroll
    for (int it = 0; it < 13; it++) {
        int idx = tid + 256 * it;
        int row = idx >> 4, w2 = (idx & 15) * 2;
        uint2 kv = make_uint2(0u, 0u);
        uint2 vv = make_uint2(0u, 0u);
        if (row < NN) {
            kv = *(const uint2*)(kp + (size_t)row * kvs + w2 * 2);
            vv = *(const uint2*)(vp + (size_t)row * kvs + w2 * 2);
        }
        Kw[row * QWS + w2]     = kv.x;
        Kw[row * QWS + w2 + 1] = kv.y;
        Vw[row * QWS + w2]     = vv.x;
        Vw[row * QWS + w2 + 1] = vv.y;
    }
    __syncthreads();

    const int n0 = wn * 104;
    float sc[13][4];
    #pragma unroll
    for (int j = 0; j < 13; j++)
        #pragma unroll
        for (int t = 0; t < 4; t++) sc[j][t] = 0.f;

    #pragma unroll
    for (int kt = 0; kt < 4; kt++) {
        unsigned a[4];
        const unsigned* ap = Qw + (wm * 16 + r) * QWS + kt * 8 + q;
        a[0] = ap[0];
        a[1] = ap[8 * QWS];
        a[2] = ap[4];
        a[3] = ap[8 * QWS + 4];
        #pragma unroll
        for (int j = 0; j < 13; j++) {
            unsigned b[2];
            const unsigned* bp = Kw + (n0 + j * 8 + r) * QWS + kt * 8 + q;
            b[0] = bp[0];
            b[1] = bp[4];
            mma16h(sc[j], a, b);
        }
    }

    #pragma unroll
    for (int j = 0; j < 13; j++) {
        int cbase = n0 + j * 8 + 2 * q;
        #pragma unroll
        for (int t = 0; t < 4; t++) {
            int col = cbase + (t & 1);
            sc[j][t] = (col < NN) ? sc[j][t] * ATTN_SCALE : -1e30f;
        }
    }

    float mx0 = -1e30f, mx1 = -1e30f;
    #pragma unroll
    for (int j = 0; j < 13; j++) {
        mx0 = fmaxf(mx0, fmaxf(sc[j][0], sc[j][1]));
        mx1 = fmaxf(mx1, fmaxf(sc[j][2], sc[j][3]));
    }
    mx0 = fmaxf(mx0, __shfl_xor_sync(0xffffffffu, mx0, 1));
    mx0 = fmaxf(mx0, __shfl_xor_sync(0xffffffffu, mx0, 2));
    mx1 = fmaxf(mx1, __shfl_xor_sync(0xffffffffu, mx1, 1));
    mx1 = fmaxf(mx1, __shfl_xor_sync(0xffffffffu, mx1, 2));
    int rowl = wm * 16 + r;
    if (q == 0) {
        redmax[wn * 64 + rowl] = mx0;
        redmax[wn * 64 + rowl + 8] = mx1;
    }
    __syncthreads();
    float fm0 = fmaxf(redmax[rowl], redmax[64 + rowl]);
    float fm1 = fmaxf(redmax[rowl + 8], redmax[64 + rowl + 8]);

    float s0 = 0.f, s1 = 0.f;
    #pragma unroll
    for (int j = 0; j < 13; j++) {
        sc[j][0] = __expf(sc[j][0] - fm0);
        sc[j][1] = __expf(sc[j][1] - fm0);
        sc[j][2] = __expf(sc[j][2] - fm1);
        sc[j][3] = __expf(sc[j][3] - fm1);
        s0 += sc[j][0] + sc[j][1];
        s1 += sc[j][2] + sc[j][3];
    }
    s0 += __shfl_xor_sync(0xffffffffu, s0, 1);
    s0 += __shfl_xor_sync(0xffffffffu, s0, 2);
    s1 += __shfl_xor_sync(0xffffffffu, s1, 1);
    s1 += __shfl_xor_sync(0xffffffffu, s1, 2);
    if (q == 0) {
        redsum[wn * 64 + rowl] = s0;
        redsum[wn * 64 + rowl + 8] = s1;
    }
    #pragma unroll
    for (int j = 0; j < 13; j++) {
        int wbase = (n0 >> 1) + j * 4 + q;
        Pw[rowl * PWS + wbase]       = pkh(sc[j][0], sc[j][1]);
        Pw[(rowl + 8) * PWS + wbase] = pkh(sc[j][2], sc[j][3]);
    }
    __syncthreads();

    const int oc0 = wn * 32;
    float oacc[4][4];
    #pragma unroll
    for (int j = 0; j < 4; j++)
        #pragma unroll
        for (int t = 0; t < 4; t++) oacc[j][t] = 0.f;

    const int lrow = lane & 15;
    const int lcol = (lane >> 4) * 8;
    #pragma unroll
    for (int kt = 0; kt < 13; kt++) {
        unsigned a[4];
        const unsigned* ap2 = Pw + rowl * PWS + kt * 8 + q;
        a[0] = ap2[0];
        a[1] = ap2[8 * PWS];
        a[2] = ap2[4];
        a[3] = ap2[8 * PWS + 4];
        #pragma unroll
        for (int jp = 0; jp < 2; jp++) {
            unsigned b4[4];
            unsigned addr = sbase + (unsigned)(W_V * 4) +
                (unsigned)((kt * 16 + lrow) * 72 + oc0 + jp * 16 + lcol) * 2u;
            ldmx4t(b4, addr);
            mma16h(oacc[jp * 2 + 0], a, b4 + 0);
            mma16h(oacc[jp * 2 + 1], a, b4 + 2);
        }
    }

    float inv0 = 1.0f / (redsum[rowl] + redsum[64 + rowl]);
    float inv1 = 1.0f / (redsum[rowl + 8] + redsum[64 + rowl + 8]);
    int mg0 = m0 + rowl, mg1 = m0 + rowl + 8;
    #pragma unroll
    for (int j = 0; j < 4; j++) {
        int col = oc0 + j * 8 + 2 * q;
        if (mg0 < NN)
            *(unsigned*)(op + (size_t)mg0 * CC + col) =
                pkh(oacc[j][0] * inv0, oacc[j][1] * inv0);
        if (mg1 < NN)
            *(unsigned*)(op + (size_t)mg1 * CC + col) =
                pkh(oacc[j][2] * inv1, oacc[j][3] * inv1);
    }
}

// ------------------------------- launch -------------------------------------
extern "C" void kernel_launch(void* const* d_in, const int* in_sizes, int n_in,
                              void* d_out, int out_size) {
    int sh = (in_sizes[5] == 1) ? 0 : -1;

    const float* xs  = (const float*)d_in[0];
    const float* ys  = (const float*)d_in[1];
    const int* rel   = (const int*)d_in[4];
    const float* qkv_w = (const float*)d_in[6 + sh];
    const float* ap_w  = (const float*)d_in[7 + sh];
    const float* ap_b  = (const float*)d_in[8 + sh];
    const float* q_w   = (const float*)d_in[9 + sh];
    const float* k_w   = (const float*)d_in[10 + sh];
    const float* v_w   = (const float*)d_in[11 + sh];
    const float* cp_w  = (const float*)d_in[12 + sh];
    const float* cp_b  = (const float*)d_in[13 + sh];
    const float* fc1_w = (const float*)d_in[14 + sh];
    const float* fc1_b = (const float*)d_in[15 + sh];
    const float* fc2_w = (const float*)d_in[16 + sh];
    const float* fc2_b = (const float*)d_in[17 + sh];
    const float* ln1w = (const float*)d_in[18 + sh];
    const float* ln1b = (const float*)d_in[19 + sh];
    const float* ln2w = (const float*)d_in[20 + sh];
    const float* ln2b = (const float*)d_in[21 + sh];
    const float* ln3w = (const float*)d_in[22 + sh];
    const float* ln3b = (const float*)d_in[23 + sh];
    const float* lnyw = (const float*)d_in[24 + sh];
    const float* lnyb = (const float*)d_in[25 + sh];
    float* out = (float*)d_out;

    float *x, *big2;
    __half *h, *yn, *qkv, *q, *o, *big, *wh;
    cudaGetSymbolAddress((void**)&x, g_x);
    cudaGetSymbolAddress((void**)&big2, g_big2);
    cudaGetSymbolAddress((void**)&h, g_h);
    cudaGetSymbolAddress((void**)&yn, g_yn);
    cudaGetSymbolAddress((void**)&qkv, g_qkv);
    cudaGetSymbolAddress((void**)&q, g_q);
    cudaGetSymbolAddress((void**)&o, g_o);
    cudaGetSymbolAddress((void**)&big, g_big);
    cudaGetSymbolAddress((void**)&wh, g_wh);

    cudaFuncSetAttribute(gemm_f16<0>, cudaFuncAttributeMaxDynamicSharedMemorySize, GEMM_SMEM);
    cudaFuncSetAttribute(gemm_f16<1>, cudaFuncAttributeMaxDynamicSharedMemorySize, GEMM_SMEM);
    cudaFuncSetAttribute(gemm_f16<2>, cudaFuncAttributeMaxDynamicSharedMemorySize, GEMM_SMEM);
    cudaFuncSetAttribute(gemm_f16<3>, cudaFuncAttributeMaxDynamicSharedMemorySize, GEMM_SMEM);
    cudaFuncSetAttribute(attn_f16<false>, cudaFuncAttributeMaxDynamicSharedMemorySize, ATTN_SMEM);
    cudaFuncSetAttribute(attn_f16<true>,  cudaFuncAttributeMaxDynamicSharedMemorySize, ATTN_SMEM);

    round_all_kernel<<<dim3(HID * CC / 4 / 256, 8), 256>>>(
        (const float4*)qkv_w, (const float4*)ap_w, (const float4*)q_w,
        (const float4*)k_w, (const float4*)v_w, (const float4*)cp_w,
        (const float4*)fc1_w, (const float4*)fc2_w, wh);

    // ---- self attention ----
    layernorm_kernel<<<T, 256>>>(xs, ln1w, ln1b, h);
    gemm_f16<0><<<dim3(18, T / 128), 256, GEMM_SMEM>>>(h, wh + WO_QKV, nullptr, nullptr, qkv, T, 3 * CC, CC);
    attn_f16<false><<<dim3(4, PSELF), 256, ATTN_SMEM>>>(qkv, qkv, nullptr, o);
    gemm_f16<2><<<dim3(6, T / 128), 256, GEMM_SMEM>>>(o, wh + WO_AP, ap_b, xs, x, T, CC, CC);

    // ---- cross attention ----
    layernorm2_kernel<<<dim3(T, 2), 256>>>(x, ln2w, ln2b, h, ys, lnyw, lnyb, yn);
    gemm_f16<0><<<dim3(6, T / 128), 256, GEMM_SMEM>>>(h, wh + WO_Q, nullptr, nullptr, q, T, CC, CC);
    gemm_f16<0><<<dim3(12, T / 128), 256, GEMM_SMEM>>>(yn, wh + WO_K, nullptr, nullptr, qkv, T, 2 * CC, CC);
    attn_f16<true><<<dim3(4, PCROSS), 256, ATTN_SMEM>>>(q, qkv, rel, big);
    gemm_f16<1><<<dim3(6, TT / 128), 256, GEMM_SMEM>>>(big, wh + WO_CP, cp_b, nullptr, big2, TT, CC, CC);
    merge_kernel<<<(T * CC / 4 + 255) / 256, 256>>>((const float4*)big2, (float4*)x);

    // ---- MLP ----
    layernorm_kernel<<<T, 256>>>(x, ln3w, ln3b, h);
    gemm_f16<3><<<dim3(24, T / 128), 256, GEMM_SMEM>>>(h, wh + WO_FC1, fc1_b, nullptr, big, T, HID, CC);
    gemm_f16<2><<<dim3(6, T / 128), 256, GEMM_SMEM>>>(big, wh + WO_FC2, fc2_b, x, out, T, CC, HID);
}

// round 14
// speedup vs baseline: 1.6044x; 1.0043x over previous
#include <cuda_runtime.h>
#include <cuda_fp16.h>
#include <math.h>
#include <stdint.h>

// ---------------------------------------------------------------------------
// MultiviewDecoderBlock (Vx=8, Vy=8, B=4, N=196, C=768, H=12, DH=64, M=4)
// fp16 GEMMs (cp.async 3-stage, K64, ldmatrix, fp32 accum) + fp16 attention.
// Two-stream overlap of the cross k|v producer chain with the self branch.
// ---------------------------------------------------------------------------

constexpr int VX = 8, BB = 4, NN = 196, CC = 768, HH = 12, DHH = 64, MV = 4;
constexpr int HID = 4 * CC;            // 3072
constexpr int VB = VX * BB;            // 32
constexpr int T  = VB * NN;            // 6272
constexpr int TT = VX * MV * BB * NN;  // 25088
constexpr int PSELF  = VB * HH;            // 384
constexpr int PCROSS = VX * MV * BB * HH;  // 1536
constexpr float ATTN_SCALE = 0.125f;

// -------------------------- device scratch ---------------------------------
__device__ __align__(256) float  g_x   [T * CC];       // residual stream (fp32)
__device__ __align__(256) float  g_big2[TT * CC];      // cross-proj out (fp32)
__device__ __align__(256) __half g_h   [T * CC];       // LN out
__device__ __align__(256) __half g_yn  [T * CC];
__device__ __align__(256) __half g_qkv [T * 3 * CC];   // self qkv
__device__ __align__(256) __half g_kv  [T * 2 * CC];   // cross k|v (own buffer)
__device__ __align__(256) __half g_q   [T * CC];
__device__ __align__(256) __half g_o   [T * CC];
__device__ __align__(256) __half g_big [TT * CC];      // cross attn out; later MLP hidden
__device__ __align__(256) __half g_wh  [9437184];      // fp16 weights

constexpr int WO_QKV = 0;
constexpr int WO_AP  = 3 * CC * CC;
constexpr int WO_Q   = WO_AP  + CC * CC;
constexpr int WO_K   = WO_Q   + CC * CC;   // k|v contiguous -> fused N=1536 GEMM
constexpr int WO_V   = WO_K   + CC * CC;
constexpr int WO_CP  = WO_V   + CC * CC;
constexpr int WO_FC1 = WO_CP  + CC * CC;
constexpr int WO_FC2 = WO_FC1 + HID * CC;

extern __shared__ __align__(16) unsigned char dyn_smem[];

// ----------------------------- helpers -------------------------------------
__device__ __forceinline__ unsigned pkh(float lo, float hi) {
    unsigned r;
    asm("cvt.rn.f16x2.f32 %0, %1, %2;" : "=r"(r) : "f"(hi), "f"(lo));
    return r;
}
__device__ __forceinline__ void mma16h(float* c, const unsigned* a, const unsigned* b) {
    asm volatile(
        "mma.sync.aligned.m16n8k16.row.col.f32.f16.f16.f32 "
        "{%0,%1,%2,%3},{%4,%5,%6,%7},{%8,%9},{%0,%1,%2,%3};\n"
        : "+f"(c[0]), "+f"(c[1]), "+f"(c[2]), "+f"(c[3])
        : "r"(a[0]), "r"(a[1]), "r"(a[2]), "r"(a[3]), "r"(b[0]), "r"(b[1]));
}
__device__ __forceinline__ void ldmx4(unsigned* d, unsigned addr) {
    asm("ldmatrix.sync.aligned.m8n8.x4.shared.b16 {%0,%1,%2,%3}, [%4];"
        : "=r"(d[0]), "=r"(d[1]), "=r"(d[2]), "=r"(d[3]) : "r"(addr));
}
__device__ __forceinline__ void ldmx4t(unsigned* d, unsigned addr) {
    asm volatile("ldmatrix.sync.aligned.m8n8.x4.trans.shared.b16 {%0,%1,%2,%3}, [%4];"
                 : "=r"(d[0]), "=r"(d[1]), "=r"(d[2]), "=r"(d[3]) : "r"(addr));
}
__device__ __forceinline__ void cp16(unsigned d, const void* s) {
    asm volatile("cp.async.cg.shared.global [%0], [%1], 16;" :: "r"(d), "l"(s));
}

// ----------------------------- utility kernels ------------------------------
__global__ void round_all_kernel(
    const float4* s0, const float4* s1, const float4* s2, const float4* s3,
    const float4* s4, const float4* s5, const float4* s6, const float4* s7,
    __half* dst)
{
    const int seg = blockIdx.y;
    const float4* srcs[8] = {s0, s1, s2, s3, s4, s5, s6, s7};
    const int sizes4[8] = {3*CC*CC/4, CC*CC/4, CC*CC/4, CC*CC/4,
                           CC*CC/4, CC*CC/4, HID*CC/4, CC*HID/4};
    const int offs4[8] = {WO_QKV/4, WO_AP/4, WO_Q/4, WO_K/4,
                          WO_V/4, WO_CP/4, WO_FC1/4, WO_FC2/4};
    int i = blockIdx.x * blockDim.x + threadIdx.x;
    if (i < sizes4[seg]) {
        float4 v = srcs[seg][i];
        __half2* d = (__half2*)(dst + (size_t)(offs4[seg] + i) * 4);
        d[0] = __floats2half2_rn(v.x, v.y);
        d[1] = __floats2half2_rn(v.z, v.w);
    }
}

__device__ __forceinline__ void ln_vals(float v0, float v1, float v2,
                                        const float* w, const float* b,
                                        __half* orow, int tid) {
    float s  = v0 + v1 + v2;
    float sq = v0 * v0 + v1 * v1 + v2 * v2;
    #pragma unroll
    for (int off = 16; off; off >>= 1) {
        s  += __shfl_xor_sync(0xffffffffu, s, off);
        sq += __shfl_xor_sync(0xffffffffu, sq, off);
    }
    __shared__ float red[2][8];
    int warp = tid >> 5, lane = tid & 31;
    if (lane == 0) { red[0][warp] = s; red[1][warp] = sq; }
    __syncthreads();
    float ts = 0.f, tsq = 0.f;
    #pragma unroll
    for (int i = 0; i < 8; i++) { ts += red[0][i]; tsq += red[1][i]; }
    float mu = ts * (1.0f / CC);
    float var = tsq * (1.0f / CC) - mu * mu;
    float rstd = rsqrtf(var + 1e-5f);
    orow[tid]       = __float2half_rn((v0 - mu) * rstd * w[tid]       + b[tid]);
    orow[tid + 256] = __float2half_rn((v1 - mu) * rstd * w[tid + 256] + b[tid + 256]);
    orow[tid + 512] = __float2half_rn((v2 - mu) * rstd * w[tid + 512] + b[tid + 512]);
}

__global__ void layernorm_kernel(const float* __restrict__ in,
                                 const float* __restrict__ w,
                                 const float* __restrict__ b,
                                 __half* __restrict__ out) {
    int row = blockIdx.x;
    const float* xr = in + (size_t)row * CC;
    int tid = threadIdx.x;
    ln_vals(xr[tid], xr[tid + 256], xr[tid + 512], w, b,
            out + (size_t)row * CC, tid);
}

// fused: max-merge over M views + residual add (updates x) + LN3 -> h
__global__ void mergeln_kernel(const float* __restrict__ proj,
                               float* __restrict__ x,
                               const float* __restrict__ w,
                               const float* __restrict__ b,
                               __half* __restrict__ out) {
    int row = blockIdx.x;
    int n = row % NN, bb = (row / NN) % BB, v = row / (NN * BB);
    size_t pbase = ((((size_t)v * MV) * BB + bb) * NN + n) * CC;
    size_t ms = (size_t)BB * NN * CC;
    float* xr = x + (size_t)row * CC;
    int tid = threadIdx.x;
    float vv[3];
    #pragma unroll
    for (int t = 0; t < 3; t++) {
        int c = tid + 256 * t;
        float mx = proj[pbase + c];
        #pragma unroll
        for (int m = 1; m < MV; m++)
            mx = fmaxf(mx, proj[pbase + (size_t)m * ms + c]);
        vv[t] = xr[c] + mx;
        xr[c] = vv[t];
    }
    ln_vals(vv[0], vv[1], vv[2], w, b, out + (size_t)row * CC, tid);
}

// --------------- fp16 GEMM, cp.async 3 stages, K64 tiles --------------------
constexpr int GSTAGES = 3;
constexpr int RB   = 144;
constexpr int ASTG = 128 * RB;
constexpr int GEMM_SMEM = GSTAGES * 2 * ASTG;  // 110592

template<int EPI>
__global__ void __launch_bounds__(256, 2) gemm_f16(
    const __half* __restrict__ A, const __half* __restrict__ Bw,
    const float* __restrict__ bias, const float* __restrict__ res,
    void* __restrict__ Cv, int Mdim, int Ndim, int Kdim)
{
    const unsigned sbase = (unsigned)__cvta_generic_to_shared(dyn_smem);
    const int tid = threadIdx.x;
    const int lane = tid & 31, warp = tid >> 5;
    const int wm = (warp >> 2) * 64;
    const int wn = (warp & 3) * 32;
    const int bm = blockIdx.y * 128, bn = blockIdx.x * 128;

    const int r0 = tid >> 3;
    const int gg = tid & 7;
    const __half* Agp = A  + (size_t)(bm + r0) * Kdim + gg * 8;
    const __half* Bgp = Bw + (size_t)(bn + r0) * Kdim + gg * 8;
    const unsigned dA = sbase + (unsigned)(r0 * RB + gg * 16);
    const unsigned dB = dA + GSTAGES * ASTG;

    float acc[4][4][4];
    #pragma unroll
    for (int i = 0; i < 4; i++)
        #pragma unroll
        for (int j = 0; j < 4; j++)
            #pragma unroll
            for (int t = 0; t < 4; t++) acc[i][j][t] = 0.f;

    const int nst = Kdim >> 6;
    #pragma unroll
    for (int s = 0; s < GSTAGES - 1; s++) {
        unsigned off = (unsigned)s * ASTG;
        int koff = s * 64;
        #pragma unroll
        for (int i = 0; i < 4; i++) {
            cp16(dA + off + (unsigned)(32 * i * RB), Agp + (size_t)(32 * i) * Kdim + koff);
            cp16(dB + off + (unsigned)(32 * i * RB), Bgp + (size_t)(32 * i) * Kdim + koff);
        }
        asm volatile("cp.async.commit_group;");
    }

    const unsigned aoff = (unsigned)((lane & 15) * RB + (lane >> 4) * 16);
    const int bsel = lane >> 3;
    const unsigned boff = (unsigned)((((bsel >> 1) << 3) + (lane & 7)) * RB +
                                     (bsel & 1) * 16);

    #pragma unroll 1
    for (int kt = 0; kt < nst; kt++) {
        asm volatile("cp.async.wait_group 1;");
        __syncthreads();
        const int buf = kt % GSTAGES;
        const unsigned abase = sbase + (unsigned)buf * ASTG;
        const unsigned bbase = sbase + (unsigned)(GSTAGES + buf) * ASTG;
        #pragma unroll
        for (int c = 0; c < 4; c++) {
            unsigned a[4][4], bb0[4], bb1[4];
            #pragma unroll
            for (int mf = 0; mf < 4; mf++)
                ldmx4(a[mf], abase + (unsigned)((wm + mf * 16) * RB + c * 32) + aoff);
            ldmx4(bb0, bbase + (unsigned)(wn * RB + c * 32) + boff);
            ldmx4(bb1, bbase + (unsigned)((wn + 16) * RB + c * 32) + boff);
            unsigned b0[2] = {bb0[0], bb0[1]};
            unsigned b1[2] = {bb0[2], bb0[3]};
            unsigned b2[2] = {bb1[0], bb1[1]};
            unsigned b3[2] = {bb1[2], bb1[3]};
            #pragma unroll
            for (int mf = 0; mf < 4; mf++) {
                mma16h(acc[mf][0], a[mf], b0);
                mma16h(acc[mf][1], a[mf], b1);
                mma16h(acc[mf][2], a[mf], b2);
                mma16h(acc[mf][3], a[mf], b3);
            }
        }
        if (kt + GSTAGES - 1 < nst) {
            unsigned off = (unsigned)((kt + GSTAGES - 1) % GSTAGES) * ASTG;
            int koff = (kt + GSTAGES - 1) * 64;
            #pragma unroll
            for (int i = 0; i < 4; i++) {
                cp16(dA + off + (unsigned)(32 * i * RB), Agp + (size_t)(32 * i) * Kdim + koff);
                cp16(dB + off + (unsigned)(32 * i * RB), Bgp + (size_t)(32 * i) * Kdim + koff);
            }
        }
        asm volatile("cp.async.commit_group;");
    }

    #pragma unroll
    for (int mf = 0; mf < 4; mf++) {
        #pragma unroll
        for (int nf = 0; nf < 4; nf++) {
            const int col = bn + wn + nf * 8 + (lane & 3) * 2;
            float bb0 = 0.f, bb1 = 0.f;
            if (EPI >= 1) { bb0 = bias[col]; bb1 = bias[col + 1]; }
            #pragma unroll
            for (int hh = 0; hh < 2; hh++) {
                const size_t row = (size_t)(bm + wm + mf * 16 + (lane >> 2) + hh * 8);
                float v0 = acc[mf][nf][hh * 2 + 0] + bb0;
                float v1 = acc[mf][nf][hh * 2 + 1] + bb1;
                if (EPI == 2) {
                    v0 += res[row * Ndim + col];
                    v1 += res[row * Ndim + col + 1];
                }
                if (EPI == 3) {
                    v0 = 0.5f * v0 * (1.0f + erff(v0 * 0.70710678118654752f));
                    v1 = 0.5f * v1 * (1.0f + erff(v1 * 0.70710678118654752f));
                }
                if (EPI == 0 || EPI == 3) {
                    __half* C = (__half*)Cv;
                    *(unsigned*)(C + row * Ndim + col) = pkh(v0, v1);
                } else {
                    float* C = (float*)Cv;
                    *(float2*)(C + row * Ndim + col) = make_float2(v0, v1);
                }
            }
        }
    }
}

// ------------------------- fp16 mma attention -------------------------------
constexpr int QWS = 36;
constexpr int PWS = 108;
constexpr int W_Q = 0;
constexpr int W_K = 2304;
constexpr int W_V = 9792;
constexpr int W_RED = 17280;
constexpr int ATTN_SMEM = (W_RED + 256) * 4;  // 70144 bytes

template<bool CROSS>
__global__ void __launch_bounds__(256) attn_f16(
    const __half* __restrict__ Qsrc, const __half* __restrict__ Ksrc,
    const int* __restrict__ rel, __half* __restrict__ Out)
{
    unsigned* W = (unsigned*)dyn_smem;
    unsigned* Qw = W + W_Q;
    unsigned* Kw = W + W_K;
    unsigned* Vw = W + W_V;
    unsigned* Pw = W;
    float* redmax = (float*)(W + W_RED);
    float* redsum = redmax + 128;
    const unsigned sbase = (unsigned)__cvta_generic_to_shared(dyn_smem);

    const int p = blockIdx.y;
    const int m0 = blockIdx.x * 64;
    const int tid = threadIdx.x;
    const int lane = tid & 31, warp = tid >> 5;
    const int wm = warp & 3, wn = warp >> 2;
    const int r = lane >> 2, q = lane & 3;

    const __half *qp, *kp, *vp;
    __half* op;
    int qrs, kvs;
    if (!CROSS) {
        int vb = p / HH, h2 = p % HH;
        const __half* base = Qsrc + (size_t)vb * NN * 3 * CC;
        qp = base + h2 * DHH;
        kp = base + CC + h2 * DHH;
        vp = base + 2 * CC + h2 * DHH;
        qrs = 3 * CC; kvs = 3 * CC;
        op = Out + (size_t)vb * NN * CC + h2 * DHH;
    } else {
        int h2 = p % HH; int rr = p / HH;
        int b = rr % BB; int r2 = rr / BB;
        int mvi = r2 % MV; int v = r2 / MV;
        int vy = rel[v * MV + mvi];
        qp = Qsrc + ((size_t)(v * BB + b) * NN) * CC + h2 * DHH; qrs = CC;
        kp = Ksrc + ((size_t)(vy * BB + b) * NN) * 1536 + h2 * DHH;
        vp = kp + CC;
        kvs = 1536;
        op = Out + (size_t)rr * NN * CC + h2 * DHH;
    }

    #pragma unroll
    for (int it = 0; it < 4; it++) {
        int idx = tid + 256 * it;
        int row = idx >> 4, w2 = (idx & 15) * 2;
        uint2 qv = make_uint2(0u, 0u);
        if (m0 + row < NN) qv = *(const uint2*)(qp + (size_t)(m0 + row) * qrs + w2 * 2);
        Qw[row * QWS + w2]     = qv.x;
        Qw[row * QWS + w2 + 1] = qv.y;
    }
    #pragma unroll
    for (int it = 0; it < 13; it++) {
        int idx = tid + 256 * it;
        int row = idx >> 4, w2 = (idx & 15) * 2;
        uint2 kv = make_uint2(0u, 0u);
        uint2 vv = make_uint2(0u, 0u);
        if (row < NN) {
            kv = *(const uint2*)(kp + (size_t)row * kvs + w2 * 2);
            vv = *(const uint2*)(vp + (size_t)row * kvs + w2 * 2);
        }
        Kw[row * QWS + w2]     = kv.x;
        Kw[row * QWS + w2 + 1] = kv.y;
        Vw[row * QWS + w2]     = vv.x;
        Vw[row * QWS + w2 + 1] = vv.y;
    }
    __syncthreads();

    const int n0 = wn * 104;
    float sc[13][4];
    #pragma unroll
    for (int j = 0; j < 13; j++)
        #pragma unroll
        for (int t = 0; t < 4; t++) sc[j][t] = 0.f;

    #pragma unroll
    for (int kt = 0; kt < 4; kt++) {
        unsigned a[4];
        const unsigned* ap = Qw + (wm * 16 + r) * QWS + kt * 8 + q;
        a[0] = ap[0];
        a[1] = ap[8 * QWS];
        a[2] = ap[4];
        a[3] = ap[8 * QWS + 4];
        #pragma unroll
        for (int j = 0; j < 13; j++) {
            unsigned b[2];
            const unsigned* bp = Kw + (n0 + j * 8 + r) * QWS + kt * 8 + q;
            b[0] = bp[0];
            b[1] = bp[4];
            mma16h(sc[j], a, b);
        }
    }

    #pragma unroll
    for (int j = 0; j < 13; j++) {
        int cbase = n0 + j * 8 + 2 * q;
        #pragma unroll
        for (int t = 0; t < 4; t++) {
            int col = cbase + (t & 1);
            sc[j][t] = (col < NN) ? sc[j][t] * ATTN_SCALE : -1e30f;
        }
    }

    float mx0 = -1e30f, mx1 = -1e30f;
    #pragma unroll
    for (int j = 0; j < 13; j++) {
        mx0 = fmaxf(mx0, fmaxf(sc[j][0], sc[j][1]));
        mx1 = fmaxf(mx1, fmaxf(sc[j][2], sc[j][3]));
    }
    mx0 = fmaxf(mx0, __shfl_xor_sync(0xffffffffu, mx0, 1));
    mx0 = fmaxf(mx0, __shfl_xor_sync(0xffffffffu, mx0, 2));
    mx1 = fmaxf(mx1, __shfl_xor_sync(0xffffffffu, mx1, 1));
    mx1 = fmaxf(mx1, __shfl_xor_sync(0xffffffffu, mx1, 2));
    int rowl = wm * 16 + r;
    if (q == 0) {
        redmax[wn * 64 + rowl] = mx0;
        redmax[wn * 64 + rowl + 8] = mx1;
    }
    __syncthreads();
    float fm0 = fmaxf(redmax[rowl], redmax[64 + rowl]);
    float fm1 = fmaxf(redmax[rowl + 8], redmax[64 + rowl + 8]);

    float s0 = 0.f, s1 = 0.f;
    #pragma unroll
    for (int j = 0; j < 13; j++) {
        sc[j][0] = __expf(sc[j][0] - fm0);
        sc[j][1] = __expf(sc[j][1] - fm0);
        sc[j][2] = __expf(sc[j][2] - fm1);
        sc[j][3] = __expf(sc[j][3] - fm1);
        s0 += sc[j][0] + sc[j][1];
        s1 += sc[j][2] + sc[j][3];
    }
    s0 += __shfl_xor_sync(0xffffffffu, s0, 1);
    s0 += __shfl_xor_sync(0xffffffffu, s0, 2);
    s1 += __shfl_xor_sync(0xffffffffu, s1, 1);
    s1 += __shfl_xor_sync(0xffffffffu, s1, 2);
    if (q == 0) {
        redsum[wn * 64 + rowl] = s0;
        redsum[wn * 64 + rowl + 8] = s1;
    }
    #pragma unroll
    for (int j = 0; j < 13; j++) {
        int wbase = (n0 >> 1) + j * 4 + q;
        Pw[rowl * PWS + wbase]       = pkh(sc[j][0], sc[j][1]);
        Pw[(rowl + 8) * PWS + wbase] = pkh(sc[j][2], sc[j][3]);
    }
    __syncthreads();

    const int oc0 = wn * 32;
    float oacc[4][4];
    #pragma unroll
    for (int j = 0; j < 4; j++)
        #pragma unroll
        for (int t = 0; t < 4; t++) oacc[j][t] = 0.f;

    const int lrow = lane & 15;
    const int lcol = (lane >> 4) * 8;
    #pragma unroll
    for (int kt = 0; kt < 13; kt++) {
        unsigned a[4];
        const unsigned* ap2 = Pw + rowl * PWS + kt * 8 + q;
        a[0] = ap2[0];
        a[1] = ap2[8 * PWS];
        a[2] = ap2[4];
        a[3] = ap2[8 * PWS + 4];
        #pragma unroll
        for (int jp = 0; jp < 2; jp++) {
            unsigned b4[4];
            unsigned addr = sbase + (unsigned)(W_V * 4) +
                (unsigned)((kt * 16 + lrow) * 72 + oc0 + jp * 16 + lcol) * 2u;
            ldmx4t(b4, addr);
            mma16h(oacc[jp * 2 + 0], a, b4 + 0);
            mma16h(oacc[jp * 2 + 1], a, b4 + 2);
        }
    }

    float inv0 = 1.0f / (redsum[rowl] + redsum[64 + rowl]);
    float inv1 = 1.0f / (redsum[rowl + 8] + redsum[64 + rowl + 8]);
    int mg0 = m0 + rowl, mg1 = m0 + rowl + 8;
    #pragma unroll
    for (int j = 0; j < 4; j++) {
        int col = oc0 + j * 8 + 2 * q;
        if (mg0 < NN)
            *(unsigned*)(op + (size_t)mg0 * CC + col) =
                pkh(oacc[j][0] * inv0, oacc[j][1] * inv0);
        if (mg1 < NN)
            *(unsigned*)(op + (size_t)mg1 * CC + col) =
                pkh(oacc[j][2] * inv1, oacc[j][3] * inv1);
    }
}

// ------------------------------- launch -------------------------------------
extern "C" void kernel_launch(void* const* d_in, const int* in_sizes, int n_in,
                              void* d_out, int out_size) {
    int sh = (in_sizes[5] == 1) ? 0 : -1;

    const float* xs  = (const float*)d_in[0];
    const float* ys  = (const float*)d_in[1];
    const int* rel   = (const int*)d_in[4];
    const float* qkv_w = (const float*)d_in[6 + sh];
    const float* ap_w  = (const float*)d_in[7 + sh];
    const float* ap_b  = (const float*)d_in[8 + sh];
    const float* q_w   = (const float*)d_in[9 + sh];
    const float* k_w   = (const float*)d_in[10 + sh];
    const float* v_w   = (const float*)d_in[11 + sh];
    const float* cp_w  = (const float*)d_in[12 + sh];
    const float* cp_b  = (const float*)d_in[13 + sh];
    const float* fc1_w = (const float*)d_in[14 + sh];
    const float* fc1_b = (const float*)d_in[15 + sh];
    const float* fc2_w = (const float*)d_in[16 + sh];
    const float* fc2_b = (const float*)d_in[17 + sh];
    const float* ln1w = (const float*)d_in[18 + sh];
    const float* ln1b = (const float*)d_in[19 + sh];
    const float* ln2w = (const float*)d_in[20 + sh];
    const float* ln2b = (const float*)d_in[21 + sh];
    const float* ln3w = (const float*)d_in[22 + sh];
    const float* ln3b = (const float*)d_in[23 + sh];
    const float* lnyw = (const float*)d_in[24 + sh];
    const float* lnyb = (const float*)d_in[25 + sh];
    float* out = (float*)d_out;

    float *x, *big2;
    __half *h, *yn, *qkv, *kv, *q, *o, *big, *wh;
    cudaGetSymbolAddress((void**)&x, g_x);
    cudaGetSymbolAddress((void**)&big2, g_big2);
    cudaGetSymbolAddress((void**)&h, g_h);
    cudaGetSymbolAddress((void**)&yn, g_yn);
    cudaGetSymbolAddress((void**)&qkv, g_qkv);
    cudaGetSymbolAddress((void**)&kv, g_kv);
    cudaGetSymbolAddress((void**)&q, g_q);
    cudaGetSymbolAddress((void**)&o, g_o);
    cudaGetSymbolAddress((void**)&big, g_big);
    cudaGetSymbolAddress((void**)&wh, g_wh);

    cudaFuncSetAttribute(gemm_f16<0>, cudaFuncAttributeMaxDynamicSharedMemorySize, GEMM_SMEM);
    cudaFuncSetAttribute(gemm_f16<1>, cudaFuncAttributeMaxDynamicSharedMemorySize, GEMM_SMEM);
    cudaFuncSetAttribute(gemm_f16<2>, cudaFuncAttributeMaxDynamicSharedMemorySize, GEMM_SMEM);
    cudaFuncSetAttribute(gemm_f16<3>, cudaFuncAttributeMaxDynamicSharedMemorySize, GEMM_SMEM);
    cudaFuncSetAttribute(attn_f16<false>, cudaFuncAttributeMaxDynamicSharedMemorySize, ATTN_SMEM);
    cudaFuncSetAttribute(attn_f16<true>,  cudaFuncAttributeMaxDynamicSharedMemorySize, ATTN_SMEM);

    // second stream + fork/join events. Created once on the first (uncaptured)
    // correctness call; reused identically on every call (same work each call).
    static cudaStream_t s2 = nullptr;
    static cudaEvent_t eF = nullptr, e1 = nullptr;
    if (s2 == nullptr) {
        cudaStreamCreate(&s2);
        cudaEventCreateWithFlags(&eF, cudaEventDisableTiming);
        cudaEventCreateWithFlags(&e1, cudaEventDisableTiming);
    }

    // weights -> fp16 (needed by both streams), then fork
    round_all_kernel<<<dim3(HID * CC / 4 / 256, 8), 256>>>(
        (const float4*)qkv_w, (const float4*)ap_w, (const float4*)q_w,
        (const float4*)k_w, (const float4*)v_w, (const float4*)cp_w,
        (const float4*)fc1_w, (const float4*)fc2_w, wh);
    cudaEventRecord(eF, 0);

    // ---- stream 2: cross k|v producer chain (independent of self branch) ----
    cudaStreamWaitEvent(s2, eF, 0);
    layernorm_kernel<<<T, 256, 0, s2>>>(ys, lnyw, lnyb, yn);
    gemm_f16<0><<<dim3(12, T / 128), 256, GEMM_SMEM, s2>>>(yn, wh + WO_K, nullptr, nullptr, kv, T, 2 * CC, CC);
    cudaEventRecord(e1, s2);

    // ---- stream 0: self attention ----
    layernorm_kernel<<<T, 256>>>(xs, ln1w, ln1b, h);
    gemm_f16<0><<<dim3(18, T / 128), 256, GEMM_SMEM>>>(h, wh + WO_QKV, nullptr, nullptr, qkv, T, 3 * CC, CC);
    attn_f16<false><<<dim3(4, PSELF), 256, ATTN_SMEM>>>(qkv, qkv, nullptr, o);
    gemm_f16<2><<<dim3(6, T / 128), 256, GEMM_SMEM>>>(o, wh + WO_AP, ap_b, xs, x, T, CC, CC);

    // ---- cross attention ----
    layernorm_kernel<<<T, 256>>>(x, ln2w, ln2b, h);
    gemm_f16<0><<<dim3(6, T / 128), 256, GEMM_SMEM>>>(h, wh + WO_Q, nullptr, nullptr, q, T, CC, CC);
    cudaStreamWaitEvent(0, e1, 0);
    attn_f16<true><<<dim3(4, PCROSS), 256, ATTN_SMEM>>>(q, kv, rel, big);
    gemm_f16<1><<<dim3(6, TT / 128), 256, GEMM_SMEM>>>(big, wh + WO_CP, cp_b, nullptr, big2, TT, CC, CC);
    mergeln_kernel<<<T, 256>>>(big2, x, ln3w, ln3b, h);

    // ---- MLP ----
    gemm_f16<3><<<dim3(24, T / 128), 256, GEMM_SMEM>>>(h, wh + WO_FC1, fc1_b, nullptr, big, T, HID, CC);
    gemm_f16<2><<<dim3(6, T / 128), 256, GEMM_SMEM>>>(big, wh + WO_FC2, fc2_b, x, out, T, CC, HID);
}

// round 15
// speedup vs baseline: 1.6190x; 1.0091x over previous
#include <cuda_runtime.h>
#include <cuda_fp16.h>
#include <math.h>
#include <stdint.h>

// ---------------------------------------------------------------------------
// MultiviewDecoderBlock (Vx=8, Vy=8, B=4, N=196, C=768, H=12, DH=64, M=4)
// fp16 GEMMs (cp.async 3-stage, K64, ldmatrix, fp32 accum) + fp16 attention
// (one block per head-problem, K/V resident, 4 q-tiles looped).
// ---------------------------------------------------------------------------

constexpr int VX = 8, BB = 4, NN = 196, CC = 768, HH = 12, DHH = 64, MV = 4;
constexpr int HID = 4 * CC;            // 3072
constexpr int VB = VX * BB;            // 32
constexpr int T  = VB * NN;            // 6272
constexpr int TT = VX * MV * BB * NN;  // 25088
constexpr int PSELF  = VB * HH;            // 384
constexpr int PCROSS = VX * MV * BB * HH;  // 1536
constexpr float ATTN_SCALE = 0.125f;

// -------------------------- device scratch ---------------------------------
__device__ __align__(256) float  g_x   [T * CC];       // residual stream (fp32)
__device__ __align__(256) float  g_big2[TT * CC];      // cross-proj out (fp32)
__device__ __align__(256) __half g_h   [T * CC];       // LN out
__device__ __align__(256) __half g_yn  [T * CC];
__device__ __align__(256) __half g_qkv [T * 3 * CC];   // self qkv
__device__ __align__(256) __half g_kv  [T * 2 * CC];   // cross k|v (own buffer)
__device__ __align__(256) __half g_q   [T * CC];
__device__ __align__(256) __half g_o   [T * CC];
__device__ __align__(256) __half g_big [TT * CC];      // cross attn out; later MLP hidden
__device__ __align__(256) __half g_wh  [9437184];      // fp16 weights

constexpr int WO_QKV = 0;
constexpr int WO_AP  = 3 * CC * CC;
constexpr int WO_Q   = WO_AP  + CC * CC;
constexpr int WO_K   = WO_Q   + CC * CC;   // k|v contiguous -> fused N=1536 GEMM
constexpr int WO_V   = WO_K   + CC * CC;
constexpr int WO_CP  = WO_V   + CC * CC;
constexpr int WO_FC1 = WO_CP  + CC * CC;
constexpr int WO_FC2 = WO_FC1 + HID * CC;

extern __shared__ __align__(16) unsigned char dyn_smem[];

// ----------------------------- helpers -------------------------------------
__device__ __forceinline__ unsigned pkh(float lo, float hi) {
    unsigned r;
    asm("cvt.rn.f16x2.f32 %0, %1, %2;" : "=r"(r) : "f"(hi), "f"(lo));
    return r;
}
__device__ __forceinline__ void mma16h(float* c, const unsigned* a, const unsigned* b) {
    asm volatile(
        "mma.sync.aligned.m16n8k16.row.col.f32.f16.f16.f32 "
        "{%0,%1,%2,%3},{%4,%5,%6,%7},{%8,%9},{%0,%1,%2,%3};\n"
        : "+f"(c[0]), "+f"(c[1]), "+f"(c[2]), "+f"(c[3])
        : "r"(a[0]), "r"(a[1]), "r"(a[2]), "r"(a[3]), "r"(b[0]), "r"(b[1]));
}
__device__ __forceinline__ void ldmx4(unsigned* d, unsigned addr) {
    asm("ldmatrix.sync.aligned.m8n8.x4.shared.b16 {%0,%1,%2,%3}, [%4];"
        : "=r"(d[0]), "=r"(d[1]), "=r"(d[2]), "=r"(d[3]) : "r"(addr));
}
__device__ __forceinline__ void ldmx4t(unsigned* d, unsigned addr) {
    asm volatile("ldmatrix.sync.aligned.m8n8.x4.trans.shared.b16 {%0,%1,%2,%3}, [%4];"
                 : "=r"(d[0]), "=r"(d[1]), "=r"(d[2]), "=r"(d[3]) : "r"(addr));
}
__device__ __forceinline__ void cp16(unsigned d, const void* s) {
    asm volatile("cp.async.cg.shared.global [%0], [%1], 16;" :: "r"(d), "l"(s));
}

// ----------------------------- utility kernels ------------------------------
__global__ void round_all_kernel(
    const float4* s0, const float4* s1, const float4* s2, const float4* s3,
    const float4* s4, const float4* s5, const float4* s6, const float4* s7,
    __half* dst)
{
    const int seg = blockIdx.y;
    const float4* srcs[8] = {s0, s1, s2, s3, s4, s5, s6, s7};
    const int sizes4[8] = {3*CC*CC/4, CC*CC/4, CC*CC/4, CC*CC/4,
                           CC*CC/4, CC*CC/4, HID*CC/4, CC*HID/4};
    const int offs4[8] = {WO_QKV/4, WO_AP/4, WO_Q/4, WO_K/4,
                          WO_V/4, WO_CP/4, WO_FC1/4, WO_FC2/4};
    int i = blockIdx.x * blockDim.x + threadIdx.x;
    if (i < sizes4[seg]) {
        float4 v = srcs[seg][i];
        __half2* d = (__half2*)(dst + (size_t)(offs4[seg] + i) * 4);
        d[0] = __floats2half2_rn(v.x, v.y);
        d[1] = __floats2half2_rn(v.z, v.w);
    }
}

__device__ __forceinline__ void ln_vals(float v0, float v1, float v2,
                                        const float* w, const float* b,
                                        __half* orow, int tid) {
    float s  = v0 + v1 + v2;
    float sq = v0 * v0 + v1 * v1 + v2 * v2;
    #pragma unroll
    for (int off = 16; off; off >>= 1) {
        s  += __shfl_xor_sync(0xffffffffu, s, off);
        sq += __shfl_xor_sync(0xffffffffu, sq, off);
    }
    __shared__ float red[2][8];
    int warp = tid >> 5, lane = tid & 31;
    if (lane == 0) { red[0][warp] = s; red[1][warp] = sq; }
    __syncthreads();
    float ts = 0.f, tsq = 0.f;
    #pragma unroll
    for (int i = 0; i < 8; i++) { ts += red[0][i]; tsq += red[1][i]; }
    float mu = ts * (1.0f / CC);
    float var = tsq * (1.0f / CC) - mu * mu;
    float rstd = rsqrtf(var + 1e-5f);
    orow[tid]       = __float2half_rn((v0 - mu) * rstd * w[tid]       + b[tid]);
    orow[tid + 256] = __float2half_rn((v1 - mu) * rstd * w[tid + 256] + b[tid + 256]);
    orow[tid + 512] = __float2half_rn((v2 - mu) * rstd * w[tid + 512] + b[tid + 512]);
}

__global__ void layernorm_kernel(const float* __restrict__ in,
                                 const float* __restrict__ w,
                                 const float* __restrict__ b,
                                 __half* __restrict__ out) {
    int row = blockIdx.x;
    const float* xr = in + (size_t)row * CC;
    int tid = threadIdx.x;
    ln_vals(xr[tid], xr[tid + 256], xr[tid + 512], w, b,
            out + (size_t)row * CC, tid);
}

// fused: max-merge over M views + residual add (updates x) + LN3 -> h
__global__ void mergeln_kernel(const float* __restrict__ proj,
                               float* __restrict__ x,
                               const float* __restrict__ w,
                               const float* __restrict__ b,
                               __half* __restrict__ out) {
    int row = blockIdx.x;
    int n = row % NN, bb = (row / NN) % BB, v = row / (NN * BB);
    size_t pbase = ((((size_t)v * MV) * BB + bb) * NN + n) * CC;
    size_t ms = (size_t)BB * NN * CC;
    float* xr = x + (size_t)row * CC;
    int tid = threadIdx.x;
    float vv[3];
    #pragma unroll
    for (int t = 0; t < 3; t++) {
        int c = tid + 256 * t;
        float mx = proj[pbase + c];
        #pragma unroll
        for (int m = 1; m < MV; m++)
            mx = fmaxf(mx, proj[pbase + (size_t)m * ms + c]);
        vv[t] = xr[c] + mx;
        xr[c] = vv[t];
    }
    ln_vals(vv[0], vv[1], vv[2], w, b, out + (size_t)row * CC, tid);
}

// --------------- fp16 GEMM, cp.async 3 stages, K64 tiles --------------------
constexpr int GSTAGES = 3;
constexpr int RB   = 144;
constexpr int ASTG = 128 * RB;
constexpr int GEMM_SMEM = GSTAGES * 2 * ASTG;  // 110592

template<int EPI>
__global__ void __launch_bounds__(256, 2) gemm_f16(
    const __half* __restrict__ A, const __half* __restrict__ Bw,
    const float* __restrict__ bias, const float* __restrict__ res,
    void* __restrict__ Cv, int Mdim, int Ndim, int Kdim)
{
    const unsigned sbase = (unsigned)__cvta_generic_to_shared(dyn_smem);
    const int tid = threadIdx.x;
    const int lane = tid & 31, warp = tid >> 5;
    const int wm = (warp >> 2) * 64;
    const int wn = (warp & 3) * 32;
    const int bm = blockIdx.y * 128, bn = blockIdx.x * 128;

    const int r0 = tid >> 3;
    const int gg = tid & 7;
    const __half* Agp = A  + (size_t)(bm + r0) * Kdim + gg * 8;
    const __half* Bgp = Bw + (size_t)(bn + r0) * Kdim + gg * 8;
    const unsigned dA = sbase + (unsigned)(r0 * RB + gg * 16);
    const unsigned dB = dA + GSTAGES * ASTG;

    float acc[4][4][4];
    #pragma unroll
    for (int i = 0; i < 4; i++)
        #pragma unroll
        for (int j = 0; j < 4; j++)
            #pragma unroll
            for (int t = 0; t < 4; t++) acc[i][j][t] = 0.f;

    const int nst = Kdim >> 6;
    #pragma unroll
    for (int s = 0; s < GSTAGES - 1; s++) {
        unsigned off = (unsigned)s * ASTG;
        int koff = s * 64;
        #pragma unroll
        for (int i = 0; i < 4; i++) {
            cp16(dA + off + (unsigned)(32 * i * RB), Agp + (size_t)(32 * i) * Kdim + koff);
            cp16(dB + off + (unsigned)(32 * i * RB), Bgp + (size_t)(32 * i) * Kdim + koff);
        }
        asm volatile("cp.async.commit_group;");
    }

    const unsigned aoff = (unsigned)((lane & 15) * RB + (lane >> 4) * 16);
    const int bsel = lane >> 3;
    const unsigned boff = (unsigned)((((bsel >> 1) << 3) + (lane & 7)) * RB +
                                     (bsel & 1) * 16);

    #pragma unroll 1
    for (int kt = 0; kt < nst; kt++) {
        asm volatile("cp.async.wait_group 1;");
        __syncthreads();
        const int buf = kt % GSTAGES;
        const unsigned abase = sbase + (unsigned)buf * ASTG;
        const unsigned bbase = sbase + (unsigned)(GSTAGES + buf) * ASTG;
        #pragma unroll
        for (int c = 0; c < 4; c++) {
            unsigned a[4][4], bb0[4], bb1[4];
            #pragma unroll
            for (int mf = 0; mf < 4; mf++)
                ldmx4(a[mf], abase + (unsigned)((wm + mf * 16) * RB + c * 32) + aoff);
            ldmx4(bb0, bbase + (unsigned)(wn * RB + c * 32) + boff);
            ldmx4(bb1, bbase + (unsigned)((wn + 16) * RB + c * 32) + boff);
            unsigned b0[2] = {bb0[0], bb0[1]};
            unsigned b1[2] = {bb0[2], bb0[3]};
            unsigned b2[2] = {bb1[0], bb1[1]};
            unsigned b3[2] = {bb1[2], bb1[3]};
            #pragma unroll
            for (int mf = 0; mf < 4; mf++) {
                mma16h(acc[mf][0], a[mf], b0);
                mma16h(acc[mf][1], a[mf], b1);
                mma16h(acc[mf][2], a[mf], b2);
                mma16h(acc[mf][3], a[mf], b3);
            }
        }
        if (kt + GSTAGES - 1 < nst) {
            unsigned off = (unsigned)((kt + GSTAGES - 1) % GSTAGES) * ASTG;
            int koff = (kt + GSTAGES - 1) * 64;
            #pragma unroll
            for (int i = 0; i < 4; i++) {
                cp16(dA + off + (unsigned)(32 * i * RB), Agp + (size_t)(32 * i) * Kdim + koff);
                cp16(dB + off + (unsigned)(32 * i * RB), Bgp + (size_t)(32 * i) * Kdim + koff);
            }
        }
        asm volatile("cp.async.commit_group;");
    }

    #pragma unroll
    for (int mf = 0; mf < 4; mf++) {
        #pragma unroll
        for (int nf = 0; nf < 4; nf++) {
            const int col = bn + wn + nf * 8 + (lane & 3) * 2;
            float bb0 = 0.f, bb1 = 0.f;
            if (EPI >= 1) { bb0 = bias[col]; bb1 = bias[col + 1]; }
            #pragma unroll
            for (int hh = 0; hh < 2; hh++) {
                const size_t row = (size_t)(bm + wm + mf * 16 + (lane >> 2) + hh * 8);
                float v0 = acc[mf][nf][hh * 2 + 0] + bb0;
                float v1 = acc[mf][nf][hh * 2 + 1] + bb1;
                if (EPI == 2) {
                    v0 += res[row * Ndim + col];
                    v1 += res[row * Ndim + col + 1];
                }
                if (EPI == 3) {
                    v0 = 0.5f * v0 * (1.0f + erff(v0 * 0.70710678118654752f));
                    v1 = 0.5f * v1 * (1.0f + erff(v1 * 0.70710678118654752f));
                }
                if (EPI == 0 || EPI == 3) {
                    __half* C = (__half*)Cv;
                    *(unsigned*)(C + row * Ndim + col) = pkh(v0, v1);
                } else {
                    float* C = (float*)Cv;
                    *(float2*)(C + row * Ndim + col) = make_float2(v0, v1);
                }
            }
        }
    }
}

// ------------------------- fp16 mma attention -------------------------------
// One block per head-problem. K/V resident in smem; loop over 4 q-tiles.
// P region overlaps Q region only (Q reads done before P writes via the
// post-redmax barrier; next-iter Q load ordered after PV via end barrier).
constexpr int QWS = 36;
constexpr int PWS = 108;
constexpr int W_PQ = 0;                 // P: 64*108 = 6912 words; Q: 64*36 inside
constexpr int W_K  = 6912;              // 208*36 = 7488 words
constexpr int W_V  = 14400;             // 7488 words
constexpr int W_RED = 21888;            // 256 floats
constexpr int ATTN_SMEM = (W_RED + 256) * 4;  // 88576 bytes

template<bool CROSS>
__global__ void __launch_bounds__(256, 2) attn_f16(
    const __half* __restrict__ Qsrc, const __half* __restrict__ Ksrc,
    const int* __restrict__ rel, __half* __restrict__ Out)
{
    unsigned* W = (unsigned*)dyn_smem;
    unsigned* Qw = W + W_PQ;
    unsigned* Kw = W + W_K;
    unsigned* Vw = W + W_V;
    unsigned* Pw = W + W_PQ;
    float* redmax = (float*)(W + W_RED);
    float* redsum = redmax + 128;
    const unsigned sbase = (unsigned)__cvta_generic_to_shared(dyn_smem);

    const int p = blockIdx.x;
    const int tid = threadIdx.x;
    const int lane = tid & 31, warp = tid >> 5;
    const int wm = warp & 3, wn = warp >> 2;
    const int r = lane >> 2, q = lane & 3;

    const __half *qp, *kp, *vp;
    __half* op;
    int qrs, kvs;
    if (!CROSS) {
        int vb = p / HH, h2 = p % HH;
        const __half* base = Qsrc + (size_t)vb * NN * 3 * CC;
        qp = base + h2 * DHH;
        kp = base + CC + h2 * DHH;
        vp = base + 2 * CC + h2 * DHH;
        qrs = 3 * CC; kvs = 3 * CC;
        op = Out + (size_t)vb * NN * CC + h2 * DHH;
    } else {
        int h2 = p % HH; int rr = p / HH;
        int b = rr % BB; int r2 = rr / BB;
        int mvi = r2 % MV; int v = r2 / MV;
        int vy = rel[v * MV + mvi];
        qp = Qsrc + ((size_t)(v * BB + b) * NN) * CC + h2 * DHH; qrs = CC;
        kp = Ksrc + ((size_t)(vy * BB + b) * NN) * 1536 + h2 * DHH;
        vp = kp + CC;
        kvs = 1536;
        op = Out + (size_t)rr * NN * CC + h2 * DHH;
    }

    // ---- load K, V once (208 rows, zero-padded >= NN) ----
    #pragma unroll
    for (int it = 0; it < 13; it++) {
        int idx = tid + 256 * it;
        int row = idx >> 4, w2 = (idx & 15) * 2;
        uint2 kv = make_uint2(0u, 0u);
        uint2 vv = make_uint2(0u, 0u);
        if (row < NN) {
            kv = *(const uint2*)(kp + (size_t)row * kvs + w2 * 2);
            vv = *(const uint2*)(vp + (size_t)row * kvs + w2 * 2);
        }
        Kw[row * QWS + w2]     = kv.x;
        Kw[row * QWS + w2 + 1] = kv.y;
        Vw[row * QWS + w2]     = vv.x;
        Vw[row * QWS + w2 + 1] = vv.y;
    }
    __syncthreads();

    const int n0 = wn * 104;
    const int rowl = wm * 16 + r;
    const int lrow = lane & 15;
    const int lcol = (lane >> 4) * 8;

    #pragma unroll 1
    for (int mt = 0; mt < 4; mt++) {
        const int m0 = mt * 64;

        // ---- load Q tile ----
        #pragma unroll
        for (int it = 0; it < 4; it++) {
            int idx = tid + 256 * it;
            int row = idx >> 4, w2 = (idx & 15) * 2;
            uint2 qv = make_uint2(0u, 0u);
            if (m0 + row < NN)
                qv = *(const uint2*)(qp + (size_t)(m0 + row) * qrs + w2 * 2);
            Qw[row * QWS + w2]     = qv.x;
            Qw[row * QWS + w2 + 1] = qv.y;
        }
        __syncthreads();

        // ---- scores: warp computes m16 x n104, k=64 ----
        float sc[13][4];
        #pragma unroll
        for (int j = 0; j < 13; j++)
            #pragma unroll
            for (int t = 0; t < 4; t++) sc[j][t] = 0.f;

        #pragma unroll
        for (int kt = 0; kt < 4; kt++) {
            unsigned a[4];
            const unsigned* ap = Qw + rowl * QWS + kt * 8 + q;
            a[0] = ap[0];
            a[1] = ap[8 * QWS];
            a[2] = ap[4];
            a[3] = ap[8 * QWS + 4];
            #pragma unroll
            for (int j = 0; j < 13; j++) {
                unsigned b[2];
                const unsigned* bp = Kw + (n0 + j * 8 + r) * QWS + kt * 8 + q;
                b[0] = bp[0];
                b[1] = bp[4];
                mma16h(sc[j], a, b);
            }
        }

        #pragma unroll
        for (int j = 0; j < 13; j++) {
            int cbase = n0 + j * 8 + 2 * q;
            #pragma unroll
            for (int t = 0; t < 4; t++) {
                int col = cbase + (t & 1);
                sc[j][t] = (col < NN) ? sc[j][t] * ATTN_SCALE : -1e30f;
            }
        }

        float mx0 = -1e30f, mx1 = -1e30f;
        #pragma unroll
        for (int j = 0; j < 13; j++) {
            mx0 = fmaxf(mx0, fmaxf(sc[j][0], sc[j][1]));
            mx1 = fmaxf(mx1, fmaxf(sc[j][2], sc[j][3]));
        }
        mx0 = fmaxf(mx0, __shfl_xor_sync(0xffffffffu, mx0, 1));
        mx0 = fmaxf(mx0, __shfl_xor_sync(0xffffffffu, mx0, 2));
        mx1 = fmaxf(mx1, __shfl_xor_sync(0xffffffffu, mx1, 1));
        mx1 = fmaxf(mx1, __shfl_xor_sync(0xffffffffu, mx1, 2));
        if (q == 0) {
            redmax[wn * 64 + rowl] = mx0;
            redmax[wn * 64 + rowl + 8] = mx1;
        }
        __syncthreads();   // all Q/K reads done -> P region writable
        float fm0 = fmaxf(redmax[rowl], redmax[64 + rowl]);
        float fm1 = fmaxf(redmax[rowl + 8], redmax[64 + rowl + 8]);

        float s0 = 0.f, s1 = 0.f;
        #pragma unroll
        for (int j = 0; j < 13; j++) {
            sc[j][0] = __expf(sc[j][0] - fm0);
            sc[j][1] = __expf(sc[j][1] - fm0);
            sc[j][2] = __expf(sc[j][2] - fm1);
            sc[j][3] = __expf(sc[j][3] - fm1);
            s0 += sc[j][0] + sc[j][1];
            s1 += sc[j][2] + sc[j][3];
        }
        s0 += __shfl_xor_sync(0xffffffffu, s0, 1);
        s0 += __shfl_xor_sync(0xffffffffu, s0, 2);
        s1 += __shfl_xor_sync(0xffffffffu, s1, 1);
        s1 += __shfl_xor_sync(0xffffffffu, s1, 2);
        if (q == 0) {
            redsum[wn * 64 + rowl] = s0;
            redsum[wn * 64 + rowl + 8] = s1;
        }
        #pragma unroll
        for (int j = 0; j < 13; j++) {
            int wbase = (n0 >> 1) + j * 4 + q;
            Pw[rowl * PWS + wbase]       = pkh(sc[j][0], sc[j][1]);
            Pw[(rowl + 8) * PWS + wbase] = pkh(sc[j][2], sc[j][3]);
        }
        __syncthreads();

        // ---- O = P @ V : warp computes m16 x n32 over 208 keys ----
        const int oc0 = wn * 32;
        float oacc[4][4];
        #pragma unroll
        for (int j = 0; j < 4; j++)
            #pragma unroll
            for (int t = 0; t < 4; t++) oacc[j][t] = 0.f;

        #pragma unroll
        for (int kt = 0; kt < 13; kt++) {
            unsigned a[4];
            const unsigned* ap2 = Pw + rowl * PWS + kt * 8 + q;
            a[0] = ap2[0];
            a[1] = ap2[8 * PWS];
            a[2] = ap2[4];
            a[3] = ap2[8 * PWS + 4];
            #pragma unroll
            for (int jp = 0; jp < 2; jp++) {
                unsigned b4[4];
                unsigned addr = sbase + (unsigned)(W_V * 4) +
                    (unsigned)((kt * 16 + lrow) * 72 + oc0 + jp * 16 + lcol) * 2u;
                ldmx4t(b4, addr);
                mma16h(oacc[jp * 2 + 0], a, b4 + 0);
                mma16h(oacc[jp * 2 + 1], a, b4 + 2);
            }
        }

        float inv0 = 1.0f / (redsum[rowl] + redsum[64 + rowl]);
        float inv1 = 1.0f / (redsum[rowl + 8] + redsum[64 + rowl + 8]);
        int mg0 = m0 + rowl, mg1 = m0 + rowl + 8;
        #pragma unroll
        for (int j = 0; j < 4; j++) {
            int col = oc0 + j * 8 + 2 * q;
            if (mg0 < NN)
                *(unsigned*)(op + (size_t)mg0 * CC + col) =
                    pkh(oacc[j][0] * inv0, oacc[j][1] * inv0);
            if (mg1 < NN)
                *(unsigned*)(op + (size_t)mg1 * CC + col) =
                    pkh(oacc[j][2] * inv1, oacc[j][3] * inv1);
        }
        __syncthreads();   // P reads (and redsum reads) done -> next Q load safe
    }
}

// ------------------------------- launch -------------------------------------
extern "C" void kernel_launch(void* const* d_in, const int* in_sizes, int n_in,
                              void* d_out, int out_size) {
    int sh = (in_sizes[5] == 1) ? 0 : -1;

    const float* xs  = (const float*)d_in[0];
    const float* ys  = (const float*)d_in[1];
    const int* rel   = (const int*)d_in[4];
    const float* qkv_w = (const float*)d_in[6 + sh];
    const float* ap_w  = (const float*)d_in[7 + sh];
    const float* ap_b  = (const float*)d_in[8 + sh];
    const float* q_w   = (const float*)d_in[9 + sh];
    const float* k_w   = (const float*)d_in[10 + sh];
    const float* v_w   = (const float*)d_in[11 + sh];
    const float* cp_w  = (const float*)d_in[12 + sh];
    const float* cp_b  = (const float*)d_in[13 + sh];
    const float* fc1_w = (const float*)d_in[14 + sh];
    const float* fc1_b = (const float*)d_in[15 + sh];
    const float* fc2_w = (const float*)d_in[16 + sh];
    const float* fc2_b = (const float*)d_in[17 + sh];
    const float* ln1w = (const float*)d_in[18 + sh];
    const float* ln1b = (const float*)d_in[19 + sh];
    const float* ln2w = (const float*)d_in[20 + sh];
    const float* ln2b = (const float*)d_in[21 + sh];
    const float* ln3w = (const float*)d_in[22 + sh];
    const float* ln3b = (const float*)d_in[23 + sh];
    const float* lnyw = (const float*)d_in[24 + sh];
    const float* lnyb = (const float*)d_in[25 + sh];
    float* out = (float*)d_out;

    float *x, *big2;
    __half *h, *yn, *qkv, *kv, *q, *o, *big, *wh;
    cudaGetSymbolAddress((void**)&x, g_x);
    cudaGetSymbolAddress((void**)&big2, g_big2);
    cudaGetSymbolAddress((void**)&h, g_h);
    cudaGetSymbolAddress((void**)&yn, g_yn);
    cudaGetSymbolAddress((void**)&qkv, g_qkv);
    cudaGetSymbolAddress((void**)&kv, g_kv);
    cudaGetSymbolAddress((void**)&q, g_q);
    cudaGetSymbolAddress((void**)&o, g_o);
    cudaGetSymbolAddress((void**)&big, g_big);
    cudaGetSymbolAddress((void**)&wh, g_wh);

    cudaFuncSetAttribute(gemm_f16<0>, cudaFuncAttributeMaxDynamicSharedMemorySize, GEMM_SMEM);
    cudaFuncSetAttribute(gemm_f16<1>, cudaFuncAttributeMaxDynamicSharedMemorySize, GEMM_SMEM);
    cudaFuncSetAttribute(gemm_f16<2>, cudaFuncAttributeMaxDynamicSharedMemorySize, GEMM_SMEM);
    cudaFuncSetAttribute(gemm_f16<3>, cudaFuncAttributeMaxDynamicSharedMemorySize, GEMM_SMEM);
    cudaFuncSetAttribute(attn_f16<false>, cudaFuncAttributeMaxDynamicSharedMemorySize, ATTN_SMEM);
    cudaFuncSetAttribute(attn_f16<true>,  cudaFuncAttributeMaxDynamicSharedMemorySize, ATTN_SMEM);

    static cudaStream_t s2 = nullptr;
    static cudaEvent_t eF = nullptr, e1 = nullptr;
    if (s2 == nullptr) {
        cudaStreamCreate(&s2);
        cudaEventCreateWithFlags(&eF, cudaEventDisableTiming);
        cudaEventCreateWithFlags(&e1, cudaEventDisableTiming);
    }

    round_all_kernel<<<dim3(HID * CC / 4 / 256, 8), 256>>>(
        (const float4*)qkv_w, (const float4*)ap_w, (const float4*)q_w,
        (const float4*)k_w, (const float4*)v_w, (const float4*)cp_w,
        (const float4*)fc1_w, (const float4*)fc2_w, wh);
    cudaEventRecord(eF, 0);

    // ---- stream 2: cross k|v producer chain ----
    cudaStreamWaitEvent(s2, eF, 0);
    layernorm_kernel<<<T, 256, 0, s2>>>(ys, lnyw, lnyb, yn);
    gemm_f16<0><<<dim3(12, T / 128), 256, GEMM_SMEM, s2>>>(yn, wh + WO_K, nullptr, nullptr, kv, T, 2 * CC, CC);
    cudaEventRecord(e1, s2);

    // ---- stream 0: self attention ----
    layernorm_kernel<<<T, 256>>>(xs, ln1w, ln1b, h);
    gemm_f16<0><<<dim3(18, T / 128), 256, GEMM_SMEM>>>(h, wh + WO_QKV, nullptr, nullptr, qkv, T, 3 * CC, CC);
    attn_f16<false><<<PSELF, 256, ATTN_SMEM>>>(qkv, qkv, nullptr, o);
    gemm_f16<2><<<dim3(6, T / 128), 256, GEMM_SMEM>>>(o, wh + WO_AP, ap_b, xs, x, T, CC, CC);

    // ---- cross attention ----
    layernorm_kernel<<<T, 256>>>(x, ln2w, ln2b, h);
    gemm_f16<0><<<dim3(6, T / 128), 256, GEMM_SMEM>>>(h, wh + WO_Q, nullptr, nullptr, q, T, CC, CC);
    cudaStreamWaitEvent(0, e1, 0);
    attn_f16<true><<<PCROSS, 256, ATTN_SMEM>>>(q, kv, rel, big);
    gemm_f16<1><<<dim3(6, TT / 128), 256, GEMM_SMEM>>>(big, wh + WO_CP, cp_b, nullptr, big2, TT, CC, CC);
    mergeln_kernel<<<T, 256>>>(big2, x, ln3w, ln3b, h);

    // ---- MLP ----
    gemm_f16<3><<<dim3(24, T / 128), 256, GEMM_SMEM>>>(h, wh + WO_FC1, fc1_b, nullptr, big, T, HID, CC);
    gemm_f16<2><<<dim3(6, T / 128), 256, GEMM_SMEM>>>(big, wh + WO_FC2, fc2_b, x, out, T, CC, HID);
}

// round 16
// speedup vs baseline: 1.6424x; 1.0144x over previous
#include <cuda_runtime.h>
#include <cuda_fp16.h>
#include <math.h>
#include <stdint.h>

// ---------------------------------------------------------------------------
// MultiviewDecoderBlock (Vx=8, Vy=8, B=4, N=196, C=768, H=12, DH=64, M=4)
// fp16 GEMMs (cp.async 3-stage, K64, ldmatrix, fp32 accum) + fp16 attention
// (K/V-resident, 4 q-tiles looped) + warp-per-row LayerNorms.
// ---------------------------------------------------------------------------

constexpr int VX = 8, BB = 4, NN = 196, CC = 768, HH = 12, DHH = 64, MV = 4;
constexpr int HID = 4 * CC;            // 3072
constexpr int VB = VX * BB;            // 32
constexpr int T  = VB * NN;            // 6272
constexpr int TT = VX * MV * BB * NN;  // 25088
constexpr int PSELF  = VB * HH;            // 384
constexpr int PCROSS = VX * MV * BB * HH;  // 1536
constexpr float ATTN_SCALE = 0.125f;

// -------------------------- device scratch ---------------------------------
__device__ __align__(256) float  g_x   [T * CC];       // residual stream (fp32)
__device__ __align__(256) float  g_big2[TT * CC];      // cross-proj out (fp32)
__device__ __align__(256) __half g_h   [T * CC];       // LN out
__device__ __align__(256) __half g_yn  [T * CC];
__device__ __align__(256) __half g_qkv [T * 3 * CC];   // self qkv
__device__ __align__(256) __half g_kv  [T * 2 * CC];   // cross k|v (own buffer)
__device__ __align__(256) __half g_q   [T * CC];
__device__ __align__(256) __half g_o   [T * CC];
__device__ __align__(256) __half g_big [TT * CC];      // cross attn out; later MLP hidden
__device__ __align__(256) __half g_wh  [9437184];      // fp16 weights

constexpr int WO_QKV = 0;
constexpr int WO_AP  = 3 * CC * CC;
constexpr int WO_Q   = WO_AP  + CC * CC;
constexpr int WO_K   = WO_Q   + CC * CC;   // k|v contiguous -> fused N=1536 GEMM
constexpr int WO_V   = WO_K   + CC * CC;
constexpr int WO_CP  = WO_V   + CC * CC;
constexpr int WO_FC1 = WO_CP  + CC * CC;
constexpr int WO_FC2 = WO_FC1 + HID * CC;

extern __shared__ __align__(16) unsigned char dyn_smem[];

// ----------------------------- helpers -------------------------------------
__device__ __forceinline__ unsigned pkh(float lo, float hi) {
    unsigned r;
    asm("cvt.rn.f16x2.f32 %0, %1, %2;" : "=r"(r) : "f"(hi), "f"(lo));
    return r;
}
__device__ __forceinline__ void mma16h(float* c, const unsigned* a, const unsigned* b) {
    asm volatile(
        "mma.sync.aligned.m16n8k16.row.col.f32.f16.f16.f32 "
        "{%0,%1,%2,%3},{%4,%5,%6,%7},{%8,%9},{%0,%1,%2,%3};\n"
        : "+f"(c[0]), "+f"(c[1]), "+f"(c[2]), "+f"(c[3])
        : "r"(a[0]), "r"(a[1]), "r"(a[2]), "r"(a[3]), "r"(b[0]), "r"(b[1]));
}
__device__ __forceinline__ void ldmx4(unsigned* d, unsigned addr) {
    asm("ldmatrix.sync.aligned.m8n8.x4.shared.b16 {%0,%1,%2,%3}, [%4];"
        : "=r"(d[0]), "=r"(d[1]), "=r"(d[2]), "=r"(d[3]) : "r"(addr));
}
__device__ __forceinline__ void ldmx4t(unsigned* d, unsigned addr) {
    asm volatile("ldmatrix.sync.aligned.m8n8.x4.trans.shared.b16 {%0,%1,%2,%3}, [%4];"
                 : "=r"(d[0]), "=r"(d[1]), "=r"(d[2]), "=r"(d[3]) : "r"(addr));
}
__device__ __forceinline__ void cp16(unsigned d, const void* s) {
    asm volatile("cp.async.cg.shared.global [%0], [%1], 16;" :: "r"(d), "l"(s));
}

// ----------------------------- utility kernels ------------------------------
__global__ void round_all_kernel(
    const float4* s0, const float4* s1, const float4* s2, const float4* s3,
    const float4* s4, const float4* s5, const float4* s6, const float4* s7,
    __half* dst)
{
    const int seg = blockIdx.y;
    const float4* srcs[8] = {s0, s1, s2, s3, s4, s5, s6, s7};
    const int sizes4[8] = {3*CC*CC/4, CC*CC/4, CC*CC/4, CC*CC/4,
                           CC*CC/4, CC*CC/4, HID*CC/4, CC*HID/4};
    const int offs4[8] = {WO_QKV/4, WO_AP/4, WO_Q/4, WO_K/4,
                          WO_V/4, WO_CP/4, WO_FC1/4, WO_FC2/4};
    int i = blockIdx.x * blockDim.x + threadIdx.x;
    if (i < sizes4[seg]) {
        float4 v = srcs[seg][i];
        __half2* d = (__half2*)(dst + (size_t)(offs4[seg] + i) * 4);
        d[0] = __floats2half2_rn(v.x, v.y);
        d[1] = __floats2half2_rn(v.z, v.w);
    }
}

// warp-per-row LN: lane holds 6 float4 (24 elems), shfl-only reduction.
__device__ __forceinline__ void ln_warp(const float4* vv, const float* w,
                                        const float* b, __half* orow, int lane) {
    float s = 0.f, sq = 0.f;
    #pragma unroll
    for (int k = 0; k < 6; k++) {
        float4 v = vv[k];
        s  += v.x + v.y + v.z + v.w;
        sq += v.x * v.x + v.y * v.y + v.z * v.z + v.w * v.w;
    }
    #pragma unroll
    for (int off = 16; off; off >>= 1) {
        s  += __shfl_xor_sync(0xffffffffu, s, off);
        sq += __shfl_xor_sync(0xffffffffu, sq, off);
    }
    float mu = s * (1.0f / CC);
    float var = sq * (1.0f / CC) - mu * mu;
    float rstd = rsqrtf(var + 1e-5f);
    #pragma unroll
    for (int k = 0; k < 6; k++) {
        int c = lane * 4 + 128 * k;
        float4 v = vv[k];
        const float4 wv = *(const float4*)(w + c);
        const float4 bv = *(const float4*)(b + c);
        uint2 o;
        o.x = pkh((v.x - mu) * rstd * wv.x + bv.x,
                  (v.y - mu) * rstd * wv.y + bv.y);
        o.y = pkh((v.z - mu) * rstd * wv.z + bv.z,
                  (v.w - mu) * rstd * wv.w + bv.w);
        *(uint2*)(orow + c) = o;
    }
}

__global__ void layernorm_kernel(const float* __restrict__ in,
                                 const float* __restrict__ w,
                                 const float* __restrict__ b,
                                 __half* __restrict__ out) {
    int row = blockIdx.x * 8 + (threadIdx.x >> 5);
    int lane = threadIdx.x & 31;
    const float* xr = in + (size_t)row * CC;
    float4 vv[6];
    #pragma unroll
    for (int k = 0; k < 6; k++) vv[k] = *(const float4*)(xr + lane * 4 + 128 * k);
    ln_warp(vv, w, b, out + (size_t)row * CC, lane);
}

// fused: max-merge over M views + residual add (updates x) + LN3 -> h.
// warp per row.
__global__ void mergeln_kernel(const float* __restrict__ proj,
                               float* __restrict__ x,
                               const float* __restrict__ w,
                               const float* __restrict__ b,
                               __half* __restrict__ out) {
    int row = blockIdx.x * 8 + (threadIdx.x >> 5);
    int lane = threadIdx.x & 31;
    int n = row % NN, bb = (row / NN) % BB, v = row / (NN * BB);
    size_t pbase = ((((size_t)v * MV) * BB + bb) * NN + n) * CC;
    size_t ms = (size_t)BB * NN * CC;
    float* xr = x + (size_t)row * CC;
    float4 vv[6];
    #pragma unroll
    for (int k = 0; k < 6; k++) {
        int c = lane * 4 + 128 * k;
        float4 mx = *(const float4*)(proj + pbase + c);
        #pragma unroll
        for (int m = 1; m < MV; m++) {
            float4 pv = *(const float4*)(proj + pbase + (size_t)m * ms + c);
            mx.x = fmaxf(mx.x, pv.x); mx.y = fmaxf(mx.y, pv.y);
            mx.z = fmaxf(mx.z, pv.z); mx.w = fmaxf(mx.w, pv.w);
        }
        float4 xv = *(const float4*)(xr + c);
        xv.x += mx.x; xv.y += mx.y; xv.z += mx.z; xv.w += mx.w;
        *(float4*)(xr + c) = xv;
        vv[k] = xv;
    }
    ln_warp(vv, w, b, out + (size_t)row * CC, lane);
}

// --------------- fp16 GEMM, cp.async 3 stages, K64 tiles --------------------
constexpr int GSTAGES = 3;
constexpr int RB   = 144;
constexpr int ASTG = 128 * RB;
constexpr int GEMM_SMEM = GSTAGES * 2 * ASTG;  // 110592

template<int EPI>
__global__ void __launch_bounds__(256, 2) gemm_f16(
    const __half* __restrict__ A, const __half* __restrict__ Bw,
    const float* __restrict__ bias, const float* __restrict__ res,
    void* __restrict__ Cv, int Mdim, int Ndim, int Kdim)
{
    const unsigned sbase = (unsigned)__cvta_generic_to_shared(dyn_smem);
    const int tid = threadIdx.x;
    const int lane = tid & 31, warp = tid >> 5;
    const int wm = (warp >> 2) * 64;
    const int wn = (warp & 3) * 32;
    const int bm = blockIdx.y * 128, bn = blockIdx.x * 128;

    const int r0 = tid >> 3;
    const int gg = tid & 7;
    const __half* Agp = A  + (size_t)(bm + r0) * Kdim + gg * 8;
    const __half* Bgp = Bw + (size_t)(bn + r0) * Kdim + gg * 8;
    const unsigned dA = sbase + (unsigned)(r0 * RB + gg * 16);
    const unsigned dB = dA + GSTAGES * ASTG;

    float acc[4][4][4];
    #pragma unroll
    for (int i = 0; i < 4; i++)
        #pragma unroll
        for (int j = 0; j < 4; j++)
            #pragma unroll
            for (int t = 0; t < 4; t++) acc[i][j][t] = 0.f;

    const int nst = Kdim >> 6;
    #pragma unroll
    for (int s = 0; s < GSTAGES - 1; s++) {
        unsigned off = (unsigned)s * ASTG;
        int koff = s * 64;
        #pragma unroll
        for (int i = 0; i < 4; i++) {
            cp16(dA + off + (unsigned)(32 * i * RB), Agp + (size_t)(32 * i) * Kdim + koff);
            cp16(dB + off + (unsigned)(32 * i * RB), Bgp + (size_t)(32 * i) * Kdim + koff);
        }
        asm volatile("cp.async.commit_group;");
    }

    const unsigned aoff = (unsigned)((lane & 15) * RB + (lane >> 4) * 16);
    const int bsel = lane >> 3;
    const unsigned boff = (unsigned)((((bsel >> 1) << 3) + (lane & 7)) * RB +
                                     (bsel & 1) * 16);

    #pragma unroll 1
    for (int kt = 0; kt < nst; kt++) {
        asm volatile("cp.async.wait_group 1;");
        __syncthreads();
        const int buf = kt % GSTAGES;
        const unsigned abase = sbase + (unsigned)buf * ASTG;
        const unsigned bbase = sbase + (unsigned)(GSTAGES + buf) * ASTG;
        #pragma unroll
        for (int c = 0; c < 4; c++) {
            unsigned a[4][4], bb0[4], bb1[4];
            #pragma unroll
            for (int mf = 0; mf < 4; mf++)
                ldmx4(a[mf], abase + (unsigned)((wm + mf * 16) * RB + c * 32) + aoff);
            ldmx4(bb0, bbase + (unsigned)(wn * RB + c * 32) + boff);
            ldmx4(bb1, bbase + (unsigned)((wn + 16) * RB + c * 32) + boff);
            unsigned b0[2] = {bb0[0], bb0[1]};
            unsigned b1[2] = {bb0[2], bb0[3]};
            unsigned b2[2] = {bb1[0], bb1[1]};
            unsigned b3[2] = {bb1[2], bb1[3]};
            #pragma unroll
            for (int mf = 0; mf < 4; mf++) {
                mma16h(acc[mf][0], a[mf], b0);
                mma16h(acc[mf][1], a[mf], b1);
                mma16h(acc[mf][2], a[mf], b2);
                mma16h(acc[mf][3], a[mf], b3);
            }
        }
        if (kt + GSTAGES - 1 < nst) {
            unsigned off = (unsigned)((kt + GSTAGES - 1) % GSTAGES) * ASTG;
            int koff = (kt + GSTAGES - 1) * 64;
            #pragma unroll
            for (int i = 0; i < 4; i++) {
                cp16(dA + off + (unsigned)(32 * i * RB), Agp + (size_t)(32 * i) * Kdim + koff);
                cp16(dB + off + (unsigned)(32 * i * RB), Bgp + (size_t)(32 * i) * Kdim + koff);
            }
        }
        asm volatile("cp.async.commit_group;");
    }

    #pragma unroll
    for (int mf = 0; mf < 4; mf++) {
        #pragma unroll
        for (int nf = 0; nf < 4; nf++) {
            const int col = bn + wn + nf * 8 + (lane & 3) * 2;
            float bb0 = 0.f, bb1 = 0.f;
            if (EPI >= 1) { bb0 = bias[col]; bb1 = bias[col + 1]; }
            #pragma unroll
            for (int hh = 0; hh < 2; hh++) {
                const size_t row = (size_t)(bm + wm + mf * 16 + (lane >> 2) + hh * 8);
                float v0 = acc[mf][nf][hh * 2 + 0] + bb0;
                float v1 = acc[mf][nf][hh * 2 + 1] + bb1;
                if (EPI == 2) {
                    v0 += res[row * Ndim + col];
                    v1 += res[row * Ndim + col + 1];
                }
                if (EPI == 3) {
                    v0 = 0.5f * v0 * (1.0f + erff(v0 * 0.70710678118654752f));
                    v1 = 0.5f * v1 * (1.0f + erff(v1 * 0.70710678118654752f));
                }
                if (EPI == 0 || EPI == 3) {
                    __half* C = (__half*)Cv;
                    *(unsigned*)(C + row * Ndim + col) = pkh(v0, v1);
                } else {
                    float* C = (float*)Cv;
                    *(float2*)(C + row * Ndim + col) = make_float2(v0, v1);
                }
            }
        }
    }
}

// ------------------------- fp16 mma attention -------------------------------
// One block per head-problem. K/V resident in smem; loop over 4 q-tiles.
constexpr int QWS = 36;
constexpr int PWS = 108;
constexpr int W_PQ = 0;                 // P: 64*108 words; Q: 64*36 inside
constexpr int W_K  = 6912;
constexpr int W_V  = 14400;
constexpr int W_RED = 21888;
constexpr int ATTN_SMEM = (W_RED + 256) * 4;  // 88576 bytes

template<bool CROSS>
__global__ void __launch_bounds__(256, 2) attn_f16(
    const __half* __restrict__ Qsrc, const __half* __restrict__ Ksrc,
    const int* __restrict__ rel, __half* __restrict__ Out)
{
    unsigned* W = (unsigned*)dyn_smem;
    unsigned* Qw = W + W_PQ;
    unsigned* Kw = W + W_K;
    unsigned* Vw = W + W_V;
    unsigned* Pw = W + W_PQ;
    float* redmax = (float*)(W + W_RED);
    float* redsum = redmax + 128;
    const unsigned sbase = (unsigned)__cvta_generic_to_shared(dyn_smem);

    const int p = blockIdx.x;
    const int tid = threadIdx.x;
    const int lane = tid & 31, warp = tid >> 5;
    const int wm = warp & 3, wn = warp >> 2;
    const int r = lane >> 2, q = lane & 3;

    const __half *qp, *kp, *vp;
    __half* op;
    int qrs, kvs;
    if (!CROSS) {
        int vb = p / HH, h2 = p % HH;
        const __half* base = Qsrc + (size_t)vb * NN * 3 * CC;
        qp = base + h2 * DHH;
        kp = base + CC + h2 * DHH;
        vp = base + 2 * CC + h2 * DHH;
        qrs = 3 * CC; kvs = 3 * CC;
        op = Out + (size_t)vb * NN * CC + h2 * DHH;
    } else {
        int h2 = p % HH; int rr = p / HH;
        int b = rr % BB; int r2 = rr / BB;
        int mvi = r2 % MV; int v = r2 / MV;
        int vy = rel[v * MV + mvi];
        qp = Qsrc + ((size_t)(v * BB + b) * NN) * CC + h2 * DHH; qrs = CC;
        kp = Ksrc + ((size_t)(vy * BB + b) * NN) * 1536 + h2 * DHH;
        vp = kp + CC;
        kvs = 1536;
        op = Out + (size_t)rr * NN * CC + h2 * DHH;
    }

    // ---- load K, V once (208 rows, zero-padded >= NN) ----
    #pragma unroll
    for (int it = 0; it < 13; it++) {
        int idx = tid + 256 * it;
        int row = idx >> 4, w2 = (idx & 15) * 2;
        uint2 kv = make_uint2(0u, 0u);
        uint2 vv = make_uint2(0u, 0u);
        if (row < NN) {
            kv = *(const uint2*)(kp + (size_t)row * kvs + w2 * 2);
            vv = *(const uint2*)(vp + (size_t)row * kvs + w2 * 2);
        }
        Kw[row * QWS + w2]     = kv.x;
        Kw[row * QWS + w2 + 1] = kv.y;
        Vw[row * QWS + w2]     = vv.x;
        Vw[row * QWS + w2 + 1] = vv.y;
    }
    __syncthreads();

    const int n0 = wn * 104;
    const int rowl = wm * 16 + r;
    const int lrow = lane & 15;
    const int lcol = (lane >> 4) * 8;

    #pragma unroll 1
    for (int mt = 0; mt < 4; mt++) {
        const int m0 = mt * 64;

        #pragma unroll
        for (int it = 0; it < 4; it++) {
            int idx = tid + 256 * it;
            int row = idx >> 4, w2 = (idx & 15) * 2;
            uint2 qv = make_uint2(0u, 0u);
            if (m0 + row < NN)
                qv = *(const uint2*)(qp + (size_t)(m0 + row) * qrs + w2 * 2);
            Qw[row * QWS + w2]     = qv.x;
            Qw[row * QWS + w2 + 1] = qv.y;
        }
        __syncthreads();

        float sc[13][4];
        #pragma unroll
        for (int j = 0; j < 13; j++)
            #pragma unroll
            for (int t = 0; t < 4; t++) sc[j][t] = 0.f;

        #pragma unroll
        for (int kt = 0; kt < 4; kt++) {
            unsigned a[4];
            const unsigned* ap = Qw + rowl * QWS + kt * 8 + q;
            a[0] = ap[0];
            a[1] = ap[8 * QWS];
            a[2] = ap[4];
            a[3] = ap[8 * QWS + 4];
            #pragma unroll
            for (int j = 0; j < 13; j++) {
                unsigned b[2];
                const unsigned* bp = Kw + (n0 + j * 8 + r) * QWS + kt * 8 + q;
                b[0] = bp[0];
                b[1] = bp[4];
                mma16h(sc[j], a, b);
            }
        }

        #pragma unroll
        for (int j = 0; j < 13; j++) {
            int cbase = n0 + j * 8 + 2 * q;
            #pragma unroll
            for (int t = 0; t < 4; t++) {
                int col = cbase + (t & 1);
                sc[j][t] = (col < NN) ? sc[j][t] * ATTN_SCALE : -1e30f;
            }
        }

        float mx0 = -1e30f, mx1 = -1e30f;
        #pragma unroll
        for (int j = 0; j < 13; j++) {
            mx0 = fmaxf(mx0, fmaxf(sc[j][0], sc[j][1]));
            mx1 = fmaxf(mx1, fmaxf(sc[j][2], sc[j][3]));
        }
        mx0 = fmaxf(mx0, __shfl_xor_sync(0xffffffffu, mx0, 1));
        mx0 = fmaxf(mx0, __shfl_xor_sync(0xffffffffu, mx0, 2));
        mx1 = fmaxf(mx1, __shfl_xor_sync(0xffffffffu, mx1, 1));
        mx1 = fmaxf(mx1, __shfl_xor_sync(0xffffffffu, mx1, 2));
        if (q == 0) {
            redmax[wn * 64 + rowl] = mx0;
            redmax[wn * 64 + rowl + 8] = mx1;
        }
        __syncthreads();   // all Q/K reads done -> P region writable
        float fm0 = fmaxf(redmax[rowl], redmax[64 + rowl]);
        float fm1 = fmaxf(redmax[rowl + 8], redmax[64 + rowl + 8]);

        float s0 = 0.f, s1 = 0.f;
        #pragma unroll
        for (int j = 0; j < 13; j++) {
            sc[j][0] = __expf(sc[j][0] - fm0);
            sc[j][1] = __expf(sc[j][1] - fm0);
            sc[j][2] = __expf(sc[j][2] - fm1);
            sc[j][3] = __expf(sc[j][3] - fm1);
            s0 += sc[j][0] + sc[j][1];
            s1 += sc[j][2] + sc[j][3];
        }
        s0 += __shfl_xor_sync(0xffffffffu, s0, 1);
        s0 += __shfl_xor_sync(0xffffffffu, s0, 2);
        s1 += __shfl_xor_sync(0xffffffffu, s1, 1);
        s1 += __shfl_xor_sync(0xffffffffu, s1, 2);
        if (q == 0) {
            redsum[wn * 64 + rowl] = s0;
            redsum[wn * 64 + rowl + 8] = s1;
        }
        #pragma unroll
        for (int j = 0; j < 13; j++) {
            int wbase = (n0 >> 1) + j * 4 + q;
            Pw[rowl * PWS + wbase]       = pkh(sc[j][0], sc[j][1]);
            Pw[(rowl + 8) * PWS + wbase] = pkh(sc[j][2], sc[j][3]);
        }
        __syncthreads();

        const int oc0 = wn * 32;
        float oacc[4][4];
        #pragma unroll
        for (int j = 0; j < 4; j++)
            #pragma unroll
            for (int t = 0; t < 4; t++) oacc[j][t] = 0.f;

        #pragma unroll
        for (int kt = 0; kt < 13; kt++) {
            unsigned a[4];
            const unsigned* ap2 = Pw + rowl * PWS + kt * 8 + q;
            a[0] = ap2[0];
            a[1] = ap2[8 * PWS];
            a[2] = ap2[4];
            a[3] = ap2[8 * PWS + 4];
            #pragma unroll
            for (int jp = 0; jp < 2; jp++) {
                unsigned b4[4];
                unsigned addr = sbase + (unsigned)(W_V * 4) +
                    (unsigned)((kt * 16 + lrow) * 72 + oc0 + jp * 16 + lcol) * 2u;
                ldmx4t(b4, addr);
                mma16h(oacc[jp * 2 + 0], a, b4 + 0);
                mma16h(oacc[jp * 2 + 1], a, b4 + 2);
            }
        }

        float inv0 = 1.0f / (redsum[rowl] + redsum[64 + rowl]);
        float inv1 = 1.0f / (redsum[rowl + 8] + redsum[64 + rowl + 8]);
        int mg0 = m0 + rowl, mg1 = m0 + rowl + 8;
        #pragma unroll
        for (int j = 0; j < 4; j++) {
            int col = oc0 + j * 8 + 2 * q;
            if (mg0 < NN)
                *(unsigned*)(op + (size_t)mg0 * CC + col) =
                    pkh(oacc[j][0] * inv0, oacc[j][1] * inv0);
            if (mg1 < NN)
                *(unsigned*)(op + (size_t)mg1 * CC + col) =
                    pkh(oacc[j][2] * inv1, oacc[j][3] * inv1);
        }
        __syncthreads();   // P reads done -> next Q load safe
    }
}

// ------------------------------- launch -------------------------------------
extern "C" void kernel_launch(void* const* d_in, const int* in_sizes, int n_in,
                              void* d_out, int out_size) {
    int sh = (in_sizes[5] == 1) ? 0 : -1;

    const float* xs  = (const float*)d_in[0];
    const float* ys  = (const float*)d_in[1];
    const int* rel   = (const int*)d_in[4];
    const float* qkv_w = (const float*)d_in[6 + sh];
    const float* ap_w  = (const float*)d_in[7 + sh];
    const float* ap_b  = (const float*)d_in[8 + sh];
    const float* q_w   = (const float*)d_in[9 + sh];
    const float* k_w   = (const float*)d_in[10 + sh];
    const float* v_w   = (const float*)d_in[11 + sh];
    const float* cp_w  = (const float*)d_in[12 + sh];
    const float* cp_b  = (const float*)d_in[13 + sh];
    const float* fc1_w = (const float*)d_in[14 + sh];
    const float* fc1_b = (const float*)d_in[15 + sh];
    const float* fc2_w = (const float*)d_in[16 + sh];
    const float* fc2_b = (const float*)d_in[17 + sh];
    const float* ln1w = (const float*)d_in[18 + sh];
    const float* ln1b = (const float*)d_in[19 + sh];
    const float* ln2w = (const float*)d_in[20 + sh];
    const float* ln2b = (const float*)d_in[21 + sh];
    const float* ln3w = (const float*)d_in[22 + sh];
    const float* ln3b = (const float*)d_in[23 + sh];
    const float* lnyw = (const float*)d_in[24 + sh];
    const float* lnyb = (const float*)d_in[25 + sh];
    float* out = (float*)d_out;

    float *x, *big2;
    __half *h, *yn, *qkv, *kv, *q, *o, *big, *wh;
    cudaGetSymbolAddress((void**)&x, g_x);
    cudaGetSymbolAddress((void**)&big2, g_big2);
    cudaGetSymbolAddress((void**)&h, g_h);
    cudaGetSymbolAddress((void**)&yn, g_yn);
    cudaGetSymbolAddress((void**)&qkv, g_qkv);
    cudaGetSymbolAddress((void**)&kv, g_kv);
    cudaGetSymbolAddress((void**)&q, g_q);
    cudaGetSymbolAddress((void**)&o, g_o);
    cudaGetSymbolAddress((void**)&big, g_big);
    cudaGetSymbolAddress((void**)&wh, g_wh);

    cudaFuncSetAttribute(gemm_f16<0>, cudaFuncAttributeMaxDynamicSharedMemorySize, GEMM_SMEM);
    cudaFuncSetAttribute(gemm_f16<1>, cudaFuncAttributeMaxDynamicSharedMemorySize, GEMM_SMEM);
    cudaFuncSetAttribute(gemm_f16<2>, cudaFuncAttributeMaxDynamicSharedMemorySize, GEMM_SMEM);
    cudaFuncSetAttribute(gemm_f16<3>, cudaFuncAttributeMaxDynamicSharedMemorySize, GEMM_SMEM);
    cudaFuncSetAttribute(attn_f16<false>, cudaFuncAttributeMaxDynamicSharedMemorySize, ATTN_SMEM);
    cudaFuncSetAttribute(attn_f16<true>,  cudaFuncAttributeMaxDynamicSharedMemorySize, ATTN_SMEM);

    static cudaStream_t s2 = nullptr;
    static cudaEvent_t eF = nullptr, e1 = nullptr;
    if (s2 == nullptr) {
        cudaStreamCreate(&s2);
        cudaEventCreateWithFlags(&eF, cudaEventDisableTiming);
        cudaEventCreateWithFlags(&e1, cudaEventDisableTiming);
    }

    round_all_kernel<<<dim3(HID * CC / 4 / 256, 8), 256>>>(
        (const float4*)qkv_w, (const float4*)ap_w, (const float4*)q_w,
        (const float4*)k_w, (const float4*)v_w, (const float4*)cp_w,
        (const float4*)fc1_w, (const float4*)fc2_w, wh);
    cudaEventRecord(eF, 0);

    // ---- stream 2: cross k|v producer chain ----
    cudaStreamWaitEvent(s2, eF, 0);
    layernorm_kernel<<<T / 8, 256, 0, s2>>>(ys, lnyw, lnyb, yn);
    gemm_f16<0><<<dim3(12, T / 128), 256, GEMM_SMEM, s2>>>(yn, wh + WO_K, nullptr, nullptr, kv, T, 2 * CC, CC);
    cudaEventRecord(e1, s2);

    // ---- stream 0: self attention ----
    layernorm_kernel<<<T / 8, 256>>>(xs, ln1w, ln1b, h);
    gemm_f16<0><<<dim3(18, T / 128), 256, GEMM_SMEM>>>(h, wh + WO_QKV, nullptr, nullptr, qkv, T, 3 * CC, CC);
    attn_f16<false><<<PSELF, 256, ATTN_SMEM>>>(qkv, qkv, nullptr, o);
    gemm_f16<2><<<dim3(6, T / 128), 256, GEMM_SMEM>>>(o, wh + WO_AP, ap_b, xs, x, T, CC, CC);

    // ---- cross attention ----
    layernorm_kernel<<<T / 8, 256>>>(x, ln2w, ln2b, h);
    gemm_f16<0><<<dim3(6, T / 128), 256, GEMM_SMEM>>>(h, wh + WO_Q, nullptr, nullptr, q, T, CC, CC);
    cudaStreamWaitEvent(0, e1, 0);
    attn_f16<true><<<PCROSS, 256, ATTN_SMEM>>>(q, kv, rel, big);
    gemm_f16<1><<<dim3(6, TT / 128), 256, GEMM_SMEM>>>(big, wh + WO_CP, cp_b, nullptr, big2, TT, CC, CC);
    mergeln_kernel<<<T / 8, 256>>>(big2, x, ln3w, ln3b, h);

    // ---- MLP ----
    gemm_f16<3><<<dim3(24, T / 128), 256, GEMM_SMEM>>>(h, wh + WO_FC1, fc1_b, nullptr, big, T, HID, CC);
    gemm_f16<2><<<dim3(6, T / 128), 256, GEMM_SMEM>>>(big, wh + WO_FC2, fc2_b, x, out, T, CC, HID);
}